// round 6
// baseline (speedup 1.0000x reference)
#include <cuda_runtime.h>
#include <cuda_bf16.h>
#include <math.h>

// Problem constants (match reference)
#define NN     50000
#define EE     800000
#define EP     850000     // edges + self loops
#define F_IN   128
#define HID    32
#define HEADS  4
#define HH     128        // HEADS*HID
#define CC     40
#define NEG_SLOPE 0.2f

#define SCAN_CHUNK 1024
#define SCAN_BLOCKS ((NN + SCAN_CHUNK - 1) / SCAN_CHUNK)   // 49

// ---------------- scratch (device globals; no allocation allowed) ----------------
__device__ int   g_flag32;
__device__ int   g_deg[NN];
__device__ int   g_off[NN + 1];
__device__ int   g_cursor[NN];
__device__ int   g_bsum[SCAN_BLOCKS];
__device__ int   g_csr_src[EP];      // src node per CSR slot (grouped by dst)

__device__ float g_h1[NN * HH];      // x @ W1            [N,128]
__device__ float g_as1[NN * HEADS];
__device__ float g_ad1[NN * HEADS];
__device__ float g_out1[NN * HH];    // GAT1 out (elu'd)  [N,128]
__device__ float g_h2[NN * CC];      // out1 @ W2         [N,40]
__device__ float g_as2[NN];
__device__ float g_ad2[NN];
__device__ float g_hg1[NN * HID];    // x @ gcnW1         [N,32]
__device__ float g_norm[NN];         // rsqrt(deg)
__device__ float g_go1[NN * HID];    // GCN1 out (relu'd) [N,32]
__device__ float g_hg2[NN * CC];     // go1 @ gcnW2       [N,40]

// Device-side symbol table: never pass __device__ symbols from host (ATS trap).
#define PTR_H2   2
#define PTR_HG2  3
#define PTR_OUT1 4
#define PTR_GO1  5
__device__ __forceinline__ float* g_ptr(int id) {
    switch (id) {
        case PTR_H2:   return g_h2;
        case PTR_HG2:  return g_hg2;
        case PTR_OUT1: return g_out1;
        case PTR_GO1:  return g_go1;
    }
    return 0;
}

// ---------------- init ----------------
__global__ void zero_init() {
    int i = blockIdx.x * blockDim.x + threadIdx.x;
    if (i == 0) g_flag32 = 0;
    if (i < NN) g_deg[i] = 0;
}

// ---------------- dtype detect: int64 => every odd 32-bit word is 0 ----------------
__global__ void detect_idx(const unsigned int* __restrict__ raw) {
    int i = blockIdx.x * blockDim.x + threadIdx.x;   // 65536 samples
    unsigned v = raw[2 * i + 1];
    if (v != 0u) g_flag32 = 1;
}

__device__ __forceinline__ int load_node(const void* eidx, long long idx) {
    int v = g_flag32 ? ((const int*)eidx)[idx]
                     : (int)((const long long*)eidx)[idx];
    return min(max(v, 0), NN - 1);
}

// ---------------- pass 1: count degrees (incl. self loops) ----------------
__global__ void count_deg(const void* __restrict__ eidx) {
    int e = blockIdx.x * blockDim.x + threadIdx.x;
    if (e >= EP) return;
    int d = (e < EE) ? load_node(eidx, (long long)EE + e) : (e - EE);
    atomicAdd(&g_deg[d], 1);
}

// ---------------- 3-phase scan ----------------
__global__ void scan_phase1() {
    __shared__ int warp_sums[32];
    int b = blockIdx.x;
    int i = b * SCAN_CHUNK + threadIdx.x;
    int lane = threadIdx.x & 31, wid = threadIdx.x >> 5;
    int v = (i < NN) ? g_deg[i] : 0;
    int x = v;
#pragma unroll
    for (int s = 1; s < 32; s <<= 1) {
        int t = __shfl_up_sync(0xffffffff, x, s);
        if (lane >= s) x += t;
    }
    if (lane == 31) warp_sums[wid] = x;
    __syncthreads();
    if (wid == 0) {
        int ws = warp_sums[lane];
#pragma unroll
        for (int s = 1; s < 32; s <<= 1) {
            int t = __shfl_up_sync(0xffffffff, ws, s);
            if (lane >= s) ws += t;
        }
        warp_sums[lane] = ws;
    }
    __syncthreads();
    int prefix = (wid > 0) ? warp_sums[wid - 1] : 0;
    int excl = prefix + x - v;
    if (i < NN) g_off[i] = excl;
    if (threadIdx.x == SCAN_CHUNK - 1) g_bsum[b] = prefix + x;
}

__global__ void scan_phase2() {
    __shared__ int sh[64];
    int lane = threadIdx.x;
    int v0 = (lane < SCAN_BLOCKS) ? g_bsum[lane] : 0;
    int v1 = (lane + 32 < SCAN_BLOCKS) ? g_bsum[lane + 32] : 0;
    int x = v0;
#pragma unroll
    for (int s = 1; s < 32; s <<= 1) {
        int t = __shfl_up_sync(0xffffffff, x, s);
        if (lane >= s) x += t;
    }
    int tot0 = __shfl_sync(0xffffffff, x, 31);
    int y = v1;
#pragma unroll
    for (int s = 1; s < 32; s <<= 1) {
        int t = __shfl_up_sync(0xffffffff, y, s);
        if (lane >= s) y += t;
    }
    sh[lane] = x - v0;
    sh[lane + 32] = tot0 + y - v1;
    __syncwarp();
    if (lane < SCAN_BLOCKS) g_bsum[lane] = sh[lane];
    if (lane + 32 < SCAN_BLOCKS) g_bsum[lane + 32] = sh[lane + 32];
}

__global__ void scan_phase3() {
    int i = blockIdx.x * blockDim.x + threadIdx.x;
    if (i == 0) g_off[NN] = EP;
    if (i >= NN) return;
    int o = g_off[i] + g_bsum[i / SCAN_CHUNK];
    g_off[i] = o;
    g_cursor[i] = o;
    g_norm[i] = rsqrtf((float)g_deg[i]);
}

// ---------------- pass 2: scatter into CSR ----------------
__global__ void scatter_csr(const void* __restrict__ eidx) {
    int e = blockIdx.x * blockDim.x + threadIdx.x;
    if (e >= EP) return;
    int s, d;
    if (e < EE) {
        s = load_node(eidx, e);
        d = load_node(eidx, (long long)EE + e);
    } else {
        s = d = e - EE;
    }
    int pos = atomicAdd(&g_cursor[d], 1);
    g_csr_src[pos] = s;
}

// ---------------- fused first projection: reads x once ----------------
// Virtual B = [gat_W1 (128x128) | gcn_W1 (128x32)] -> Ncat = 160.
#define BM 64
#define BN 64
#define BK 16
#define NCAT (HH + HID)   // 160
__global__ void fused_proj(const float* __restrict__ x,
                           const float* __restrict__ W1,
                           const float* __restrict__ Wg) {
    __shared__ float As[BK][BM + 1];
    __shared__ float Bs[BK][BN];
    int tid = threadIdx.x;
    int tx = tid % 16, ty = tid / 16;
    int row0 = blockIdx.y * BM, col0 = blockIdx.x * BN;
    float acc[4][4] = {};
    for (int k0 = 0; k0 < F_IN; k0 += BK) {
        for (int i = tid; i < BM * BK; i += 256) {
            int r = i / BK, c = i % BK;
            int gr = row0 + r;
            As[c][r] = (gr < NN) ? x[gr * F_IN + k0 + c] : 0.f;
        }
        for (int i = tid; i < BK * BN; i += 256) {
            int r = i / BN, c = i % BN;
            int gc = col0 + c;
            float v;
            if (gc < HH) v = W1[(k0 + r) * HH + gc];
            else if (gc < NCAT) v = Wg[(k0 + r) * HID + (gc - HH)];
            else v = 0.f;
            Bs[r][c] = v;
        }
        __syncthreads();
#pragma unroll
        for (int k = 0; k < BK; k++) {
            float a[4], b[4];
#pragma unroll
            for (int i = 0; i < 4; i++) a[i] = As[k][ty * 4 + i];
#pragma unroll
            for (int j = 0; j < 4; j++) b[j] = Bs[k][tx * 4 + j];
#pragma unroll
            for (int i = 0; i < 4; i++)
#pragma unroll
                for (int j = 0; j < 4; j++) acc[i][j] += a[i] * b[j];
        }
        __syncthreads();
    }
#pragma unroll
    for (int i = 0; i < 4; i++) {
        int gr = row0 + ty * 4 + i;
        if (gr >= NN) continue;
#pragma unroll
        for (int j = 0; j < 4; j++) {
            int gc = col0 + tx * 4 + j;
            if (gc < HH) g_h1[gr * HH + gc] = acc[i][j];
            else if (gc < NCAT) g_hg1[gr * HID + (gc - HH)] = acc[i][j];
        }
    }
}

// ---------------- register-blocked SGEMM (device-tagged operands) ----------------
__global__ void sgemm_rb(int aid, const float* __restrict__ B, int cid,
                         int M, int Nn, int K) {
    const float* A = g_ptr(aid);
    float* Cm = g_ptr(cid);
    __shared__ float As[BK][BM + 1];
    __shared__ float Bs[BK][BN];
    int tid = threadIdx.x;
    int tx = tid % 16, ty = tid / 16;
    int row0 = blockIdx.y * BM, col0 = blockIdx.x * BN;
    float acc[4][4] = {};
    for (int k0 = 0; k0 < K; k0 += BK) {
        for (int i = tid; i < BM * BK; i += 256) {
            int r = i / BK, c = i % BK;
            int gr = row0 + r, gc = k0 + c;
            As[c][r] = (gr < M && gc < K) ? A[gr * K + gc] : 0.f;
        }
        for (int i = tid; i < BK * BN; i += 256) {
            int r = i / BN, c = i % BN;
            int gr = k0 + r, gc = col0 + c;
            Bs[r][c] = (gr < K && gc < Nn) ? B[gr * Nn + gc] : 0.f;
        }
        __syncthreads();
#pragma unroll
        for (int k = 0; k < BK; k++) {
            float a[4], b[4];
#pragma unroll
            for (int i = 0; i < 4; i++) a[i] = As[k][ty * 4 + i];
#pragma unroll
            for (int j = 0; j < 4; j++) b[j] = Bs[k][tx * 4 + j];
#pragma unroll
            for (int i = 0; i < 4; i++)
#pragma unroll
                for (int j = 0; j < 4; j++) acc[i][j] += a[i] * b[j];
        }
        __syncthreads();
    }
#pragma unroll
    for (int i = 0; i < 4; i++) {
        int gr = row0 + ty * 4 + i;
        if (gr >= M) continue;
#pragma unroll
        for (int j = 0; j < 4; j++) {
            int gc = col0 + tx * 4 + j;
            if (gc < Nn) Cm[gr * Nn + gc] = acc[i][j];
        }
    }
}

// ---------------- attention logits ----------------
__global__ void att_logits1(const float* __restrict__ att_src,
                            const float* __restrict__ att_dst) {
    int t = blockIdx.x * blockDim.x + threadIdx.x;
    if (t >= NN * HEADS) return;
    int n = t >> 2, h = t & 3;
    const float* hp = &g_h1[n * HH + h * HID];
    const float* as = &att_src[h * HID];
    const float* ad = &att_dst[h * HID];
    float s = 0.f, d = 0.f;
#pragma unroll
    for (int k = 0; k < HID; k++) { float v = hp[k]; s += v * as[k]; d += v * ad[k]; }
    g_as1[t] = s;
    g_ad1[t] = d;
}

__global__ void att_logits2(const float* __restrict__ att_src,
                            const float* __restrict__ att_dst) {
    int n = blockIdx.x * blockDim.x + threadIdx.x;
    if (n >= NN) return;
    const float* hp = &g_h2[n * CC];
    float s = 0.f, d = 0.f;
#pragma unroll
    for (int k = 0; k < CC; k++) { float v = hp[k]; s += v * att_src[k]; d += v * att_dst[k]; }
    g_as2[n] = s;
    g_ad2[n] = d;
}

// ---------------- fused layer-1 aggregation (GAT1 + GCN1), warp per node -------
// lane: GAT feature float4 at lane*4 (head = lane>>3); GCN feature = lane.
__global__ void layer1_agg(const float* __restrict__ gat_b1,
                           const float* __restrict__ gcn_b1) {
    int warp = (blockIdx.x * blockDim.x + threadIdx.x) >> 5;
    if (warp >= NN) return;
    int lane = threadIdx.x & 31;
    int n = warp;
    int beg = g_off[n], end = g_off[n + 1];
    int h = lane >> 3;
    float ad = g_ad1[n * 4 + h];
    float nd = g_norm[n];
    float4 acc = {0.f, 0.f, 0.f, 0.f};
    float accg = 0.f, sumw = 0.f;
    int p = beg;
    for (; p + 1 < end; p += 2) {
        int s0 = g_csr_src[p];
        int s1 = g_csr_src[p + 1];
        float l0 = g_as1[s0 * 4 + h] + ad;
        float l1 = g_as1[s1 * 4 + h] + ad;
        float4 h0 = *(const float4*)&g_h1[s0 * HH + lane * 4];
        float4 h1 = *(const float4*)&g_h1[s1 * HH + lane * 4];
        float gv0 = g_hg1[s0 * HID + lane];
        float gv1 = g_hg1[s1 * HID + lane];
        float c0 = g_norm[s0], c1 = g_norm[s1];
        l0 = (l0 > 0.f) ? l0 : NEG_SLOPE * l0;
        l1 = (l1 > 0.f) ? l1 : NEG_SLOPE * l1;
        float w0 = __expf(l0), w1 = __expf(l1);   // logits O(1); shift-invariant
        sumw += w0 + w1;
        acc.x += w0 * h0.x + w1 * h1.x;
        acc.y += w0 * h0.y + w1 * h1.y;
        acc.z += w0 * h0.z + w1 * h1.z;
        acc.w += w0 * h0.w + w1 * h1.w;
        accg += c0 * gv0 + c1 * gv1;
    }
    if (p < end) {
        int s0 = g_csr_src[p];
        float l0 = g_as1[s0 * 4 + h] + ad;
        float4 h0 = *(const float4*)&g_h1[s0 * HH + lane * 4];
        float gv0 = g_hg1[s0 * HID + lane];
        float c0 = g_norm[s0];
        l0 = (l0 > 0.f) ? l0 : NEG_SLOPE * l0;
        float w0 = __expf(l0);
        sumw += w0;
        acc.x += w0 * h0.x; acc.y += w0 * h0.y; acc.z += w0 * h0.z; acc.w += w0 * h0.w;
        accg += c0 * gv0;
    }
    float inv = 1.f / sumw;
    float4 bv = *(const float4*)&gat_b1[lane * 4];
    float4 o;
    float vx = acc.x * inv + bv.x; o.x = (vx > 0.f) ? vx : expm1f(vx);
    float vy = acc.y * inv + bv.y; o.y = (vy > 0.f) ? vy : expm1f(vy);
    float vz = acc.z * inv + bv.z; o.z = (vz > 0.f) ? vz : expm1f(vz);
    float vw = acc.w * inv + bv.w; o.w = (vw > 0.f) ? vw : expm1f(vw);
    *(float4*)&g_out1[n * HH + lane * 4] = o;
    float gval = accg * nd + gcn_b1[lane];
    g_go1[n * HID + lane] = (gval > 0.f) ? gval : 0.f;
}

// ---------------- fused layer-2 aggregation + final head, warp per node --------
// GAT2: softmax-weighted sum of h2[src]; GCN2: norm-weighted sum of hg2[src].
// Then out[n,:] = [gcn*wc , gat*wt] (with conv biases) @ lin_W + lin_b.
__global__ void layer2_head(const float* __restrict__ gat_b2,
                            const float* __restrict__ gcn_b2,
                            const float* __restrict__ lin_W,
                            const float* __restrict__ lin_b,
                            const float* __restrict__ wc_p,
                            const float* __restrict__ wt_p,
                            float* __restrict__ out) {
    __shared__ float cat_sh[8][2 * CC];      // 8 warps per block
    int warp = (blockIdx.x * blockDim.x + threadIdx.x) >> 5;
    if (warp >= NN) return;
    int lane = threadIdx.x & 31;
    int wloc = (threadIdx.x >> 5) & 7;
    int n = warp;
    int beg = g_off[n], end = g_off[n + 1];
    float ad = g_ad2[n];
    float nd = g_norm[n];
    float ga1 = 0.f, ga2 = 0.f, gc1 = 0.f, gc2 = 0.f, sumw = 0.f;
    int p = beg;
    for (; p + 1 < end; p += 2) {
        int s0 = g_csr_src[p];
        int s1 = g_csr_src[p + 1];
        float l0 = g_as2[s0] + ad;
        float l1 = g_as2[s1] + ad;
        float ha0 = g_h2[s0 * CC + lane];
        float ha1 = g_h2[s1 * CC + lane];
        float hb0 = (lane < CC - 32) ? g_h2[s0 * CC + 32 + lane] : 0.f;
        float hb1 = (lane < CC - 32) ? g_h2[s1 * CC + 32 + lane] : 0.f;
        float va0 = g_hg2[s0 * CC + lane];
        float va1 = g_hg2[s1 * CC + lane];
        float vb0 = (lane < CC - 32) ? g_hg2[s0 * CC + 32 + lane] : 0.f;
        float vb1 = (lane < CC - 32) ? g_hg2[s1 * CC + 32 + lane] : 0.f;
        float c0 = g_norm[s0], c1 = g_norm[s1];
        l0 = (l0 > 0.f) ? l0 : NEG_SLOPE * l0;
        l1 = (l1 > 0.f) ? l1 : NEG_SLOPE * l1;
        float w0 = __expf(l0), w1 = __expf(l1);
        sumw += w0 + w1;
        ga1 += w0 * ha0 + w1 * ha1;
        ga2 += w0 * hb0 + w1 * hb1;
        gc1 += c0 * va0 + c1 * va1;
        gc2 += c0 * vb0 + c1 * vb1;
    }
    if (p < end) {
        int s0 = g_csr_src[p];
        float l0 = g_as2[s0] + ad;
        float ha0 = g_h2[s0 * CC + lane];
        float hb0 = (lane < CC - 32) ? g_h2[s0 * CC + 32 + lane] : 0.f;
        float va0 = g_hg2[s0 * CC + lane];
        float vb0 = (lane < CC - 32) ? g_hg2[s0 * CC + 32 + lane] : 0.f;
        float c0 = g_norm[s0];
        l0 = (l0 > 0.f) ? l0 : NEG_SLOPE * l0;
        float w0 = __expf(l0);
        sumw += w0;
        ga1 += w0 * ha0;
        ga2 += w0 * hb0;
        gc1 += c0 * va0;
        gc2 += c0 * vb0;
    }
    float inv = 1.f / sumw;
    float wc = *wc_p, wt = *wt_p;
    // Stage cat row: [gcn2 + b] * wc (40) then [gat2 + b] * wt (40)
    cat_sh[wloc][lane] = (gc1 * nd + gcn_b2[lane]) * wc;
    if (lane < CC - 32) cat_sh[wloc][32 + lane] = (gc2 * nd + gcn_b2[32 + lane]) * wc;
    cat_sh[wloc][CC + lane] = (ga1 * inv + gat_b2[lane]) * wt;
    if (lane < CC - 32) cat_sh[wloc][CC + 32 + lane] = (ga2 * inv + gat_b2[32 + lane]) * wt;
    __syncwarp();
    // out[n,co] = sum_j cat[j] * lin_W[j*CC + co] + lin_b[co]
    const float* cat = cat_sh[wloc];
    if (lane < 32) {
        float a0 = lin_b[lane];
        float a1 = (lane < CC - 32) ? lin_b[32 + lane] : 0.f;
#pragma unroll
        for (int j = 0; j < 2 * CC; j++) {
            float cv = cat[j];
            a0 += cv * lin_W[j * CC + lane];
            if (lane < CC - 32) a1 += cv * lin_W[j * CC + 32 + lane];
        }
        out[n * CC + lane] = a0;
        if (lane < CC - 32) out[n * CC + 32 + lane] = a1;
    }
}

// ---------------- launch ----------------
extern "C" void kernel_launch(void* const* d_in, const int* in_sizes, int n_in,
                              void* d_out, int out_size) {
    const float* x      = (const float*)d_in[0];
    const void*  eidx   = d_in[1];
    const float* gat_W1 = (const float*)d_in[2];
    const float* att_s1 = (const float*)d_in[3];
    const float* att_d1 = (const float*)d_in[4];
    const float* gat_b1 = (const float*)d_in[5];
    const float* gat_W2 = (const float*)d_in[6];
    const float* att_s2 = (const float*)d_in[7];
    const float* att_d2 = (const float*)d_in[8];
    const float* gat_b2 = (const float*)d_in[9];
    const float* gcn_W1 = (const float*)d_in[10];
    const float* gcn_b1 = (const float*)d_in[11];
    const float* gcn_W2 = (const float*)d_in[12];
    const float* gcn_b2 = (const float*)d_in[13];
    const float* lin_W  = (const float*)d_in[14];
    const float* lin_b  = (const float*)d_in[15];
    const float* wc     = (const float*)d_in[16];
    const float* wt     = (const float*)d_in[17];
    float*       out    = (float*)d_out;

    const int WPB = 8;
    const int AGG_BLK = (NN + WPB - 1) / WPB;

    // CSR build
    zero_init<<<(NN + 255) / 256, 256>>>();
    detect_idx<<<256, 256>>>((const unsigned int*)eidx);
    count_deg<<<(EP + 255) / 256, 256>>>(eidx);
    scan_phase1<<<SCAN_BLOCKS, SCAN_CHUNK>>>();
    scan_phase2<<<1, 32>>>();
    scan_phase3<<<(NN + 255) / 256, 256>>>();
    scatter_csr<<<(EP + 255) / 256, 256>>>(eidx);

    // Fused projection: h1 = x@W1, hg1 = x@gcnW1 (x read once)
    fused_proj<<<dim3((NCAT + BN - 1) / BN, (NN + BM - 1) / BM), 256>>>(x, gat_W1, gcn_W1);

    // Layer 1 (GAT1 + GCN1 fused over one CSR sweep)
    att_logits1<<<(NN * HEADS + 255) / 256, 256>>>(att_s1, att_d1);
    layer1_agg<<<AGG_BLK, WPB * 32>>>(gat_b1, gcn_b1);

    // Layer 2 projections
    sgemm_rb<<<dim3((CC + BN - 1) / BN, (NN + BM - 1) / BM), 256>>>(PTR_OUT1, gat_W2, PTR_H2, NN, CC, HH);
    att_logits2<<<(NN + 255) / 256, 256>>>(att_s2, att_d2);
    sgemm_rb<<<dim3((CC + BN - 1) / BN, (NN + BM - 1) / BM), 256>>>(PTR_GO1, gcn_W2, PTR_HG2, NN, CC, HID);

    // Layer 2 aggregation + final head (fused)
    layer2_head<<<AGG_BLK, WPB * 32>>>(gat_b2, gcn_b2, lin_W, lin_b, wc, wt, out);
}

// round 7
// speedup vs baseline: 1.3551x; 1.3551x over previous
#include <cuda_runtime.h>
#include <cuda_bf16.h>
#include <math.h>

// Problem constants (match reference)
#define NN     50000
#define EE     800000
#define EP     850000     // edges + self loops
#define F_IN   128
#define HID    32
#define HEADS  4
#define HH     128        // HEADS*HID
#define CC     40
#define NEG_SLOPE 0.2f

#define SCAN_CHUNK 1024
#define SCAN_BLOCKS ((NN + SCAN_CHUNK - 1) / SCAN_CHUNK)   // 49

// ---------------- scratch (device globals; no allocation allowed) ----------------
__device__ int   g_flag32;
__device__ int   g_deg[NN];
__device__ int   g_off[NN + 1];
__device__ int   g_cursor[NN];
__device__ int   g_bsum[SCAN_BLOCKS];
__device__ int   g_csr_src[EP];      // src node per CSR slot (grouped by dst)

__device__ float g_h1[NN * HH];      // x @ W1            [N,128]
__device__ float g_as1[NN * HEADS];
__device__ float g_ad1[NN * HEADS];
__device__ float g_out1[NN * HH];    // GAT1 out (elu'd)  [N,128]
__device__ float g_h2[NN * CC];      // out1 @ W2         [N,40]
__device__ float g_as2[NN];
__device__ float g_ad2[NN];
__device__ float g_out2[NN * CC];    // GAT2 out          [N,40]
__device__ float g_hg1[NN * HID];    // x @ gcnW1         [N,32]
__device__ float g_norm[NN];         // rsqrt(deg)
__device__ float g_go1[NN * HID];    // GCN1 out (relu'd) [N,32]
__device__ float g_hg2[NN * CC];     // go1 @ gcnW2       [N,40]
__device__ float g_go2[NN * CC];     // GCN2 out          [N,40]

// Device-side symbol table: never pass __device__ symbols from host (ATS trap).
#define PTR_H2   2
#define PTR_HG2  3
#define PTR_OUT1 4
#define PTR_GO1  5
__device__ __forceinline__ float* g_ptr(int id) {
    switch (id) {
        case PTR_H2:   return g_h2;
        case PTR_HG2:  return g_hg2;
        case PTR_OUT1: return g_out1;
        case PTR_GO1:  return g_go1;
    }
    return 0;
}

// ---------------- init ----------------
__global__ void zero_init() {
    int i = blockIdx.x * blockDim.x + threadIdx.x;
    if (i == 0) g_flag32 = 0;
    if (i < NN) g_deg[i] = 0;
}

// ---------------- dtype detect: int64 => every odd 32-bit word is 0 ----------------
__global__ void detect_idx(const unsigned int* __restrict__ raw) {
    int i = blockIdx.x * blockDim.x + threadIdx.x;   // 65536 samples
    unsigned v = raw[2 * i + 1];
    if (v != 0u) g_flag32 = 1;
}

__device__ __forceinline__ int load_node(const void* eidx, long long idx) {
    int v = g_flag32 ? ((const int*)eidx)[idx]
                     : (int)((const long long*)eidx)[idx];
    return min(max(v, 0), NN - 1);
}

// ---------------- pass 1: count degrees (incl. self loops) ----------------
__global__ void count_deg(const void* __restrict__ eidx) {
    int e = blockIdx.x * blockDim.x + threadIdx.x;
    if (e >= EP) return;
    int d = (e < EE) ? load_node(eidx, (long long)EE + e) : (e - EE);
    atomicAdd(&g_deg[d], 1);
}

// ---------------- 3-phase scan ----------------
__global__ void scan_phase1() {
    __shared__ int warp_sums[32];
    int b = blockIdx.x;
    int i = b * SCAN_CHUNK + threadIdx.x;
    int lane = threadIdx.x & 31, wid = threadIdx.x >> 5;
    int v = (i < NN) ? g_deg[i] : 0;
    int x = v;
#pragma unroll
    for (int s = 1; s < 32; s <<= 1) {
        int t = __shfl_up_sync(0xffffffff, x, s);
        if (lane >= s) x += t;
    }
    if (lane == 31) warp_sums[wid] = x;
    __syncthreads();
    if (wid == 0) {
        int ws = warp_sums[lane];
#pragma unroll
        for (int s = 1; s < 32; s <<= 1) {
            int t = __shfl_up_sync(0xffffffff, ws, s);
            if (lane >= s) ws += t;
        }
        warp_sums[lane] = ws;
    }
    __syncthreads();
    int prefix = (wid > 0) ? warp_sums[wid - 1] : 0;
    int excl = prefix + x - v;
    if (i < NN) g_off[i] = excl;
    if (threadIdx.x == SCAN_CHUNK - 1) g_bsum[b] = prefix + x;
}

__global__ void scan_phase2() {
    __shared__ int sh[64];
    int lane = threadIdx.x;
    int v0 = (lane < SCAN_BLOCKS) ? g_bsum[lane] : 0;
    int v1 = (lane + 32 < SCAN_BLOCKS) ? g_bsum[lane + 32] : 0;
    int x = v0;
#pragma unroll
    for (int s = 1; s < 32; s <<= 1) {
        int t = __shfl_up_sync(0xffffffff, x, s);
        if (lane >= s) x += t;
    }
    int tot0 = __shfl_sync(0xffffffff, x, 31);
    int y = v1;
#pragma unroll
    for (int s = 1; s < 32; s <<= 1) {
        int t = __shfl_up_sync(0xffffffff, y, s);
        if (lane >= s) y += t;
    }
    sh[lane] = x - v0;
    sh[lane + 32] = tot0 + y - v1;
    __syncwarp();
    if (lane < SCAN_BLOCKS) g_bsum[lane] = sh[lane];
    if (lane + 32 < SCAN_BLOCKS) g_bsum[lane + 32] = sh[lane + 32];
}

__global__ void scan_phase3() {
    int i = blockIdx.x * blockDim.x + threadIdx.x;
    if (i == 0) g_off[NN] = EP;
    if (i >= NN) return;
    int o = g_off[i] + g_bsum[i / SCAN_CHUNK];
    g_off[i] = o;
    g_cursor[i] = o;
    g_norm[i] = rsqrtf((float)g_deg[i]);
}

// ---------------- pass 2: scatter into CSR ----------------
__global__ void scatter_csr(const void* __restrict__ eidx) {
    int e = blockIdx.x * blockDim.x + threadIdx.x;
    if (e >= EP) return;
    int s, d;
    if (e < EE) {
        s = load_node(eidx, e);
        d = load_node(eidx, (long long)EE + e);
    } else {
        s = d = e - EE;
    }
    int pos = atomicAdd(&g_cursor[d], 1);
    g_csr_src[pos] = s;
}

// ---------------- fused first projection: reads x once ----------------
// Virtual B = [gat_W1 (128x128) | gcn_W1 (128x32)] -> NCAT = 160.
#define BM 64
#define BN 64
#define BK 16
#define NCAT (HH + HID)   // 160
__global__ void fused_proj(const float* __restrict__ x,
                           const float* __restrict__ W1,
                           const float* __restrict__ Wg) {
    __shared__ float As[BK][BM + 1];
    __shared__ float Bs[BK][BN];
    int tid = threadIdx.x;
    int tx = tid % 16, ty = tid / 16;
    int row0 = blockIdx.y * BM, col0 = blockIdx.x * BN;
    float acc[4][4] = {};
    for (int k0 = 0; k0 < F_IN; k0 += BK) {
        for (int i = tid; i < BM * BK; i += 256) {
            int r = i / BK, c = i % BK;
            int gr = row0 + r;
            As[c][r] = (gr < NN) ? x[gr * F_IN + k0 + c] : 0.f;
        }
        for (int i = tid; i < BK * BN; i += 256) {
            int r = i / BN, c = i % BN;
            int gc = col0 + c;
            float v;
            if (gc < HH) v = W1[(k0 + r) * HH + gc];
            else if (gc < NCAT) v = Wg[(k0 + r) * HID + (gc - HH)];
            else v = 0.f;
            Bs[r][c] = v;
        }
        __syncthreads();
#pragma unroll
        for (int k = 0; k < BK; k++) {
            float a[4], b[4];
#pragma unroll
            for (int i = 0; i < 4; i++) a[i] = As[k][ty * 4 + i];
#pragma unroll
            for (int j = 0; j < 4; j++) b[j] = Bs[k][tx * 4 + j];
#pragma unroll
            for (int i = 0; i < 4; i++)
#pragma unroll
                for (int j = 0; j < 4; j++) acc[i][j] += a[i] * b[j];
        }
        __syncthreads();
    }
#pragma unroll
    for (int i = 0; i < 4; i++) {
        int gr = row0 + ty * 4 + i;
        if (gr >= NN) continue;
#pragma unroll
        for (int j = 0; j < 4; j++) {
            int gc = col0 + tx * 4 + j;
            if (gc < HH) g_h1[gr * HH + gc] = acc[i][j];
            else if (gc < NCAT) g_hg1[gr * HID + (gc - HH)] = acc[i][j];
        }
    }
}

// ---------------- register-blocked SGEMM (device-tagged operands) ----------------
__global__ void sgemm_rb(int aid, const float* __restrict__ B, int cid,
                         int M, int Nn, int K) {
    const float* A = g_ptr(aid);
    float* Cm = g_ptr(cid);
    __shared__ float As[BK][BM + 1];
    __shared__ float Bs[BK][BN];
    int tid = threadIdx.x;
    int tx = tid % 16, ty = tid / 16;
    int row0 = blockIdx.y * BM, col0 = blockIdx.x * BN;
    float acc[4][4] = {};
    for (int k0 = 0; k0 < K; k0 += BK) {
        for (int i = tid; i < BM * BK; i += 256) {
            int r = i / BK, c = i % BK;
            int gr = row0 + r, gc = k0 + c;
            As[c][r] = (gr < M && gc < K) ? A[gr * K + gc] : 0.f;
        }
        for (int i = tid; i < BK * BN; i += 256) {
            int r = i / BN, c = i % BN;
            int gr = k0 + r, gc = col0 + c;
            Bs[r][c] = (gr < K && gc < Nn) ? B[gr * Nn + gc] : 0.f;
        }
        __syncthreads();
#pragma unroll
        for (int k = 0; k < BK; k++) {
            float a[4], b[4];
#pragma unroll
            for (int i = 0; i < 4; i++) a[i] = As[k][ty * 4 + i];
#pragma unroll
            for (int j = 0; j < 4; j++) b[j] = Bs[k][tx * 4 + j];
#pragma unroll
            for (int i = 0; i < 4; i++)
#pragma unroll
                for (int j = 0; j < 4; j++) acc[i][j] += a[i] * b[j];
        }
        __syncthreads();
    }
#pragma unroll
    for (int i = 0; i < 4; i++) {
        int gr = row0 + ty * 4 + i;
        if (gr >= M) continue;
#pragma unroll
        for (int j = 0; j < 4; j++) {
            int gc = col0 + tx * 4 + j;
            if (gc < Nn) Cm[gr * Nn + gc] = acc[i][j];
        }
    }
}

// ---------------- attention logits ----------------
__global__ void att_logits1(const float* __restrict__ att_src,
                            const float* __restrict__ att_dst) {
    int t = blockIdx.x * blockDim.x + threadIdx.x;
    if (t >= NN * HEADS) return;
    int n = t >> 2, h = t & 3;
    const float* hp = &g_h1[n * HH + h * HID];
    const float* as = &att_src[h * HID];
    const float* ad = &att_dst[h * HID];
    float s = 0.f, d = 0.f;
#pragma unroll
    for (int k = 0; k < HID; k++) { float v = hp[k]; s += v * as[k]; d += v * ad[k]; }
    g_as1[t] = s;
    g_ad1[t] = d;
}

__global__ void att_logits2(const float* __restrict__ att_src,
                            const float* __restrict__ att_dst) {
    int n = blockIdx.x * blockDim.x + threadIdx.x;
    if (n >= NN) return;
    const float* hp = &g_h2[n * CC];
    float s = 0.f, d = 0.f;
#pragma unroll
    for (int k = 0; k < CC; k++) { float v = hp[k]; s += v * att_src[k]; d += v * att_dst[k]; }
    g_as2[n] = s;
    g_ad2[n] = d;
}

// ---------------- GAT1 fused softmax + aggregation + bias + ELU ----------------
// One warp per dst node; lane owns features [lane*4, lane*4+4); head = lane>>3.
__global__ void gat1_agg_csr(const float* __restrict__ bias) {
    int warp = (blockIdx.x * blockDim.x + threadIdx.x) >> 5;
    if (warp >= NN) return;
    int lane = threadIdx.x & 31;
    int n = warp;
    int beg = g_off[n], end = g_off[n + 1];
    int h = lane >> 3;
    float ad = g_ad1[n * 4 + h];
    float4 acc = {0.f, 0.f, 0.f, 0.f};
    float sumw = 0.f;
    int p = beg;
    for (; p + 1 < end; p += 2) {
        int s0 = g_csr_src[p];
        int s1 = g_csr_src[p + 1];
        float l0 = g_as1[s0 * 4 + h] + ad;
        float l1 = g_as1[s1 * 4 + h] + ad;
        float4 h0 = *(const float4*)&g_h1[s0 * HH + lane * 4];
        float4 h1 = *(const float4*)&g_h1[s1 * HH + lane * 4];
        l0 = (l0 > 0.f) ? l0 : NEG_SLOPE * l0;
        l1 = (l1 > 0.f) ? l1 : NEG_SLOPE * l1;
        float w0 = __expf(l0);
        float w1 = __expf(l1);
        sumw += w0 + w1;
        acc.x += w0 * h0.x + w1 * h1.x;
        acc.y += w0 * h0.y + w1 * h1.y;
        acc.z += w0 * h0.z + w1 * h1.z;
        acc.w += w0 * h0.w + w1 * h1.w;
    }
    if (p < end) {
        int s0 = g_csr_src[p];
        float l0 = g_as1[s0 * 4 + h] + ad;
        float4 h0 = *(const float4*)&g_h1[s0 * HH + lane * 4];
        l0 = (l0 > 0.f) ? l0 : NEG_SLOPE * l0;
        float w0 = __expf(l0);
        sumw += w0;
        acc.x += w0 * h0.x; acc.y += w0 * h0.y; acc.z += w0 * h0.z; acc.w += w0 * h0.w;
    }
    float inv = 1.f / sumw;
    float4 bv = *(const float4*)&bias[lane * 4];
    float4 o;
    float vx = acc.x * inv + bv.x; o.x = (vx > 0.f) ? vx : expm1f(vx);
    float vy = acc.y * inv + bv.y; o.y = (vy > 0.f) ? vy : expm1f(vy);
    float vz = acc.z * inv + bv.z; o.z = (vz > 0.f) ? vz : expm1f(vz);
    float vw = acc.w * inv + bv.w; o.w = (vw > 0.f) ? vw : expm1f(vw);
    *(float4*)&g_out1[n * HH + lane * 4] = o;
}

// ---------------- GAT2 fused softmax + aggregation ----------------
__global__ void gat2_agg_csr() {
    int warp = (blockIdx.x * blockDim.x + threadIdx.x) >> 5;
    if (warp >= NN) return;
    int lane = threadIdx.x & 31;
    int n = warp;
    int beg = g_off[n], end = g_off[n + 1];
    float ad = g_ad2[n];
    float acc1 = 0.f, acc2 = 0.f, sumw = 0.f;
    int p = beg;
    for (; p + 1 < end; p += 2) {
        int s0 = g_csr_src[p];
        int s1 = g_csr_src[p + 1];
        float l0 = g_as2[s0] + ad;
        float l1 = g_as2[s1] + ad;
        float a0 = g_h2[s0 * CC + lane];
        float a1 = g_h2[s1 * CC + lane];
        float b0 = (lane < CC - 32) ? g_h2[s0 * CC + 32 + lane] : 0.f;
        float b1 = (lane < CC - 32) ? g_h2[s1 * CC + 32 + lane] : 0.f;
        l0 = (l0 > 0.f) ? l0 : NEG_SLOPE * l0;
        l1 = (l1 > 0.f) ? l1 : NEG_SLOPE * l1;
        float w0 = __expf(l0), w1 = __expf(l1);
        sumw += w0 + w1;
        acc1 += w0 * a0 + w1 * a1;
        acc2 += w0 * b0 + w1 * b1;
    }
    if (p < end) {
        int s0 = g_csr_src[p];
        float l0 = g_as2[s0] + ad;
        float a0 = g_h2[s0 * CC + lane];
        float b0 = (lane < CC - 32) ? g_h2[s0 * CC + 32 + lane] : 0.f;
        l0 = (l0 > 0.f) ? l0 : NEG_SLOPE * l0;
        float w0 = __expf(l0);
        sumw += w0;
        acc1 += w0 * a0;
        acc2 += w0 * b0;
    }
    float inv = 1.f / sumw;
    g_out2[n * CC + lane] = acc1 * inv;
    if (lane < CC - 32) g_out2[n * CC + 32 + lane] = acc2 * inv;
}

// ---------------- GCN1 fused aggregation + bias + ReLU ----------------
__global__ void gcn1_agg_csr(const float* __restrict__ bias) {
    int warp = (blockIdx.x * blockDim.x + threadIdx.x) >> 5;
    if (warp >= NN) return;
    int lane = threadIdx.x & 31;
    int n = warp;
    int beg = g_off[n], end = g_off[n + 1];
    float nd = g_norm[n];
    float acc = 0.f;
    int p = beg;
    for (; p + 1 < end; p += 2) {
        int s0 = g_csr_src[p];
        int s1 = g_csr_src[p + 1];
        float c0 = g_norm[s0];
        float c1 = g_norm[s1];
        float v0 = g_hg1[s0 * HID + lane];
        float v1 = g_hg1[s1 * HID + lane];
        acc += c0 * v0 + c1 * v1;
    }
    if (p < end) {
        int s0 = g_csr_src[p];
        acc += g_norm[s0] * g_hg1[s0 * HID + lane];
    }
    float v = acc * nd + bias[lane];
    g_go1[n * HID + lane] = (v > 0.f) ? v : 0.f;
}

// ---------------- GCN2 aggregation ----------------
__global__ void gcn2_agg_csr() {
    int warp = (blockIdx.x * blockDim.x + threadIdx.x) >> 5;
    if (warp >= NN) return;
    int lane = threadIdx.x & 31;
    int n = warp;
    int beg = g_off[n], end = g_off[n + 1];
    float nd = g_norm[n];
    float acc1 = 0.f, acc2 = 0.f;
    int p = beg;
    for (; p + 1 < end; p += 2) {
        int s0 = g_csr_src[p];
        int s1 = g_csr_src[p + 1];
        float c0 = g_norm[s0], c1 = g_norm[s1];
        float a0 = g_hg2[s0 * CC + lane];
        float a1 = g_hg2[s1 * CC + lane];
        float b0 = (lane < CC - 32) ? g_hg2[s0 * CC + 32 + lane] : 0.f;
        float b1 = (lane < CC - 32) ? g_hg2[s1 * CC + 32 + lane] : 0.f;
        acc1 += c0 * a0 + c1 * a1;
        acc2 += c0 * b0 + c1 * b1;
    }
    if (p < end) {
        int s0 = g_csr_src[p];
        float c0 = g_norm[s0];
        acc1 += c0 * g_hg2[s0 * CC + lane];
        if (lane < CC - 32) acc2 += c0 * g_hg2[s0 * CC + 32 + lane];
    }
    g_go2[n * CC + lane] = acc1 * nd;
    if (lane < CC - 32) g_go2[n * CC + 32 + lane] = acc2 * nd;
}

// ---------------- final head ----------------
__global__ void final_head(const float* __restrict__ gat_b2,
                           const float* __restrict__ gcn_b2,
                           const float* __restrict__ lin_W,
                           const float* __restrict__ lin_b,
                           const float* __restrict__ wc_p,
                           const float* __restrict__ wt_p,
                           float* __restrict__ out) {
    int t = blockIdx.x * blockDim.x + threadIdx.x;
    if (t >= NN * CC) return;
    int n = t / CC, co = t % CC;
    float wc = *wc_p, wt = *wt_p;
    float acc = lin_b[co];
    const float* gcn = &g_go2[n * CC];
    const float* gat = &g_out2[n * CC];
#pragma unroll
    for (int j = 0; j < CC; j++)
        acc += (gcn[j] + gcn_b2[j]) * wc * lin_W[j * CC + co];
#pragma unroll
    for (int j = 0; j < CC; j++)
        acc += (gat[j] + gat_b2[j]) * wt * lin_W[(CC + j) * CC + co];
    out[t] = acc;
}

// ---------------- launch ----------------
extern "C" void kernel_launch(void* const* d_in, const int* in_sizes, int n_in,
                              void* d_out, int out_size) {
    const float* x      = (const float*)d_in[0];
    const void*  eidx   = d_in[1];
    const float* gat_W1 = (const float*)d_in[2];
    const float* att_s1 = (const float*)d_in[3];
    const float* att_d1 = (const float*)d_in[4];
    const float* gat_b1 = (const float*)d_in[5];
    const float* gat_W2 = (const float*)d_in[6];
    const float* att_s2 = (const float*)d_in[7];
    const float* att_d2 = (const float*)d_in[8];
    const float* gat_b2 = (const float*)d_in[9];
    const float* gcn_W1 = (const float*)d_in[10];
    const float* gcn_b1 = (const float*)d_in[11];
    const float* gcn_W2 = (const float*)d_in[12];
    const float* gcn_b2 = (const float*)d_in[13];
    const float* lin_W  = (const float*)d_in[14];
    const float* lin_b  = (const float*)d_in[15];
    const float* wc     = (const float*)d_in[16];
    const float* wt     = (const float*)d_in[17];
    float*       out    = (float*)d_out;

    const int WPB = 8;
    const int AGG_BLK = (NN + WPB - 1) / WPB;

    // CSR build
    zero_init<<<(NN + 255) / 256, 256>>>();
    detect_idx<<<256, 256>>>((const unsigned int*)eidx);
    count_deg<<<(EP + 255) / 256, 256>>>(eidx);
    scan_phase1<<<SCAN_BLOCKS, SCAN_CHUNK>>>();
    scan_phase2<<<1, 32>>>();
    scan_phase3<<<(NN + 255) / 256, 256>>>();
    scatter_csr<<<(EP + 255) / 256, 256>>>(eidx);

    // Fused projection: h1 = x@W1, hg1 = x@gcnW1 (x read once)
    fused_proj<<<dim3((NCAT + BN - 1) / BN, (NN + BM - 1) / BM), 256>>>(x, gat_W1, gcn_W1);

    // GAT layer 1
    att_logits1<<<(NN * HEADS + 255) / 256, 256>>>(att_s1, att_d1);
    gat1_agg_csr<<<AGG_BLK, WPB * 32>>>(gat_b1);

    // GAT layer 2
    sgemm_rb<<<dim3((CC + BN - 1) / BN, (NN + BM - 1) / BM), 256>>>(PTR_OUT1, gat_W2, PTR_H2, NN, CC, HH);
    att_logits2<<<(NN + 255) / 256, 256>>>(att_s2, att_d2);
    gat2_agg_csr<<<AGG_BLK, WPB * 32>>>();

    // GCN branch
    gcn1_agg_csr<<<AGG_BLK, WPB * 32>>>(gcn_b1);
    sgemm_rb<<<dim3((CC + BN - 1) / BN, (NN + BM - 1) / BM), 256>>>(PTR_GO1, gcn_W2, PTR_HG2, NN, CC, HID);
    gcn2_agg_csr<<<AGG_BLK, WPB * 32>>>();

    // Final linear head
    final_head<<<(NN * CC + 255) / 256, 256>>>(gat_b2, gcn_b2, lin_W, lin_b, wc, wt, out);
}

// round 8
// speedup vs baseline: 1.4873x; 1.0975x over previous
#include <cuda_runtime.h>
#include <cuda_bf16.h>
#include <math.h>

// Problem constants (match reference)
#define NN     50000
#define EE     800000
#define EP     850000     // edges + self loops
#define F_IN   128
#define HID    32
#define HEADS  4
#define HH     128        // HEADS*HID
#define CC     40
#define NEG_SLOPE 0.2f

#define SCAN_CHUNK 1024
#define SCAN_BLOCKS ((NN + SCAN_CHUNK - 1) / SCAN_CHUNK)   // 49

// ---------------- scratch (device globals; no allocation allowed) ----------------
__device__ int   g_flag32;
__device__ int   g_deg[NN];
__device__ int   g_off[NN + 1];
__device__ int   g_cursor[NN];
__device__ int   g_bsum[SCAN_BLOCKS];
__device__ int   g_csr_src[EP];      // src node per CSR slot (grouped by dst)

__device__ float g_comb1[F_IN * 8];  // [f, 0..3]=W1@att_src1 blockdiag, [f,4..7]=dst
__device__ float g_comb2[F_IN * 2];  // [f,0]=W2@att_s2, [f,1]=W2@att_d2

__device__ float g_h1[NN * HH];      // x @ W1            [N,128]
__device__ float g_as1[NN * HEADS];
__device__ float g_ad1[NN * HEADS];
__device__ float g_out1[NN * HH];    // GAT1 out (elu'd)  [N,128]
__device__ float g_h2[NN * CC];      // out1 @ W2         [N,40]
__device__ float g_as2[NN];
__device__ float g_ad2[NN];
__device__ float g_out2[NN * CC];    // GAT2 out          [N,40]
__device__ float g_hg1[NN * HID];    // x @ gcnW1         [N,32]
__device__ float g_norm[NN];         // rsqrt(deg)
__device__ float g_go1[NN * HID];    // GCN1 out (relu'd) [N,32]
__device__ float g_hg2[NN * CC];     // go1 @ gcnW2       [N,40]
__device__ float g_go2[NN * CC];     // GCN2 out          [N,40]

// Device-side symbol table: never pass __device__ symbols from host (ATS trap).
#define PTR_HG2  3
#define PTR_GO1  5
__device__ __forceinline__ float* g_ptr(int id) {
    switch (id) {
        case PTR_HG2:  return g_hg2;
        case PTR_GO1:  return g_go1;
    }
    return 0;
}

// ---------------- init ----------------
__global__ void zero_init() {
    int i = blockIdx.x * blockDim.x + threadIdx.x;
    if (i == 0) g_flag32 = 0;
    if (i < NN) g_deg[i] = 0;
}

// ---------------- dtype detect: int64 => every odd 32-bit word is 0 ----------------
__global__ void detect_idx(const unsigned int* __restrict__ raw) {
    int i = blockIdx.x * blockDim.x + threadIdx.x;   // 65536 samples
    unsigned v = raw[2 * i + 1];
    if (v != 0u) g_flag32 = 1;
}

__device__ __forceinline__ int load_node(const void* eidx, long long idx) {
    int v = g_flag32 ? ((const int*)eidx)[idx]
                     : (int)((const long long*)eidx)[idx];
    return min(max(v, 0), NN - 1);
}

// ---------------- pass 1: count degrees (incl. self loops) ----------------
__global__ void count_deg(const void* __restrict__ eidx) {
    int e = blockIdx.x * blockDim.x + threadIdx.x;
    if (e >= EP) return;
    int d = (e < EE) ? load_node(eidx, (long long)EE + e) : (e - EE);
    atomicAdd(&g_deg[d], 1);
}

// ---------------- 3-phase scan ----------------
__global__ void scan_phase1() {
    __shared__ int warp_sums[32];
    int b = blockIdx.x;
    int i = b * SCAN_CHUNK + threadIdx.x;
    int lane = threadIdx.x & 31, wid = threadIdx.x >> 5;
    int v = (i < NN) ? g_deg[i] : 0;
    int x = v;
#pragma unroll
    for (int s = 1; s < 32; s <<= 1) {
        int t = __shfl_up_sync(0xffffffff, x, s);
        if (lane >= s) x += t;
    }
    if (lane == 31) warp_sums[wid] = x;
    __syncthreads();
    if (wid == 0) {
        int ws = warp_sums[lane];
#pragma unroll
        for (int s = 1; s < 32; s <<= 1) {
            int t = __shfl_up_sync(0xffffffff, ws, s);
            if (lane >= s) ws += t;
        }
        warp_sums[lane] = ws;
    }
    __syncthreads();
    int prefix = (wid > 0) ? warp_sums[wid - 1] : 0;
    int excl = prefix + x - v;
    if (i < NN) g_off[i] = excl;
    if (threadIdx.x == SCAN_CHUNK - 1) g_bsum[b] = prefix + x;
}

__global__ void scan_phase2() {
    __shared__ int sh[64];
    int lane = threadIdx.x;
    int v0 = (lane < SCAN_BLOCKS) ? g_bsum[lane] : 0;
    int v1 = (lane + 32 < SCAN_BLOCKS) ? g_bsum[lane + 32] : 0;
    int x = v0;
#pragma unroll
    for (int s = 1; s < 32; s <<= 1) {
        int t = __shfl_up_sync(0xffffffff, x, s);
        if (lane >= s) x += t;
    }
    int tot0 = __shfl_sync(0xffffffff, x, 31);
    int y = v1;
#pragma unroll
    for (int s = 1; s < 32; s <<= 1) {
        int t = __shfl_up_sync(0xffffffff, y, s);
        if (lane >= s) y += t;
    }
    sh[lane] = x - v0;
    sh[lane + 32] = tot0 + y - v1;
    __syncwarp();
    if (lane < SCAN_BLOCKS) g_bsum[lane] = sh[lane];
    if (lane + 32 < SCAN_BLOCKS) g_bsum[lane + 32] = sh[lane + 32];
}

__global__ void scan_phase3() {
    int i = blockIdx.x * blockDim.x + threadIdx.x;
    if (i == 0) g_off[NN] = EP;
    if (i >= NN) return;
    int o = g_off[i] + g_bsum[i / SCAN_CHUNK];
    g_off[i] = o;
    g_cursor[i] = o;
    g_norm[i] = rsqrtf((float)g_deg[i]);
}

// ---------------- pass 2: scatter into CSR ----------------
__global__ void scatter_csr(const void* __restrict__ eidx) {
    int e = blockIdx.x * blockDim.x + threadIdx.x;
    if (e >= EP) return;
    int s, d;
    if (e < EE) {
        s = load_node(eidx, e);
        d = load_node(eidx, (long long)EE + e);
    } else {
        s = d = e - EE;
    }
    int pos = atomicAdd(&g_cursor[d], 1);
    g_csr_src[pos] = s;
}

// ---------------- precompute combined attention matrices ----------------
// comb1[f, h]   = sum_d gat_W1[f, h*32+d] * att_src1[h, d]   (h<4)
// comb1[f, 4+h] = same with att_dst1
// comb2[f, 0/1] = sum_c gat_W2[f, c] * att_{s,d}2[c]
__global__ void precompute_comb(const float* __restrict__ gat_W1,
                                const float* __restrict__ att_s1,
                                const float* __restrict__ att_d1,
                                const float* __restrict__ gat_W2,
                                const float* __restrict__ att_s2,
                                const float* __restrict__ att_d2) {
    int t = blockIdx.x * blockDim.x + threadIdx.x;
    if (t < 1024) {
        int f = (t >> 3);            // 0..127
        int j = t & 7;               // 0..7
        int h = j & 3;
        const float* av = (j < 4) ? &att_s1[h * HID] : &att_d1[h * HID];
        const float* wr = &gat_W1[f * HH + h * HID];
        float s = 0.f;
#pragma unroll
        for (int d = 0; d < HID; d++) s += wr[d] * av[d];
        g_comb1[f * 8 + j] = s;
    } else if (t < 1024 + 256) {
        int u = t - 1024;
        int f = u >> 1;
        const float* av = (u & 1) ? att_d2 : att_s2;
        const float* wr = &gat_W2[f * CC];
        float s = 0.f;
#pragma unroll
        for (int c = 0; c < CC; c++) s += wr[c] * av[c];
        g_comb2[f * 2 + (u & 1)] = s;
    }
}

// ---------------- fused first projection + attention logits ----------------
// Virtual B = [gat_W1 (128x128) | gcn_W1 (128x32) | comb1 (128x8)] -> 168 cols.
#define BM 64
#define BN 64
#define BK 16
#define NCAT (HH + HID + 8)   // 168
__global__ void fused_proj(const float* __restrict__ x,
                           const float* __restrict__ W1,
                           const float* __restrict__ Wg) {
    __shared__ float As[BK][BM + 1];
    __shared__ float Bs[BK][BN];
    int tid = threadIdx.x;
    int tx = tid % 16, ty = tid / 16;
    int row0 = blockIdx.y * BM, col0 = blockIdx.x * BN;
    float acc[4][4] = {};
    for (int k0 = 0; k0 < F_IN; k0 += BK) {
        for (int i = tid; i < BM * BK; i += 256) {
            int r = i / BK, c = i % BK;
            int gr = row0 + r;
            As[c][r] = (gr < NN) ? x[gr * F_IN + k0 + c] : 0.f;
        }
        for (int i = tid; i < BK * BN; i += 256) {
            int r = i / BN, c = i % BN;
            int gc = col0 + c;
            float v;
            if (gc < HH) v = W1[(k0 + r) * HH + gc];
            else if (gc < HH + HID) v = Wg[(k0 + r) * HID + (gc - HH)];
            else if (gc < NCAT) v = g_comb1[(k0 + r) * 8 + (gc - HH - HID)];
            else v = 0.f;
            Bs[r][c] = v;
        }
        __syncthreads();
#pragma unroll
        for (int k = 0; k < BK; k++) {
            float a[4], b[4];
#pragma unroll
            for (int i = 0; i < 4; i++) a[i] = As[k][ty * 4 + i];
#pragma unroll
            for (int j = 0; j < 4; j++) b[j] = Bs[k][tx * 4 + j];
#pragma unroll
            for (int i = 0; i < 4; i++)
#pragma unroll
                for (int j = 0; j < 4; j++) acc[i][j] += a[i] * b[j];
        }
        __syncthreads();
    }
#pragma unroll
    for (int i = 0; i < 4; i++) {
        int gr = row0 + ty * 4 + i;
        if (gr >= NN) continue;
#pragma unroll
        for (int j = 0; j < 4; j++) {
            int gc = col0 + tx * 4 + j;
            if (gc < HH) g_h1[gr * HH + gc] = acc[i][j];
            else if (gc < HH + HID) g_hg1[gr * HID + (gc - HH)] = acc[i][j];
            else if (gc < HH + HID + 4) g_as1[gr * 4 + (gc - HH - HID)] = acc[i][j];
            else if (gc < NCAT) g_ad1[gr * 4 + (gc - HH - HID - 4)] = acc[i][j];
        }
    }
}

// ---------------- layer-2 GAT projection + logits: out1 @ [W2 | comb2] --------
// Nn = 42: cols 0..39 -> g_h2, col 40 -> g_as2, col 41 -> g_ad2.
__global__ void gemm_l2(const float* __restrict__ W2) {
    const float* A = g_out1;
    __shared__ float As[BK][BM + 1];
    __shared__ float Bs[BK][BN];
    int tid = threadIdx.x;
    int tx = tid % 16, ty = tid / 16;
    int row0 = blockIdx.y * BM;
    float acc[4][4] = {};
    for (int k0 = 0; k0 < HH; k0 += BK) {
        for (int i = tid; i < BM * BK; i += 256) {
            int r = i / BK, c = i % BK;
            int gr = row0 + r;
            As[c][r] = (gr < NN) ? A[gr * HH + k0 + c] : 0.f;
        }
        for (int i = tid; i < BK * BN; i += 256) {
            int r = i / BN, c = i % BN;
            float v;
            if (c < CC) v = W2[(k0 + r) * CC + c];
            else if (c < CC + 2) v = g_comb2[(k0 + r) * 2 + (c - CC)];
            else v = 0.f;
            Bs[r][c] = v;
        }
        __syncthreads();
#pragma unroll
        for (int k = 0; k < BK; k++) {
            float a[4], b[4];
#pragma unroll
            for (int i = 0; i < 4; i++) a[i] = As[k][ty * 4 + i];
#pragma unroll
            for (int j = 0; j < 4; j++) b[j] = Bs[k][tx * 4 + j];
#pragma unroll
            for (int i = 0; i < 4; i++)
#pragma unroll
                for (int j = 0; j < 4; j++) acc[i][j] += a[i] * b[j];
        }
        __syncthreads();
    }
#pragma unroll
    for (int i = 0; i < 4; i++) {
        int gr = row0 + ty * 4 + i;
        if (gr >= NN) continue;
#pragma unroll
        for (int j = 0; j < 4; j++) {
            int gc = tx * 4 + j;
            if (gc < CC) g_h2[gr * CC + gc] = acc[i][j];
            else if (gc == CC) g_as2[gr] = acc[i][j];
            else if (gc == CC + 1) g_ad2[gr] = acc[i][j];
        }
    }
}

// ---------------- generic register-blocked SGEMM (device-tagged operands) -------
__global__ void sgemm_rb(int aid, const float* __restrict__ B, int cid,
                         int M, int Nn, int K) {
    const float* A = g_ptr(aid);
    float* Cm = g_ptr(cid);
    __shared__ float As[BK][BM + 1];
    __shared__ float Bs[BK][BN];
    int tid = threadIdx.x;
    int tx = tid % 16, ty = tid / 16;
    int row0 = blockIdx.y * BM, col0 = blockIdx.x * BN;
    float acc[4][4] = {};
    for (int k0 = 0; k0 < K; k0 += BK) {
        for (int i = tid; i < BM * BK; i += 256) {
            int r = i / BK, c = i % BK;
            int gr = row0 + r, gc = k0 + c;
            As[c][r] = (gr < M && gc < K) ? A[gr * K + gc] : 0.f;
        }
        for (int i = tid; i < BK * BN; i += 256) {
            int r = i / BN, c = i % BN;
            int gr = k0 + r, gc = col0 + c;
            Bs[r][c] = (gr < K && gc < Nn) ? B[gr * Nn + gc] : 0.f;
        }
        __syncthreads();
#pragma unroll
        for (int k = 0; k < BK; k++) {
            float a[4], b[4];
#pragma unroll
            for (int i = 0; i < 4; i++) a[i] = As[k][ty * 4 + i];
#pragma unroll
            for (int j = 0; j < 4; j++) b[j] = Bs[k][tx * 4 + j];
#pragma unroll
            for (int i = 0; i < 4; i++)
#pragma unroll
                for (int j = 0; j < 4; j++) acc[i][j] += a[i] * b[j];
        }
        __syncthreads();
    }
#pragma unroll
    for (int i = 0; i < 4; i++) {
        int gr = row0 + ty * 4 + i;
        if (gr >= M) continue;
#pragma unroll
        for (int j = 0; j < 4; j++) {
            int gc = col0 + tx * 4 + j;
            if (gc < Nn) Cm[gr * Nn + gc] = acc[i][j];
        }
    }
}

// ---------------- GAT1 fused softmax + aggregation + bias + ELU ----------------
// One warp per dst node; lane owns features [lane*4, lane*4+4); head = lane>>3.
// 4x edge unroll: 4 concurrent gather chains on the same arrays.
__global__ void gat1_agg_csr(const float* __restrict__ bias) {
    int warp = (blockIdx.x * blockDim.x + threadIdx.x) >> 5;
    if (warp >= NN) return;
    int lane = threadIdx.x & 31;
    int n = warp;
    int beg = g_off[n], end = g_off[n + 1];
    int h = lane >> 3;
    float ad = g_ad1[n * 4 + h];
    float4 acc = {0.f, 0.f, 0.f, 0.f};
    float sumw = 0.f;
    int p = beg;
    for (; p + 3 < end; p += 4) {
        int s0 = g_csr_src[p];
        int s1 = g_csr_src[p + 1];
        int s2 = g_csr_src[p + 2];
        int s3 = g_csr_src[p + 3];
        float l0 = g_as1[s0 * 4 + h] + ad;
        float l1 = g_as1[s1 * 4 + h] + ad;
        float l2 = g_as1[s2 * 4 + h] + ad;
        float l3 = g_as1[s3 * 4 + h] + ad;
        float4 h0 = *(const float4*)&g_h1[s0 * HH + lane * 4];
        float4 h1 = *(const float4*)&g_h1[s1 * HH + lane * 4];
        float4 h2 = *(const float4*)&g_h1[s2 * HH + lane * 4];
        float4 h3 = *(const float4*)&g_h1[s3 * HH + lane * 4];
        l0 = (l0 > 0.f) ? l0 : NEG_SLOPE * l0;
        l1 = (l1 > 0.f) ? l1 : NEG_SLOPE * l1;
        l2 = (l2 > 0.f) ? l2 : NEG_SLOPE * l2;
        l3 = (l3 > 0.f) ? l3 : NEG_SLOPE * l3;
        float w0 = __expf(l0), w1 = __expf(l1), w2 = __expf(l2), w3 = __expf(l3);
        sumw += (w0 + w1) + (w2 + w3);
        acc.x += w0 * h0.x + w1 * h1.x + w2 * h2.x + w3 * h3.x;
        acc.y += w0 * h0.y + w1 * h1.y + w2 * h2.y + w3 * h3.y;
        acc.z += w0 * h0.z + w1 * h1.z + w2 * h2.z + w3 * h3.z;
        acc.w += w0 * h0.w + w1 * h1.w + w2 * h2.w + w3 * h3.w;
    }
    for (; p < end; p++) {
        int s0 = g_csr_src[p];
        float l0 = g_as1[s0 * 4 + h] + ad;
        float4 h0 = *(const float4*)&g_h1[s0 * HH + lane * 4];
        l0 = (l0 > 0.f) ? l0 : NEG_SLOPE * l0;
        float w0 = __expf(l0);
        sumw += w0;
        acc.x += w0 * h0.x; acc.y += w0 * h0.y; acc.z += w0 * h0.z; acc.w += w0 * h0.w;
    }
    float inv = 1.f / sumw;
    float4 bv = *(const float4*)&bias[lane * 4];
    float4 o;
    float vx = acc.x * inv + bv.x; o.x = (vx > 0.f) ? vx : expm1f(vx);
    float vy = acc.y * inv + bv.y; o.y = (vy > 0.f) ? vy : expm1f(vy);
    float vz = acc.z * inv + bv.z; o.z = (vz > 0.f) ? vz : expm1f(vz);
    float vw = acc.w * inv + bv.w; o.w = (vw > 0.f) ? vw : expm1f(vw);
    *(float4*)&g_out1[n * HH + lane * 4] = o;
}

// ---------------- GAT2 fused softmax + aggregation ----------------
__global__ void gat2_agg_csr() {
    int warp = (blockIdx.x * blockDim.x + threadIdx.x) >> 5;
    if (warp >= NN) return;
    int lane = threadIdx.x & 31;
    int n = warp;
    int beg = g_off[n], end = g_off[n + 1];
    float ad = g_ad2[n];
    float acc1 = 0.f, acc2 = 0.f, sumw = 0.f;
    int p = beg;
    for (; p + 1 < end; p += 2) {
        int s0 = g_csr_src[p];
        int s1 = g_csr_src[p + 1];
        float l0 = g_as2[s0] + ad;
        float l1 = g_as2[s1] + ad;
        float a0 = g_h2[s0 * CC + lane];
        float a1 = g_h2[s1 * CC + lane];
        float b0 = (lane < CC - 32) ? g_h2[s0 * CC + 32 + lane] : 0.f;
        float b1 = (lane < CC - 32) ? g_h2[s1 * CC + 32 + lane] : 0.f;
        l0 = (l0 > 0.f) ? l0 : NEG_SLOPE * l0;
        l1 = (l1 > 0.f) ? l1 : NEG_SLOPE * l1;
        float w0 = __expf(l0), w1 = __expf(l1);
        sumw += w0 + w1;
        acc1 += w0 * a0 + w1 * a1;
        acc2 += w0 * b0 + w1 * b1;
    }
    if (p < end) {
        int s0 = g_csr_src[p];
        float l0 = g_as2[s0] + ad;
        float a0 = g_h2[s0 * CC + lane];
        float b0 = (lane < CC - 32) ? g_h2[s0 * CC + 32 + lane] : 0.f;
        l0 = (l0 > 0.f) ? l0 : NEG_SLOPE * l0;
        float w0 = __expf(l0);
        sumw += w0;
        acc1 += w0 * a0;
        acc2 += w0 * b0;
    }
    float inv = 1.f / sumw;
    g_out2[n * CC + lane] = acc1 * inv;
    if (lane < CC - 32) g_out2[n * CC + 32 + lane] = acc2 * inv;
}

// ---------------- GCN1 fused aggregation + bias + ReLU ----------------
__global__ void gcn1_agg_csr(const float* __restrict__ bias) {
    int warp = (blockIdx.x * blockDim.x + threadIdx.x) >> 5;
    if (warp >= NN) return;
    int lane = threadIdx.x & 31;
    int n = warp;
    int beg = g_off[n], end = g_off[n + 1];
    float nd = g_norm[n];
    float acc = 0.f;
    int p = beg;
    for (; p + 1 < end; p += 2) {
        int s0 = g_csr_src[p];
        int s1 = g_csr_src[p + 1];
        float c0 = g_norm[s0];
        float c1 = g_norm[s1];
        float v0 = g_hg1[s0 * HID + lane];
        float v1 = g_hg1[s1 * HID + lane];
        acc += c0 * v0 + c1 * v1;
    }
    if (p < end) {
        int s0 = g_csr_src[p];
        acc += g_norm[s0] * g_hg1[s0 * HID + lane];
    }
    float v = acc * nd + bias[lane];
    g_go1[n * HID + lane] = (v > 0.f) ? v : 0.f;
}

// ---------------- GCN2 aggregation ----------------
__global__ void gcn2_agg_csr() {
    int warp = (blockIdx.x * blockDim.x + threadIdx.x) >> 5;
    if (warp >= NN) return;
    int lane = threadIdx.x & 31;
    int n = warp;
    int beg = g_off[n], end = g_off[n + 1];
    float nd = g_norm[n];
    float acc1 = 0.f, acc2 = 0.f;
    int p = beg;
    for (; p + 1 < end; p += 2) {
        int s0 = g_csr_src[p];
        int s1 = g_csr_src[p + 1];
        float c0 = g_norm[s0], c1 = g_norm[s1];
        float a0 = g_hg2[s0 * CC + lane];
        float a1 = g_hg2[s1 * CC + lane];
        float b0 = (lane < CC - 32) ? g_hg2[s0 * CC + 32 + lane] : 0.f;
        float b1 = (lane < CC - 32) ? g_hg2[s1 * CC + 32 + lane] : 0.f;
        acc1 += c0 * a0 + c1 * a1;
        acc2 += c0 * b0 + c1 * b1;
    }
    if (p < end) {
        int s0 = g_csr_src[p];
        float c0 = g_norm[s0];
        acc1 += c0 * g_hg2[s0 * CC + lane];
        if (lane < CC - 32) acc2 += c0 * g_hg2[s0 * CC + 32 + lane];
    }
    g_go2[n * CC + lane] = acc1 * nd;
    if (lane < CC - 32) g_go2[n * CC + 32 + lane] = acc2 * nd;
}

// ---------------- final head ----------------
__global__ void final_head(const float* __restrict__ gat_b2,
                           const float* __restrict__ gcn_b2,
                           const float* __restrict__ lin_W,
                           const float* __restrict__ lin_b,
                           const float* __restrict__ wc_p,
                           const float* __restrict__ wt_p,
                           float* __restrict__ out) {
    int t = blockIdx.x * blockDim.x + threadIdx.x;
    if (t >= NN * CC) return;
    int n = t / CC, co = t % CC;
    float wc = *wc_p, wt = *wt_p;
    float acc = lin_b[co];
    const float* gcn = &g_go2[n * CC];
    const float* gat = &g_out2[n * CC];
#pragma unroll
    for (int j = 0; j < CC; j++)
        acc += (gcn[j] + gcn_b2[j]) * wc * lin_W[j * CC + co];
#pragma unroll
    for (int j = 0; j < CC; j++)
        acc += (gat[j] + gat_b2[j]) * wt * lin_W[(CC + j) * CC + co];
    out[t] = acc;
}

// ---------------- launch ----------------
extern "C" void kernel_launch(void* const* d_in, const int* in_sizes, int n_in,
                              void* d_out, int out_size) {
    const float* x      = (const float*)d_in[0];
    const void*  eidx   = d_in[1];
    const float* gat_W1 = (const float*)d_in[2];
    const float* att_s1 = (const float*)d_in[3];
    const float* att_d1 = (const float*)d_in[4];
    const float* gat_b1 = (const float*)d_in[5];
    const float* gat_W2 = (const float*)d_in[6];
    const float* att_s2 = (const float*)d_in[7];
    const float* att_d2 = (const float*)d_in[8];
    const float* gat_b2 = (const float*)d_in[9];
    const float* gcn_W1 = (const float*)d_in[10];
    const float* gcn_b1 = (const float*)d_in[11];
    const float* gcn_W2 = (const float*)d_in[12];
    const float* gcn_b2 = (const float*)d_in[13];
    const float* lin_W  = (const float*)d_in[14];
    const float* lin_b  = (const float*)d_in[15];
    const float* wc     = (const float*)d_in[16];
    const float* wt     = (const float*)d_in[17];
    float*       out    = (float*)d_out;

    const int WPB = 8;
    const int AGG_BLK = (NN + WPB - 1) / WPB;

    // CSR build
    zero_init<<<(NN + 255) / 256, 256>>>();
    detect_idx<<<256, 256>>>((const unsigned int*)eidx);
    count_deg<<<(EP + 255) / 256, 256>>>(eidx);
    scan_phase1<<<SCAN_BLOCKS, SCAN_CHUNK>>>();
    scan_phase2<<<1, 32>>>();
    scan_phase3<<<(NN + 255) / 256, 256>>>();
    scatter_csr<<<(EP + 255) / 256, 256>>>(eidx);

    // Precompute combined attention matrices, then fused projection + logits
    precompute_comb<<<5, 256>>>(gat_W1, att_s1, att_d1, gat_W2, att_s2, att_d2);
    fused_proj<<<dim3((NCAT + BN - 1) / BN, (NN + BM - 1) / BM), 256>>>(x, gat_W1, gcn_W1);

    // GAT layer 1
    gat1_agg_csr<<<AGG_BLK, WPB * 32>>>(gat_b1);

    // GAT layer 2 (projection + logits fused)
    gemm_l2<<<dim3(1, (NN + BM - 1) / BM), 256>>>(gat_W2);
    gat2_agg_csr<<<AGG_BLK, WPB * 32>>>();

    // GCN branch
    gcn1_agg_csr<<<AGG_BLK, WPB * 32>>>(gcn_b1);
    sgemm_rb<<<dim3((CC + BN - 1) / BN, (NN + BM - 1) / BM), 256>>>(PTR_GO1, gcn_W2, PTR_HG2, NN, CC, HID);
    gcn2_agg_csr<<<AGG_BLK, WPB * 32>>>();

    // Final linear head
    final_head<<<(NN * CC + 255) / 256, 256>>>(gat_b2, gcn_b2, lin_W, lin_b, wc, wt, out);
}

// round 9
// speedup vs baseline: 1.8264x; 1.2280x over previous
#include <cuda_runtime.h>
#include <cuda_bf16.h>
#include <math.h>

// Problem constants (match reference)
#define NN     50000
#define EE     800000
#define EP     850000     // edges + self loops
#define F_IN   128
#define HID    32
#define HEADS  4
#define HH     128        // HEADS*HID
#define CC     40
#define NEG_SLOPE 0.2f

#define SCAN_CHUNK 1024
#define SCAN_BLOCKS ((NN + SCAN_CHUNK - 1) / SCAN_CHUNK)   // 49

// ---------------- scratch (device globals; no allocation allowed) ----------------
__device__ int   g_flag32;
__device__ int   g_deg[NN];
__device__ int   g_off[NN + 1];
__device__ int   g_cursor[NN];
__device__ int   g_bsum[SCAN_BLOCKS];
__device__ int   g_csr_src[EP];      // src node per CSR slot (grouped by dst)

__device__ float g_comb1[F_IN * 8];  // attention fold for layer 1
__device__ float g_comb2[F_IN * 2];  // attention fold for layer 2
__device__ float g_W2fold[HH * CC];  // gat_W2 @ (wt * lin_W[40:80])
__device__ float g_Wgfold[HID * CC]; // gcn_W2 @ (wc * lin_W[0:40])
__device__ float g_cvec[CC];         // lin_b + biases through head

__device__ float g_h1[NN * HH];      // x @ W1            [N,128]
__device__ float g_as1[NN * HEADS];
__device__ float g_ad1[NN * HEADS];
__device__ float g_out1[NN * HH];    // GAT1 out (elu'd)  [N,128]
__device__ float g_h2[NN * CC];      // out1 @ W2fold     [N,40]
__device__ float g_as2[NN];
__device__ float g_ad2[NN];
__device__ float g_hg1[NN * HID];    // x @ gcnW1         [N,32]
__device__ float g_norm[NN];         // rsqrt(deg)
__device__ float g_go1[NN * HID];    // GCN1 out (relu'd) [N,32]
__device__ float g_hg2[NN * CC];     // go1 @ Wgfold      [N,40]
__device__ float g_go2[NN * CC];     // GCN2 agg + cvec   [N,40]

// ---------------- init ----------------
__global__ void zero_init() {
    int i = blockIdx.x * blockDim.x + threadIdx.x;
    if (i == 0) g_flag32 = 0;
    if (i < NN) g_deg[i] = 0;
}

// ---------------- dtype detect: int64 => every odd 32-bit word is 0 ----------------
__global__ void detect_idx(const unsigned int* __restrict__ raw) {
    int i = blockIdx.x * blockDim.x + threadIdx.x;   // 65536 samples
    unsigned v = raw[2 * i + 1];
    if (v != 0u) g_flag32 = 1;
}

__device__ __forceinline__ int load_node(const void* eidx, long long idx) {
    int v = g_flag32 ? ((const int*)eidx)[idx]
                     : (int)((const long long*)eidx)[idx];
    return min(max(v, 0), NN - 1);
}

// ---------------- pass 1: count degrees (incl. self loops) ----------------
__global__ void count_deg(const void* __restrict__ eidx) {
    int e = blockIdx.x * blockDim.x + threadIdx.x;
    if (e >= EP) return;
    int d = (e < EE) ? load_node(eidx, (long long)EE + e) : (e - EE);
    atomicAdd(&g_deg[d], 1);
}

// ---------------- 3-phase scan ----------------
__global__ void scan_phase1() {
    __shared__ int warp_sums[32];
    int b = blockIdx.x;
    int i = b * SCAN_CHUNK + threadIdx.x;
    int lane = threadIdx.x & 31, wid = threadIdx.x >> 5;
    int v = (i < NN) ? g_deg[i] : 0;
    int x = v;
#pragma unroll
    for (int s = 1; s < 32; s <<= 1) {
        int t = __shfl_up_sync(0xffffffff, x, s);
        if (lane >= s) x += t;
    }
    if (lane == 31) warp_sums[wid] = x;
    __syncthreads();
    if (wid == 0) {
        int ws = warp_sums[lane];
#pragma unroll
        for (int s = 1; s < 32; s <<= 1) {
            int t = __shfl_up_sync(0xffffffff, ws, s);
            if (lane >= s) ws += t;
        }
        warp_sums[lane] = ws;
    }
    __syncthreads();
    int prefix = (wid > 0) ? warp_sums[wid - 1] : 0;
    int excl = prefix + x - v;
    if (i < NN) g_off[i] = excl;
    if (threadIdx.x == SCAN_CHUNK - 1) g_bsum[b] = prefix + x;
}

__global__ void scan_phase2() {
    __shared__ int sh[64];
    int lane = threadIdx.x;
    int v0 = (lane < SCAN_BLOCKS) ? g_bsum[lane] : 0;
    int v1 = (lane + 32 < SCAN_BLOCKS) ? g_bsum[lane + 32] : 0;
    int x = v0;
#pragma unroll
    for (int s = 1; s < 32; s <<= 1) {
        int t = __shfl_up_sync(0xffffffff, x, s);
        if (lane >= s) x += t;
    }
    int tot0 = __shfl_sync(0xffffffff, x, 31);
    int y = v1;
#pragma unroll
    for (int s = 1; s < 32; s <<= 1) {
        int t = __shfl_up_sync(0xffffffff, y, s);
        if (lane >= s) y += t;
    }
    sh[lane] = x - v0;
    sh[lane + 32] = tot0 + y - v1;
    __syncwarp();
    if (lane < SCAN_BLOCKS) g_bsum[lane] = sh[lane];
    if (lane + 32 < SCAN_BLOCKS) g_bsum[lane + 32] = sh[lane + 32];
}

__global__ void scan_phase3() {
    int i = blockIdx.x * blockDim.x + threadIdx.x;
    if (i == 0) g_off[NN] = EP;
    if (i >= NN) return;
    int o = g_off[i] + g_bsum[i / SCAN_CHUNK];
    g_off[i] = o;
    g_cursor[i] = o;
    g_norm[i] = rsqrtf((float)g_deg[i]);
}

// ---------------- pass 2: scatter into CSR ----------------
__global__ void scatter_csr(const void* __restrict__ eidx) {
    int e = blockIdx.x * blockDim.x + threadIdx.x;
    if (e >= EP) return;
    int s, d;
    if (e < EE) {
        s = load_node(eidx, e);
        d = load_node(eidx, (long long)EE + e);
    } else {
        s = d = e - EE;
    }
    int pos = atomicAdd(&g_cursor[d], 1);
    g_csr_src[pos] = s;
}

// ---------------- precompute combined attention + folded head matrices ----------
__global__ void precompute_comb(const float* __restrict__ gat_W1,
                                const float* __restrict__ att_s1,
                                const float* __restrict__ att_d1,
                                const float* __restrict__ gat_W2,
                                const float* __restrict__ att_s2,
                                const float* __restrict__ att_d2,
                                const float* __restrict__ gcn_W2,
                                const float* __restrict__ gat_b2,
                                const float* __restrict__ gcn_b2,
                                const float* __restrict__ lin_W,
                                const float* __restrict__ lin_b,
                                const float* __restrict__ wc_p,
                                const float* __restrict__ wt_p) {
    int t = blockIdx.x * blockDim.x + threadIdx.x;
    float wc = *wc_p, wt = *wt_p;
    if (t < 1024) {
        // comb1: [128 x 8]
        int f = t >> 3, j = t & 7, h = j & 3;
        const float* av = (j < 4) ? &att_s1[h * HID] : &att_d1[h * HID];
        const float* wr = &gat_W1[f * HH + h * HID];
        float s = 0.f;
#pragma unroll
        for (int d = 0; d < HID; d++) s += wr[d] * av[d];
        g_comb1[f * 8 + j] = s;
    } else if (t < 1024 + 256) {
        // comb2: [128 x 2]
        int u = t - 1024, f = u >> 1;
        const float* av = (u & 1) ? att_d2 : att_s2;
        const float* wr = &gat_W2[f * CC];
        float s = 0.f;
#pragma unroll
        for (int c = 0; c < CC; c++) s += wr[c] * av[c];
        g_comb2[f * 2 + (u & 1)] = s;
    } else if (t < 1024 + 256 + HH * CC) {
        // W2fold[f,c] = sum_j gat_W2[f,j] * wt * lin_W[(CC+j)*CC + c]
        int u = t - 1024 - 256;
        int f = u / CC, c = u % CC;
        float s = 0.f;
#pragma unroll
        for (int j = 0; j < CC; j++) s += gat_W2[f * CC + j] * lin_W[(CC + j) * CC + c];
        g_W2fold[u] = s * wt;
    } else if (t < 1024 + 256 + HH * CC + HID * CC) {
        // Wgfold[f,c] = sum_j gcn_W2[f,j] * wc * lin_W[j*CC + c]
        int u = t - 1024 - 256 - HH * CC;
        int f = u / CC, c = u % CC;
        float s = 0.f;
#pragma unroll
        for (int j = 0; j < CC; j++) s += gcn_W2[f * CC + j] * lin_W[j * CC + c];
        g_Wgfold[u] = s * wc;
    } else if (t < 1024 + 256 + HH * CC + HID * CC + CC) {
        // cvec[c] = lin_b[c] + wc*gcn_b2@W_top + wt*gat_b2@W_bot
        int c = t - 1024 - 256 - HH * CC - HID * CC;
        float s = lin_b[c];
#pragma unroll
        for (int j = 0; j < CC; j++) {
            s += wc * gcn_b2[j] * lin_W[j * CC + c];
            s += wt * gat_b2[j] * lin_W[(CC + j) * CC + c];
        }
        g_cvec[c] = s;
    }
}

// ---------------- fused first projection + attention logits ----------------
#define BM 64
#define BN 64
#define BK 16
#define NCAT (HH + HID + 8)   // 168
__global__ void fused_proj(const float* __restrict__ x,
                           const float* __restrict__ W1,
                           const float* __restrict__ Wg) {
    __shared__ float As[BK][BM + 1];
    __shared__ float Bs[BK][BN];
    int tid = threadIdx.x;
    int tx = tid % 16, ty = tid / 16;
    int row0 = blockIdx.y * BM, col0 = blockIdx.x * BN;
    float acc[4][4] = {};
    for (int k0 = 0; k0 < F_IN; k0 += BK) {
        for (int i = tid; i < BM * BK; i += 256) {
            int r = i / BK, c = i % BK;
            int gr = row0 + r;
            As[c][r] = (gr < NN) ? x[gr * F_IN + k0 + c] : 0.f;
        }
        for (int i = tid; i < BK * BN; i += 256) {
            int r = i / BN, c = i % BN;
            int gc = col0 + c;
            float v;
            if (gc < HH) v = W1[(k0 + r) * HH + gc];
            else if (gc < HH + HID) v = Wg[(k0 + r) * HID + (gc - HH)];
            else if (gc < NCAT) v = g_comb1[(k0 + r) * 8 + (gc - HH - HID)];
            else v = 0.f;
            Bs[r][c] = v;
        }
        __syncthreads();
#pragma unroll
        for (int k = 0; k < BK; k++) {
            float a[4], b[4];
#pragma unroll
            for (int i = 0; i < 4; i++) a[i] = As[k][ty * 4 + i];
#pragma unroll
            for (int j = 0; j < 4; j++) b[j] = Bs[k][tx * 4 + j];
#pragma unroll
            for (int i = 0; i < 4; i++)
#pragma unroll
                for (int j = 0; j < 4; j++) acc[i][j] += a[i] * b[j];
        }
        __syncthreads();
    }
#pragma unroll
    for (int i = 0; i < 4; i++) {
        int gr = row0 + ty * 4 + i;
        if (gr >= NN) continue;
#pragma unroll
        for (int j = 0; j < 4; j++) {
            int gc = col0 + tx * 4 + j;
            if (gc < HH) g_h1[gr * HH + gc] = acc[i][j];
            else if (gc < HH + HID) g_hg1[gr * HID + (gc - HH)] = acc[i][j];
            else if (gc < HH + HID + 4) g_as1[gr * 4 + (gc - HH - HID)] = acc[i][j];
            else if (gc < NCAT) g_ad1[gr * 4 + (gc - HH - HID - 4)] = acc[i][j];
        }
    }
}

// ---------------- layer-2 GAT projection + logits: out1 @ [W2fold | comb2] -----
// cols 0..39 -> g_h2 (head-folded), col 40 -> g_as2, col 41 -> g_ad2.
__global__ void gemm_l2() {
    const float* A = g_out1;
    __shared__ float As[BK][BM + 1];
    __shared__ float Bs[BK][BN];
    int tid = threadIdx.x;
    int tx = tid % 16, ty = tid / 16;
    int row0 = blockIdx.y * BM;
    float acc[4][4] = {};
    for (int k0 = 0; k0 < HH; k0 += BK) {
        for (int i = tid; i < BM * BK; i += 256) {
            int r = i / BK, c = i % BK;
            int gr = row0 + r;
            As[c][r] = (gr < NN) ? A[gr * HH + k0 + c] : 0.f;
        }
        for (int i = tid; i < BK * BN; i += 256) {
            int r = i / BN, c = i % BN;
            float v;
            if (c < CC) v = g_W2fold[(k0 + r) * CC + c];
            else if (c < CC + 2) v = g_comb2[(k0 + r) * 2 + (c - CC)];
            else v = 0.f;
            Bs[r][c] = v;
        }
        __syncthreads();
#pragma unroll
        for (int k = 0; k < BK; k++) {
            float a[4], b[4];
#pragma unroll
            for (int i = 0; i < 4; i++) a[i] = As[k][ty * 4 + i];
#pragma unroll
            for (int j = 0; j < 4; j++) b[j] = Bs[k][tx * 4 + j];
#pragma unroll
            for (int i = 0; i < 4; i++)
#pragma unroll
                for (int j = 0; j < 4; j++) acc[i][j] += a[i] * b[j];
        }
        __syncthreads();
    }
#pragma unroll
    for (int i = 0; i < 4; i++) {
        int gr = row0 + ty * 4 + i;
        if (gr >= NN) continue;
#pragma unroll
        for (int j = 0; j < 4; j++) {
            int gc = tx * 4 + j;
            if (gc < CC) g_h2[gr * CC + gc] = acc[i][j];
            else if (gc == CC) g_as2[gr] = acc[i][j];
            else if (gc == CC + 1) g_ad2[gr] = acc[i][j];
        }
    }
}

// ---------------- gcn layer-2 projection: go1 @ Wgfold -> hg2 ----------------
__global__ void gemm_gcn2() {
    const float* A = g_go1;
    __shared__ float As[BK][BM + 1];
    __shared__ float Bs[BK][BN];
    int tid = threadIdx.x;
    int tx = tid % 16, ty = tid / 16;
    int row0 = blockIdx.y * BM;
    float acc[4][4] = {};
    for (int k0 = 0; k0 < HID; k0 += BK) {
        for (int i = tid; i < BM * BK; i += 256) {
            int r = i / BK, c = i % BK;
            int gr = row0 + r;
            As[c][r] = (gr < NN) ? A[gr * HID + k0 + c] : 0.f;
        }
        for (int i = tid; i < BK * BN; i += 256) {
            int r = i / BN, c = i % BN;
            Bs[r][c] = (c < CC) ? g_Wgfold[(k0 + r) * CC + c] : 0.f;
        }
        __syncthreads();
#pragma unroll
        for (int k = 0; k < BK; k++) {
            float a[4], b[4];
#pragma unroll
            for (int i = 0; i < 4; i++) a[i] = As[k][ty * 4 + i];
#pragma unroll
            for (int j = 0; j < 4; j++) b[j] = Bs[k][tx * 4 + j];
#pragma unroll
            for (int i = 0; i < 4; i++)
#pragma unroll
                for (int j = 0; j < 4; j++) acc[i][j] += a[i] * b[j];
        }
        __syncthreads();
    }
#pragma unroll
    for (int i = 0; i < 4; i++) {
        int gr = row0 + ty * 4 + i;
        if (gr >= NN) continue;
#pragma unroll
        for (int j = 0; j < 4; j++) {
            int gc = tx * 4 + j;
            if (gc < CC) g_hg2[gr * CC + gc] = acc[i][j];
        }
    }
}

// ---------------- GAT1 fused softmax + aggregation + bias + ELU (4x unroll) ----
__global__ void gat1_agg_csr(const float* __restrict__ bias) {
    int warp = (blockIdx.x * blockDim.x + threadIdx.x) >> 5;
    if (warp >= NN) return;
    int lane = threadIdx.x & 31;
    int n = warp;
    int beg = g_off[n], end = g_off[n + 1];
    int h = lane >> 3;
    float ad = g_ad1[n * 4 + h];
    float4 acc = {0.f, 0.f, 0.f, 0.f};
    float sumw = 0.f;
    int p = beg;
    for (; p + 3 < end; p += 4) {
        int s0 = g_csr_src[p];
        int s1 = g_csr_src[p + 1];
        int s2 = g_csr_src[p + 2];
        int s3 = g_csr_src[p + 3];
        float l0 = g_as1[s0 * 4 + h] + ad;
        float l1 = g_as1[s1 * 4 + h] + ad;
        float l2 = g_as1[s2 * 4 + h] + ad;
        float l3 = g_as1[s3 * 4 + h] + ad;
        float4 h0 = *(const float4*)&g_h1[s0 * HH + lane * 4];
        float4 h1 = *(const float4*)&g_h1[s1 * HH + lane * 4];
        float4 h2 = *(const float4*)&g_h1[s2 * HH + lane * 4];
        float4 h3 = *(const float4*)&g_h1[s3 * HH + lane * 4];
        l0 = (l0 > 0.f) ? l0 : NEG_SLOPE * l0;
        l1 = (l1 > 0.f) ? l1 : NEG_SLOPE * l1;
        l2 = (l2 > 0.f) ? l2 : NEG_SLOPE * l2;
        l3 = (l3 > 0.f) ? l3 : NEG_SLOPE * l3;
        float w0 = __expf(l0), w1 = __expf(l1), w2 = __expf(l2), w3 = __expf(l3);
        sumw += (w0 + w1) + (w2 + w3);
        acc.x += w0 * h0.x + w1 * h1.x + w2 * h2.x + w3 * h3.x;
        acc.y += w0 * h0.y + w1 * h1.y + w2 * h2.y + w3 * h3.y;
        acc.z += w0 * h0.z + w1 * h1.z + w2 * h2.z + w3 * h3.z;
        acc.w += w0 * h0.w + w1 * h1.w + w2 * h2.w + w3 * h3.w;
    }
    for (; p < end; p++) {
        int s0 = g_csr_src[p];
        float l0 = g_as1[s0 * 4 + h] + ad;
        float4 h0 = *(const float4*)&g_h1[s0 * HH + lane * 4];
        l0 = (l0 > 0.f) ? l0 : NEG_SLOPE * l0;
        float w0 = __expf(l0);
        sumw += w0;
        acc.x += w0 * h0.x; acc.y += w0 * h0.y; acc.z += w0 * h0.z; acc.w += w0 * h0.w;
    }
    float inv = 1.f / sumw;
    float4 bv = *(const float4*)&bias[lane * 4];
    float4 o;
    float vx = acc.x * inv + bv.x; o.x = (vx > 0.f) ? vx : expm1f(vx);
    float vy = acc.y * inv + bv.y; o.y = (vy > 0.f) ? vy : expm1f(vy);
    float vz = acc.z * inv + bv.z; o.z = (vz > 0.f) ? vz : expm1f(vz);
    float vw = acc.w * inv + bv.w; o.w = (vw > 0.f) ? vw : expm1f(vw);
    *(float4*)&g_out1[n * HH + lane * 4] = o;
}

// ---------------- GCN1 fused aggregation + bias + ReLU (4x unroll) ----------
__global__ void gcn1_agg_csr(const float* __restrict__ bias) {
    int warp = (blockIdx.x * blockDim.x + threadIdx.x) >> 5;
    if (warp >= NN) return;
    int lane = threadIdx.x & 31;
    int n = warp;
    int beg = g_off[n], end = g_off[n + 1];
    float nd = g_norm[n];
    float acc = 0.f;
    int p = beg;
    for (; p + 3 < end; p += 4) {
        int s0 = g_csr_src[p];
        int s1 = g_csr_src[p + 1];
        int s2 = g_csr_src[p + 2];
        int s3 = g_csr_src[p + 3];
        float c0 = g_norm[s0], c1 = g_norm[s1], c2 = g_norm[s2], c3 = g_norm[s3];
        float v0 = g_hg1[s0 * HID + lane];
        float v1 = g_hg1[s1 * HID + lane];
        float v2 = g_hg1[s2 * HID + lane];
        float v3 = g_hg1[s3 * HID + lane];
        acc += (c0 * v0 + c1 * v1) + (c2 * v2 + c3 * v3);
    }
    for (; p < end; p++) {
        int s0 = g_csr_src[p];
        acc += g_norm[s0] * g_hg1[s0 * HID + lane];
    }
    float v = acc * nd + bias[lane];
    g_go1[n * HID + lane] = (v > 0.f) ? v : 0.f;
}

// ---------------- GCN2 aggregation -> go2 = A_gcn(hg2) + cvec (4x unroll) -----
__global__ void gcn2_agg_csr() {
    int warp = (blockIdx.x * blockDim.x + threadIdx.x) >> 5;
    if (warp >= NN) return;
    int lane = threadIdx.x & 31;
    int n = warp;
    int beg = g_off[n], end = g_off[n + 1];
    float nd = g_norm[n];
    float acc1 = 0.f, acc2 = 0.f;
    int p = beg;
    for (; p + 3 < end; p += 4) {
        int s0 = g_csr_src[p];
        int s1 = g_csr_src[p + 1];
        int s2 = g_csr_src[p + 2];
        int s3 = g_csr_src[p + 3];
        float c0 = g_norm[s0], c1 = g_norm[s1], c2 = g_norm[s2], c3 = g_norm[s3];
        float a0 = g_hg2[s0 * CC + lane];
        float a1 = g_hg2[s1 * CC + lane];
        float a2 = g_hg2[s2 * CC + lane];
        float a3 = g_hg2[s3 * CC + lane];
        acc1 += (c0 * a0 + c1 * a1) + (c2 * a2 + c3 * a3);
        if (lane < CC - 32) {
            float b0 = g_hg2[s0 * CC + 32 + lane];
            float b1 = g_hg2[s1 * CC + 32 + lane];
            float b2 = g_hg2[s2 * CC + 32 + lane];
            float b3 = g_hg2[s3 * CC + 32 + lane];
            acc2 += (c0 * b0 + c1 * b1) + (c2 * b2 + c3 * b3);
        }
    }
    for (; p < end; p++) {
        int s0 = g_csr_src[p];
        float c0 = g_norm[s0];
        acc1 += c0 * g_hg2[s0 * CC + lane];
        if (lane < CC - 32) acc2 += c0 * g_hg2[s0 * CC + 32 + lane];
    }
    g_go2[n * CC + lane] = acc1 * nd + g_cvec[lane];
    if (lane < CC - 32) g_go2[n * CC + 32 + lane] = acc2 * nd + g_cvec[32 + lane];
}

// ---------------- GAT2 aggregation + add go2 -> final out (4x unroll) ---------
__global__ void gat2_agg_out(float* __restrict__ out) {
    int warp = (blockIdx.x * blockDim.x + threadIdx.x) >> 5;
    if (warp >= NN) return;
    int lane = threadIdx.x & 31;
    int n = warp;
    int beg = g_off[n], end = g_off[n + 1];
    float ad = g_ad2[n];
    float acc1 = 0.f, acc2 = 0.f, sumw = 0.f;
    int p = beg;
    for (; p + 3 < end; p += 4) {
        int s0 = g_csr_src[p];
        int s1 = g_csr_src[p + 1];
        int s2 = g_csr_src[p + 2];
        int s3 = g_csr_src[p + 3];
        float l0 = g_as2[s0] + ad;
        float l1 = g_as2[s1] + ad;
        float l2 = g_as2[s2] + ad;
        float l3 = g_as2[s3] + ad;
        float a0 = g_h2[s0 * CC + lane];
        float a1 = g_h2[s1 * CC + lane];
        float a2 = g_h2[s2 * CC + lane];
        float a3 = g_h2[s3 * CC + lane];
        l0 = (l0 > 0.f) ? l0 : NEG_SLOPE * l0;
        l1 = (l1 > 0.f) ? l1 : NEG_SLOPE * l1;
        l2 = (l2 > 0.f) ? l2 : NEG_SLOPE * l2;
        l3 = (l3 > 0.f) ? l3 : NEG_SLOPE * l3;
        float w0 = __expf(l0), w1 = __expf(l1), w2 = __expf(l2), w3 = __expf(l3);
        sumw += (w0 + w1) + (w2 + w3);
        acc1 += (w0 * a0 + w1 * a1) + (w2 * a2 + w3 * a3);
        if (lane < CC - 32) {
            float b0 = g_h2[s0 * CC + 32 + lane];
            float b1 = g_h2[s1 * CC + 32 + lane];
            float b2 = g_h2[s2 * CC + 32 + lane];
            float b3 = g_h2[s3 * CC + 32 + lane];
            acc2 += (w0 * b0 + w1 * b1) + (w2 * b2 + w3 * b3);
        }
    }
    for (; p < end; p++) {
        int s0 = g_csr_src[p];
        float l0 = g_as2[s0] + ad;
        float a0 = g_h2[s0 * CC + lane];
        l0 = (l0 > 0.f) ? l0 : NEG_SLOPE * l0;
        float w0 = __expf(l0);
        sumw += w0;
        acc1 += w0 * a0;
        if (lane < CC - 32) acc2 += w0 * g_h2[s0 * CC + 32 + lane];
    }
    float inv = 1.f / sumw;
    out[n * CC + lane] = acc1 * inv + g_go2[n * CC + lane];
    if (lane < CC - 32) out[n * CC + 32 + lane] = acc2 * inv + g_go2[n * CC + 32 + lane];
}

// ---------------- launch ----------------
extern "C" void kernel_launch(void* const* d_in, const int* in_sizes, int n_in,
                              void* d_out, int out_size) {
    const float* x      = (const float*)d_in[0];
    const void*  eidx   = d_in[1];
    const float* gat_W1 = (const float*)d_in[2];
    const float* att_s1 = (const float*)d_in[3];
    const float* att_d1 = (const float*)d_in[4];
    const float* gat_b1 = (const float*)d_in[5];
    const float* gat_W2 = (const float*)d_in[6];
    const float* att_s2 = (const float*)d_in[7];
    const float* att_d2 = (const float*)d_in[8];
    const float* gat_b2 = (const float*)d_in[9];
    const float* gcn_W1 = (const float*)d_in[10];
    const float* gcn_b1 = (const float*)d_in[11];
    const float* gcn_W2 = (const float*)d_in[12];
    const float* gcn_b2 = (const float*)d_in[13];
    const float* lin_W  = (const float*)d_in[14];
    const float* lin_b  = (const float*)d_in[15];
    const float* wc     = (const float*)d_in[16];
    const float* wt     = (const float*)d_in[17];
    float*       out    = (float*)d_out;

    const int WPB = 8;
    const int AGG_BLK = (NN + WPB - 1) / WPB;
    const int PRE_TOT = 1024 + 256 + HH * CC + HID * CC + CC;

    // CSR build
    zero_init<<<(NN + 255) / 256, 256>>>();
    detect_idx<<<256, 256>>>((const unsigned int*)eidx);
    count_deg<<<(EP + 255) / 256, 256>>>(eidx);
    scan_phase1<<<SCAN_BLOCKS, SCAN_CHUNK>>>();
    scan_phase2<<<1, 32>>>();
    scan_phase3<<<(NN + 255) / 256, 256>>>();
    scatter_csr<<<(EP + 255) / 256, 256>>>(eidx);

    // Precompute folds, then fused projection + logits
    precompute_comb<<<(PRE_TOT + 255) / 256, 256>>>(gat_W1, att_s1, att_d1,
                                                    gat_W2, att_s2, att_d2,
                                                    gcn_W2, gat_b2, gcn_b2,
                                                    lin_W, lin_b, wc, wt);
    fused_proj<<<dim3((NCAT + BN - 1) / BN, (NN + BM - 1) / BM), 256>>>(x, gat_W1, gcn_W1);

    // GAT layer 1
    gat1_agg_csr<<<AGG_BLK, WPB * 32>>>(gat_b1);

    // GCN branch (through folded head weights)
    gcn1_agg_csr<<<AGG_BLK, WPB * 32>>>(gcn_b1);
    gemm_gcn2<<<dim3(1, (NN + BM - 1) / BM), 256>>>();
    gcn2_agg_csr<<<AGG_BLK, WPB * 32>>>();

    // GAT layer 2 (projection through folded head weights + logits)
    gemm_l2<<<dim3(1, (NN + BM - 1) / BM), 256>>>();
    gat2_agg_out<<<AGG_BLK, WPB * 32>>>(out);
}

// round 12
// speedup vs baseline: 1.8638x; 1.0205x over previous
#include <cuda_runtime.h>
#include <cuda_bf16.h>
#include <math.h>

// Problem constants (match reference)
#define NN     50000
#define EE     800000
#define EP     850000     // edges + self loops
#define F_IN   128
#define HID    32
#define HEADS  4
#define HH     128        // HEADS*HID
#define CC     40
#define NEG_SLOPE 0.2f

#define SCAN_CHUNK 1024
#define SCAN_BLOCKS ((NN + SCAN_CHUNK - 1) / SCAN_CHUNK)   // 49

#define NCAT (HH + HID + 8)   // 168: [W1 | Wg | comb1]

// ---------------- scratch (device globals; no allocation allowed) ----------------
__device__ int   g_flag32;
__device__ int   g_deg[NN];
__device__ int   g_off[NN + 1];
__device__ int   g_cursor[NN];
__device__ int   g_bsum[SCAN_BLOCKS];
__device__ int   g_csr_src[EP];      // src node per CSR slot (grouped by dst)

__device__ float g_Bcat[F_IN * NCAT];  // packed B for fused_proj
__device__ float g_comb2[F_IN * 2];    // attention fold for layer 2
__device__ float g_W2fold[HH * CC];    // gat_W2 @ (wt * lin_W[40:80])
__device__ float g_Wgfold[HID * CC];   // gcn_W2 @ (wc * lin_W[0:40])
__device__ float g_cvec[CC];           // lin_b + biases through head

__device__ float g_h1[NN * HH];      // x @ W1            [N,128]
__device__ float g_as1[NN * HEADS];
__device__ float g_ad1[NN * HEADS];
__device__ float g_out1[NN * HH];    // GAT1 out (elu'd)  [N,128]
__device__ float g_h2[NN * CC];      // out1 @ W2fold     [N,40]
__device__ float g_as2[NN];
__device__ float g_ad2[NN];
__device__ float g_hg1[NN * HID];    // x @ gcnW1         [N,32]
__device__ float g_norm[NN];         // rsqrt(deg)
__device__ float g_go1[NN * HID];    // GCN1 out (relu'd) [N,32]
__device__ float g_hg2[NN * CC];     // go1 @ Wgfold      [N,40]
__device__ float g_go2[NN * CC];     // GCN2 agg + cvec   [N,40]

// ---------------- init ----------------
__global__ void zero_init() {
    int i = blockIdx.x * blockDim.x + threadIdx.x;
    if (i == 0) g_flag32 = 0;
    if (i < NN) g_deg[i] = 0;
}

// ---------------- dtype detect: int64 => every odd 32-bit word is 0 ----------------
__global__ void detect_idx(const unsigned int* __restrict__ raw) {
    int i = blockIdx.x * blockDim.x + threadIdx.x;   // 65536 samples
    unsigned v = raw[2 * i + 1];
    if (v != 0u) g_flag32 = 1;
}

__device__ __forceinline__ int load_node(const void* eidx, long long idx) {
    int v = g_flag32 ? ((const int*)eidx)[idx]
                     : (int)((const long long*)eidx)[idx];
    return min(max(v, 0), NN - 1);
}

// ---------------- pass 1: count degrees (incl. self loops) ----------------
__global__ void count_deg(const void* __restrict__ eidx) {
    int e = blockIdx.x * blockDim.x + threadIdx.x;
    if (e >= EP) return;
    int d = (e < EE) ? load_node(eidx, (long long)EE + e) : (e - EE);
    atomicAdd(&g_deg[d], 1);
}

// ---------------- 3-phase scan ----------------
__global__ void scan_phase1() {
    __shared__ int warp_sums[32];
    int b = blockIdx.x;
    int i = b * SCAN_CHUNK + threadIdx.x;
    int lane = threadIdx.x & 31, wid = threadIdx.x >> 5;
    int v = (i < NN) ? g_deg[i] : 0;
    int x = v;
#pragma unroll
    for (int s = 1; s < 32; s <<= 1) {
        int t = __shfl_up_sync(0xffffffff, x, s);
        if (lane >= s) x += t;
    }
    if (lane == 31) warp_sums[wid] = x;
    __syncthreads();
    if (wid == 0) {
        int ws = warp_sums[lane];
#pragma unroll
        for (int s = 1; s < 32; s <<= 1) {
            int t = __shfl_up_sync(0xffffffff, ws, s);
            if (lane >= s) ws += t;
        }
        warp_sums[lane] = ws;
    }
    __syncthreads();
    int prefix = (wid > 0) ? warp_sums[wid - 1] : 0;
    int excl = prefix + x - v;
    if (i < NN) g_off[i] = excl;
    if (threadIdx.x == SCAN_CHUNK - 1) g_bsum[b] = prefix + x;
}

__global__ void scan_phase2() {
    __shared__ int sh[64];
    int lane = threadIdx.x;
    int v0 = (lane < SCAN_BLOCKS) ? g_bsum[lane] : 0;
    int v1 = (lane + 32 < SCAN_BLOCKS) ? g_bsum[lane + 32] : 0;
    int x = v0;
#pragma unroll
    for (int s = 1; s < 32; s <<= 1) {
        int t = __shfl_up_sync(0xffffffff, x, s);
        if (lane >= s) x += t;
    }
    int tot0 = __shfl_sync(0xffffffff, x, 31);
    int y = v1;
#pragma unroll
    for (int s = 1; s < 32; s <<= 1) {
        int t = __shfl_up_sync(0xffffffff, y, s);
        if (lane >= s) y += t;
    }
    sh[lane] = x - v0;
    sh[lane + 32] = tot0 + y - v1;
    __syncwarp();
    if (lane < SCAN_BLOCKS) g_bsum[lane] = sh[lane];
    if (lane + 32 < SCAN_BLOCKS) g_bsum[lane + 32] = sh[lane + 32];
}

__global__ void scan_phase3() {
    int i = blockIdx.x * blockDim.x + threadIdx.x;
    if (i == 0) g_off[NN] = EP;
    if (i >= NN) return;
    int o = g_off[i] + g_bsum[i / SCAN_CHUNK];
    g_off[i] = o;
    g_cursor[i] = o;
    g_norm[i] = rsqrtf((float)g_deg[i]);
}

// ---------------- pass 2: scatter into CSR ----------------
__global__ void scatter_csr(const void* __restrict__ eidx) {
    int e = blockIdx.x * blockDim.x + threadIdx.x;
    if (e >= EP) return;
    int s, d;
    if (e < EE) {
        s = load_node(eidx, e);
        d = load_node(eidx, (long long)EE + e);
    } else {
        s = d = e - EE;
    }
    int pos = atomicAdd(&g_cursor[d], 1);
    g_csr_src[pos] = s;
}

// ---------------- precompute packed Bcat + attention folds + head folds ---------
__global__ void precompute_comb(const float* __restrict__ gat_W1,
                                const float* __restrict__ att_s1,
                                const float* __restrict__ att_d1,
                                const float* __restrict__ gat_W2,
                                const float* __restrict__ att_s2,
                                const float* __restrict__ att_d2,
                                const float* __restrict__ gcn_W1,
                                const float* __restrict__ gcn_W2,
                                const float* __restrict__ gat_b2,
                                const float* __restrict__ gcn_b2,
                                const float* __restrict__ lin_W,
                                const float* __restrict__ lin_b,
                                const float* __restrict__ wc_p,
                                const float* __restrict__ wt_p) {
    int t = blockIdx.x * blockDim.x + threadIdx.x;
    float wc = *wc_p, wt = *wt_p;
    const int N_BCAT = F_IN * NCAT;                    // 21504
    if (t < N_BCAT) {
        int f = t / NCAT, c = t % NCAT;
        float v;
        if (c < HH) v = gat_W1[f * HH + c];
        else if (c < HH + HID) v = gcn_W1[f * HID + (c - HH)];
        else {
            int j = c - HH - HID;                      // 0..7
            int h = j & 3;
            const float* av = (j < 4) ? &att_s1[h * HID] : &att_d1[h * HID];
            const float* wr = &gat_W1[f * HH + h * HID];
            float s = 0.f;
#pragma unroll
            for (int d = 0; d < HID; d++) s += wr[d] * av[d];
            v = s;
        }
        g_Bcat[t] = v;
    } else if (t < N_BCAT + 256) {
        int u = t - N_BCAT, f = u >> 1;
        const float* av = (u & 1) ? att_d2 : att_s2;
        const float* wr = &gat_W2[f * CC];
        float s = 0.f;
#pragma unroll
        for (int c = 0; c < CC; c++) s += wr[c] * av[c];
        g_comb2[f * 2 + (u & 1)] = s;
    } else if (t < N_BCAT + 256 + HH * CC) {
        int u = t - N_BCAT - 256;
        int f = u / CC, c = u % CC;
        float s = 0.f;
#pragma unroll
        for (int j = 0; j < CC; j++) s += gat_W2[f * CC + j] * lin_W[(CC + j) * CC + c];
        g_W2fold[u] = s * wt;
    } else if (t < N_BCAT + 256 + HH * CC + HID * CC) {
        int u = t - N_BCAT - 256 - HH * CC;
        int f = u / CC, c = u % CC;
        float s = 0.f;
#pragma unroll
        for (int j = 0; j < CC; j++) s += gcn_W2[f * CC + j] * lin_W[j * CC + c];
        g_Wgfold[u] = s * wc;
    } else if (t < N_BCAT + 256 + HH * CC + HID * CC + CC) {
        int c = t - N_BCAT - 256 - HH * CC - HID * CC;
        float s = lin_b[c];
#pragma unroll
        for (int j = 0; j < CC; j++) {
            s += wc * gcn_b2[j] * lin_W[j * CC + c];
            s += wt * gat_b2[j] * lin_W[(CC + j) * CC + c];
        }
        g_cvec[c] = s;
    }
}

// ---------------- fused first projection + attention logits (float4 loads) -----
#define BM 64
#define BN 64
#define BK 16
__global__ void fused_proj(const float* __restrict__ x) {
    __shared__ float As[BK][BM + 1];
    __shared__ float Bs[BK][BN];
    int tid = threadIdx.x;
    int tx = tid % 16, ty = tid / 16;
    int row0 = blockIdx.y * BM, col0 = blockIdx.x * BN;
    float acc[4][4] = {};
    for (int k0 = 0; k0 < F_IN; k0 += BK) {
        {
            int r = tid >> 2;                 // 0..63
            int c4 = (tid & 3) * 4;           // 0,4,8,12
            int gr = row0 + r;
            float4 v = (gr < NN) ? *(const float4*)&x[gr * F_IN + k0 + c4]
                                 : make_float4(0.f, 0.f, 0.f, 0.f);
            As[c4 + 0][r] = v.x;
            As[c4 + 1][r] = v.y;
            As[c4 + 2][r] = v.z;
            As[c4 + 3][r] = v.w;
        }
        {
            int r = tid >> 4;                 // 0..15
            int c4 = (tid & 15) * 4;          // 0..60
            int gc = col0 + c4;
            float4 v = (gc + 3 < NCAT) ? *(const float4*)&g_Bcat[(k0 + r) * NCAT + gc]
                                       : make_float4(0.f, 0.f, 0.f, 0.f);
            *(float4*)&Bs[r][c4] = v;
        }
        __syncthreads();
#pragma unroll
        for (int k = 0; k < BK; k++) {
            float a[4], b[4];
#pragma unroll
            for (int i = 0; i < 4; i++) a[i] = As[k][ty * 4 + i];
#pragma unroll
            for (int j = 0; j < 4; j++) b[j] = Bs[k][tx * 4 + j];
#pragma unroll
            for (int i = 0; i < 4; i++)
#pragma unroll
                for (int j = 0; j < 4; j++) acc[i][j] += a[i] * b[j];
        }
        __syncthreads();
    }
#pragma unroll
    for (int i = 0; i < 4; i++) {
        int gr = row0 + ty * 4 + i;
        if (gr >= NN) continue;
#pragma unroll
        for (int j = 0; j < 4; j++) {
            int gc = col0 + tx * 4 + j;
            if (gc < HH) g_h1[gr * HH + gc] = acc[i][j];
            else if (gc < HH + HID) g_hg1[gr * HID + (gc - HH)] = acc[i][j];
            else if (gc < HH + HID + 4) g_as1[gr * 4 + (gc - HH - HID)] = acc[i][j];
            else if (gc < NCAT) g_ad1[gr * 4 + (gc - HH - HID - 4)] = acc[i][j];
        }
    }
}

// ---------------- layer-2 GAT projection + logits: out1 @ [W2fold | comb2] -----
__global__ void gemm_l2() {
    const float* A = g_out1;
    __shared__ float As[BK][BM + 1];
    __shared__ float Bs[BK][BN];
    int tid = threadIdx.x;
    int tx = tid % 16, ty = tid / 16;
    int row0 = blockIdx.y * BM;
    float acc[4][4] = {};
    for (int k0 = 0; k0 < HH; k0 += BK) {
        {
            int r = tid >> 2;
            int c4 = (tid & 3) * 4;
            int gr = row0 + r;
            float4 v = (gr < NN) ? *(const float4*)&A[gr * HH + k0 + c4]
                                 : make_float4(0.f, 0.f, 0.f, 0.f);
            As[c4 + 0][r] = v.x;
            As[c4 + 1][r] = v.y;
            As[c4 + 2][r] = v.z;
            As[c4 + 3][r] = v.w;
        }
        for (int i = tid; i < BK * BN; i += 256) {
            int r = i / BN, c = i % BN;
            float v;
            if (c < CC) v = g_W2fold[(k0 + r) * CC + c];
            else if (c < CC + 2) v = g_comb2[(k0 + r) * 2 + (c - CC)];
            else v = 0.f;
            Bs[r][c] = v;
        }
        __syncthreads();
#pragma unroll
        for (int k = 0; k < BK; k++) {
            float a[4], b[4];
#pragma unroll
            for (int i = 0; i < 4; i++) a[i] = As[k][ty * 4 + i];
#pragma unroll
            for (int j = 0; j < 4; j++) b[j] = Bs[k][tx * 4 + j];
#pragma unroll
            for (int i = 0; i < 4; i++)
#pragma unroll
                for (int j = 0; j < 4; j++) acc[i][j] += a[i] * b[j];
        }
        __syncthreads();
    }
#pragma unroll
    for (int i = 0; i < 4; i++) {
        int gr = row0 + ty * 4 + i;
        if (gr >= NN) continue;
#pragma unroll
        for (int j = 0; j < 4; j++) {
            int gc = tx * 4 + j;
            if (gc < CC) g_h2[gr * CC + gc] = acc[i][j];
            else if (gc == CC) g_as2[gr] = acc[i][j];
            else if (gc == CC + 1) g_ad2[gr] = acc[i][j];
        }
    }
}

// ---------------- gcn layer-2 projection: go1 @ Wgfold -> hg2 ----------------
__global__ void gemm_gcn2() {
    const float* A = g_go1;
    __shared__ float As[BK][BM + 1];
    __shared__ float Bs[BK][BN];
    int tid = threadIdx.x;
    int tx = tid % 16, ty = tid / 16;
    int row0 = blockIdx.y * BM;
    float acc[4][4] = {};
    for (int k0 = 0; k0 < HID; k0 += BK) {
        {
            int r = tid >> 2;
            int c4 = (tid & 3) * 4;
            int gr = row0 + r;
            float4 v = (gr < NN) ? *(const float4*)&A[gr * HID + k0 + c4]
                                 : make_float4(0.f, 0.f, 0.f, 0.f);
            As[c4 + 0][r] = v.x;
            As[c4 + 1][r] = v.y;
            As[c4 + 2][r] = v.z;
            As[c4 + 3][r] = v.w;
        }
        for (int i = tid; i < BK * BN; i += 256) {
            int r = i / BN, c = i % BN;
            Bs[r][c] = (c < CC) ? g_Wgfold[(k0 + r) * CC + c] : 0.f;
        }
        __syncthreads();
#pragma unroll
        for (int k = 0; k < BK; k++) {
            float a[4], b[4];
#pragma unroll
            for (int i = 0; i < 4; i++) a[i] = As[k][ty * 4 + i];
#pragma unroll
            for (int j = 0; j < 4; j++) b[j] = Bs[k][tx * 4 + j];
#pragma unroll
            for (int i = 0; i < 4; i++)
#pragma unroll
                for (int j = 0; j < 4; j++) acc[i][j] += a[i] * b[j];
        }
        __syncthreads();
    }
#pragma unroll
    for (int i = 0; i < 4; i++) {
        int gr = row0 + ty * 4 + i;
        if (gr >= NN) continue;
#pragma unroll
        for (int j = 0; j < 4; j++) {
            int gc = tx * 4 + j;
            if (gc < CC) g_hg2[gr * CC + gc] = acc[i][j];
        }
    }
}

// ---------------- GAT1: 2 warps per node (edge-range split), smem combine ------
// Block: 256 threads = 8 warps = 4 nodes. 12500 blocks (exact).
// NOTE: sumw is PER-HEAD (h = lane>>3), so partials combine through a per-head
// slot s_sum[wid][h] (written by lanes 0/8/16/24), not a single scalar.
__global__ void gat1_agg_csr(const float* __restrict__ bias) {
    __shared__ float s_acc[8][HH];     // partial acc per warp
    __shared__ float s_sum[8][4];      // partial sumw per warp PER HEAD
    int wid = threadIdx.x >> 5;
    int lane = threadIdx.x & 31;
    int n = blockIdx.x * 4 + (wid >> 1);
    int half = wid & 1;
    int beg = g_off[n], end = g_off[n + 1];
    int mid = beg + ((end - beg) >> 1);
    int lo = half ? mid : beg;
    int hi = half ? end : mid;
    int h = lane >> 3;
    float ad = g_ad1[n * 4 + h];
    float4 acc = {0.f, 0.f, 0.f, 0.f};
    float sumw = 0.f;
    int p = lo;
    for (; p + 3 < hi; p += 4) {
        int s0 = g_csr_src[p];
        int s1 = g_csr_src[p + 1];
        int s2 = g_csr_src[p + 2];
        int s3 = g_csr_src[p + 3];
        float l0 = g_as1[s0 * 4 + h] + ad;
        float l1 = g_as1[s1 * 4 + h] + ad;
        float l2 = g_as1[s2 * 4 + h] + ad;
        float l3 = g_as1[s3 * 4 + h] + ad;
        float4 h0 = *(const float4*)&g_h1[s0 * HH + lane * 4];
        float4 h1 = *(const float4*)&g_h1[s1 * HH + lane * 4];
        float4 h2 = *(const float4*)&g_h1[s2 * HH + lane * 4];
        float4 h3 = *(const float4*)&g_h1[s3 * HH + lane * 4];
        l0 = (l0 > 0.f) ? l0 : NEG_SLOPE * l0;
        l1 = (l1 > 0.f) ? l1 : NEG_SLOPE * l1;
        l2 = (l2 > 0.f) ? l2 : NEG_SLOPE * l2;
        l3 = (l3 > 0.f) ? l3 : NEG_SLOPE * l3;
        float w0 = __expf(l0), w1 = __expf(l1), w2 = __expf(l2), w3 = __expf(l3);
        sumw += (w0 + w1) + (w2 + w3);
        acc.x += w0 * h0.x + w1 * h1.x + w2 * h2.x + w3 * h3.x;
        acc.y += w0 * h0.y + w1 * h1.y + w2 * h2.y + w3 * h3.y;
        acc.z += w0 * h0.z + w1 * h1.z + w2 * h2.z + w3 * h3.z;
        acc.w += w0 * h0.w + w1 * h1.w + w2 * h2.w + w3 * h3.w;
    }
    for (; p < hi; p++) {
        int s0 = g_csr_src[p];
        float l0 = g_as1[s0 * 4 + h] + ad;
        float4 h0 = *(const float4*)&g_h1[s0 * HH + lane * 4];
        l0 = (l0 > 0.f) ? l0 : NEG_SLOPE * l0;
        float w0 = __expf(l0);
        sumw += w0;
        acc.x += w0 * h0.x; acc.y += w0 * h0.y; acc.z += w0 * h0.z; acc.w += w0 * h0.w;
    }
    if (half) {                         // stash partner's partials
        *(float4*)&s_acc[wid][lane * 4] = acc;
        if ((lane & 7) == 0) s_sum[wid][h] = sumw;   // lanes 0,8,16,24 -> heads 0..3
    }
    __syncthreads();
    if (!half) {
        float4 pa = *(const float4*)&s_acc[wid + 1][lane * 4];
        acc.x += pa.x; acc.y += pa.y; acc.z += pa.z; acc.w += pa.w;
        sumw += s_sum[wid + 1][h];
        float inv = 1.f / sumw;
        float4 bv = *(const float4*)&bias[lane * 4];
        float4 o;
        float vx = acc.x * inv + bv.x; o.x = (vx > 0.f) ? vx : expm1f(vx);
        float vy = acc.y * inv + bv.y; o.y = (vy > 0.f) ? vy : expm1f(vy);
        float vz = acc.z * inv + bv.z; o.z = (vz > 0.f) ? vz : expm1f(vz);
        float vw = acc.w * inv + bv.w; o.w = (vw > 0.f) ? vw : expm1f(vw);
        *(float4*)&g_out1[n * HH + lane * 4] = o;
    }
}

// ---------------- GCN1 fused aggregation + bias + ReLU (4x unroll) ----------
__global__ void gcn1_agg_csr(const float* __restrict__ bias) {
    int warp = (blockIdx.x * blockDim.x + threadIdx.x) >> 5;
    if (warp >= NN) return;
    int lane = threadIdx.x & 31;
    int n = warp;
    int beg = g_off[n], end = g_off[n + 1];
    float nd = g_norm[n];
    float acc = 0.f;
    int p = beg;
    for (; p + 3 < end; p += 4) {
        int s0 = g_csr_src[p];
        int s1 = g_csr_src[p + 1];
        int s2 = g_csr_src[p + 2];
        int s3 = g_csr_src[p + 3];
        float c0 = g_norm[s0], c1 = g_norm[s1], c2 = g_norm[s2], c3 = g_norm[s3];
        float v0 = g_hg1[s0 * HID + lane];
        float v1 = g_hg1[s1 * HID + lane];
        float v2 = g_hg1[s2 * HID + lane];
        float v3 = g_hg1[s3 * HID + lane];
        acc += (c0 * v0 + c1 * v1) + (c2 * v2 + c3 * v3);
    }
    for (; p < end; p++) {
        int s0 = g_csr_src[p];
        acc += g_norm[s0] * g_hg1[s0 * HID + lane];
    }
    float v = acc * nd + bias[lane];
    g_go1[n * HID + lane] = (v > 0.f) ? v : 0.f;
}

// ---------------- GCN2 aggregation -> go2 = A_gcn(hg2) + cvec (4x unroll) -----
__global__ void gcn2_agg_csr() {
    int warp = (blockIdx.x * blockDim.x + threadIdx.x) >> 5;
    if (warp >= NN) return;
    int lane = threadIdx.x & 31;
    int n = warp;
    int beg = g_off[n], end = g_off[n + 1];
    float nd = g_norm[n];
    float acc1 = 0.f, acc2 = 0.f;
    int p = beg;
    for (; p + 3 < end; p += 4) {
        int s0 = g_csr_src[p];
        int s1 = g_csr_src[p + 1];
        int s2 = g_csr_src[p + 2];
        int s3 = g_csr_src[p + 3];
        float c0 = g_norm[s0], c1 = g_norm[s1], c2 = g_norm[s2], c3 = g_norm[s3];
        float a0 = g_hg2[s0 * CC + lane];
        float a1 = g_hg2[s1 * CC + lane];
        float a2 = g_hg2[s2 * CC + lane];
        float a3 = g_hg2[s3 * CC + lane];
        acc1 += (c0 * a0 + c1 * a1) + (c2 * a2 + c3 * a3);
        if (lane < CC - 32) {
            float b0 = g_hg2[s0 * CC + 32 + lane];
            float b1 = g_hg2[s1 * CC + 32 + lane];
            float b2 = g_hg2[s2 * CC + 32 + lane];
            float b3 = g_hg2[s3 * CC + 32 + lane];
            acc2 += (c0 * b0 + c1 * b1) + (c2 * b2 + c3 * b3);
        }
    }
    for (; p < end; p++) {
        int s0 = g_csr_src[p];
        float c0 = g_norm[s0];
        acc1 += c0 * g_hg2[s0 * CC + lane];
        if (lane < CC - 32) acc2 += c0 * g_hg2[s0 * CC + 32 + lane];
    }
    g_go2[n * CC + lane] = acc1 * nd + g_cvec[lane];
    if (lane < CC - 32) g_go2[n * CC + 32 + lane] = acc2 * nd + g_cvec[32 + lane];
}

// ---------------- GAT2 aggregation + add go2 -> final out (4x unroll) ---------
__global__ void gat2_agg_out(float* __restrict__ out) {
    int warp = (blockIdx.x * blockDim.x + threadIdx.x) >> 5;
    if (warp >= NN) return;
    int lane = threadIdx.x & 31;
    int n = warp;
    int beg = g_off[n], end = g_off[n + 1];
    float ad = g_ad2[n];
    float acc1 = 0.f, acc2 = 0.f, sumw = 0.f;
    int p = beg;
    for (; p + 3 < end; p += 4) {
        int s0 = g_csr_src[p];
        int s1 = g_csr_src[p + 1];
        int s2 = g_csr_src[p + 2];
        int s3 = g_csr_src[p + 3];
        float l0 = g_as2[s0] + ad;
        float l1 = g_as2[s1] + ad;
        float l2 = g_as2[s2] + ad;
        float l3 = g_as2[s3] + ad;
        float a0 = g_h2[s0 * CC + lane];
        float a1 = g_h2[s1 * CC + lane];
        float a2 = g_h2[s2 * CC + lane];
        float a3 = g_h2[s3 * CC + lane];
        l0 = (l0 > 0.f) ? l0 : NEG_SLOPE * l0;
        l1 = (l1 > 0.f) ? l1 : NEG_SLOPE * l1;
        l2 = (l2 > 0.f) ? l2 : NEG_SLOPE * l2;
        l3 = (l3 > 0.f) ? l3 : NEG_SLOPE * l3;
        float w0 = __expf(l0), w1 = __expf(l1), w2 = __expf(l2), w3 = __expf(l3);
        sumw += (w0 + w1) + (w2 + w3);
        acc1 += (w0 * a0 + w1 * a1) + (w2 * a2 + w3 * a3);
        if (lane < CC - 32) {
            float b0 = g_h2[s0 * CC + 32 + lane];
            float b1 = g_h2[s1 * CC + 32 + lane];
            float b2 = g_h2[s2 * CC + 32 + lane];
            float b3 = g_h2[s3 * CC + 32 + lane];
            acc2 += (w0 * b0 + w1 * b1) + (w2 * b2 + w3 * b3);
        }
    }
    for (; p < end; p++) {
        int s0 = g_csr_src[p];
        float l0 = g_as2[s0] + ad;
        float a0 = g_h2[s0 * CC + lane];
        l0 = (l0 > 0.f) ? l0 : NEG_SLOPE * l0;
        float w0 = __expf(l0);
        sumw += w0;
        acc1 += w0 * a0;
        if (lane < CC - 32) acc2 += w0 * g_h2[s0 * CC + 32 + lane];
    }
    float inv = 1.f / sumw;
    out[n * CC + lane] = acc1 * inv + g_go2[n * CC + lane];
    if (lane < CC - 32) out[n * CC + 32 + lane] = acc2 * inv + g_go2[n * CC + 32 + lane];
}

// ---------------- launch ----------------
extern "C" void kernel_launch(void* const* d_in, const int* in_sizes, int n_in,
                              void* d_out, int out_size) {
    const float* x      = (const float*)d_in[0];
    const void*  eidx   = d_in[1];
    const float* gat_W1 = (const float*)d_in[2];
    const float* att_s1 = (const float*)d_in[3];
    const float* att_d1 = (const float*)d_in[4];
    const float* gat_b1 = (const float*)d_in[5];
    const float* gat_W2 = (const float*)d_in[6];
    const float* att_s2 = (const float*)d_in[7];
    const float* att_d2 = (const float*)d_in[8];
    const float* gat_b2 = (const float*)d_in[9];
    const float* gcn_W1 = (const float*)d_in[10];
    const float* gcn_b1 = (const float*)d_in[11];
    const float* gcn_W2 = (const float*)d_in[12];
    const float* gcn_b2 = (const float*)d_in[13];
    const float* lin_W  = (const float*)d_in[14];
    const float* lin_b  = (const float*)d_in[15];
    const float* wc     = (const float*)d_in[16];
    const float* wt     = (const float*)d_in[17];
    float*       out    = (float*)d_out;

    const int WPB = 8;
    const int AGG_BLK = (NN + WPB - 1) / WPB;
    const int PRE_TOT = F_IN * NCAT + 256 + HH * CC + HID * CC + CC;

    // CSR build
    zero_init<<<(NN + 255) / 256, 256>>>();
    detect_idx<<<256, 256>>>((const unsigned int*)eidx);
    count_deg<<<(EP + 255) / 256, 256>>>(eidx);
    scan_phase1<<<SCAN_BLOCKS, SCAN_CHUNK>>>();
    scan_phase2<<<1, 32>>>();
    scan_phase3<<<(NN + 255) / 256, 256>>>();
    scatter_csr<<<(EP + 255) / 256, 256>>>(eidx);

    // Precompute folds + packed Bcat, then fused projection + logits
    precompute_comb<<<(PRE_TOT + 255) / 256, 256>>>(gat_W1, att_s1, att_d1,
                                                    gat_W2, att_s2, att_d2,
                                                    gcn_W1, gcn_W2, gat_b2, gcn_b2,
                                                    lin_W, lin_b, wc, wt);
    fused_proj<<<dim3((NCAT + BN - 1) / BN, (NN + BM - 1) / BM), 256>>>(x);

    // GAT layer 1 (2 warps/node, 4 nodes/block, exact grid)
    gat1_agg_csr<<<NN / 4, 256>>>(gat_b1);

    // GCN branch (through folded head weights)
    gcn1_agg_csr<<<AGG_BLK, WPB * 32>>>(gcn_b1);
    gemm_gcn2<<<dim3(1, (NN + BM - 1) / BM), 256>>>();
    gcn2_agg_csr<<<AGG_BLK, WPB * 32>>>();

    // GAT layer 2 (projection through folded head weights + logits)
    gemm_l2<<<dim3(1, (NN + BM - 1) / BM), 256>>>();
    gat2_agg_out<<<AGG_BLK, WPB * 32>>>(out);
}

// round 14
// speedup vs baseline: 2.0558x; 1.1030x over previous
#include <cuda_runtime.h>
#include <cuda_bf16.h>
#include <math.h>

// Problem constants (match reference)
#define NN     50000
#define EE     800000
#define EP     850000     // edges + self loops
#define F_IN   128
#define HID    32
#define HEADS  4
#define HH     128        // HEADS*HID
#define CC     40
#define NEG_SLOPE 0.2f

#define SCAN_CHUNK 1024
#define SCAN_BLOCKS ((NN + SCAN_CHUNK - 1) / SCAN_CHUNK)   // 49

#define NCAT (HH + HID + 8)   // 168: [W1 | Wg | comb1]

#define BM 64
#define BN 64
#define BK 16
#define NB_ROWS ((NN + BM - 1) / BM)          // 782
#define PROJ_COLS ((NCAT + BN - 1) / BN)      // 3
#define PROJ_BLOCKS (PROJ_COLS * NB_ROWS)     // 2346
#define SCAT_BLOCKS ((EP + 255) / 256)        // 3321
#define GAT1_BLOCKS (NN / 4)                  // 12500
#define GCN1_BLOCKS ((NN + 7) / 8)            // 6250
#define CNT_BLOCKS ((EP + 255) / 256)         // 3321
#define PRE_TOT (F_IN * NCAT + 256 + HH * CC + HID * CC + CC)
#define PRE_BLOCKS ((PRE_TOT + 255) / 256)    // ~93
#define ZI_BLOCKS ((NN + 255) / 256)          // 196

// ---------------- scratch (device globals; no allocation allowed) ----------------
// g_flag32: NEVER zeroed in device code. Zero-initialized at module load.
// Samplers write 1 iff they see a nonzero odd 32-bit word (=> int32 layout).
// Idempotent and identical across all calls/replays -> deterministic, race-free.
__device__ int   g_flag32;
__device__ int   g_deg[NN];
__device__ int   g_off[NN + 1];
__device__ int   g_cursor[NN];
__device__ int   g_bsum[SCAN_BLOCKS];
__device__ int   g_csr_src[EP];      // src node per CSR slot (grouped by dst)

__device__ float g_Bcat[F_IN * NCAT];  // packed B for fused_proj
__device__ float g_comb2[F_IN * 2];    // attention fold for layer 2
__device__ float g_W2fold[HH * CC];    // gat_W2 @ (wt * lin_W[40:80])
__device__ float g_Wgfold[HID * CC];   // gcn_W2 @ (wc * lin_W[0:40])
__device__ float g_cvec[CC];           // lin_b + biases through head

__device__ float g_h1[NN * HH];      // x @ W1            [N,128]
__device__ float g_as1[NN * HEADS];
__device__ float g_ad1[NN * HEADS];
__device__ float g_out1[NN * HH];    // GAT1 out (elu'd)  [N,128]
__device__ float g_h2[NN * CC];      // out1 @ W2fold     [N,40]
__device__ float g_as2[NN];
__device__ float g_ad2[NN];
__device__ float g_hg1[NN * HID];    // x @ gcnW1         [N,32]
__device__ float g_norm[NN];         // rsqrt(deg)
__device__ float g_go1[NN * HID];    // GCN1 out (relu'd) [N,32]
__device__ float g_hg2[NN * CC];     // go1 @ Wgfold      [N,40]
__device__ float g_go2[NN * CC];     // GCN2 agg + cvec   [N,40]

__device__ __forceinline__ int load_node(const void* eidx, long long idx) {
    int v = g_flag32 ? ((const int*)eidx)[idx]
                     : (int)((const long long*)eidx)[idx];
    return min(max(v, 0), NN - 1);
}

// ---------------- merged: zero degrees + dtype detect ----------------
__global__ void k_init_detect(const unsigned int* __restrict__ raw) {
    int b = blockIdx.x;
    if (b < ZI_BLOCKS) {
        int i = b * 256 + threadIdx.x;
        if (i < NN) g_deg[i] = 0;
    } else {
        int i = (b - ZI_BLOCKS) * 256 + threadIdx.x;   // 65536 samples
        unsigned v = raw[2 * i + 1];
        if (v != 0u) g_flag32 = 1;      // idempotent; never zeroed anywhere
    }
}

// ---------------- merged: count degrees + precompute folds ----------------
__global__ void k_count_pre(const void* __restrict__ eidx,
                            const float* __restrict__ gat_W1,
                            const float* __restrict__ att_s1,
                            const float* __restrict__ att_d1,
                            const float* __restrict__ gat_W2,
                            const float* __restrict__ att_s2,
                            const float* __restrict__ att_d2,
                            const float* __restrict__ gcn_W1,
                            const float* __restrict__ gcn_W2,
                            const float* __restrict__ gat_b2,
                            const float* __restrict__ gcn_b2,
                            const float* __restrict__ lin_W,
                            const float* __restrict__ lin_b,
                            const float* __restrict__ wc_p,
                            const float* __restrict__ wt_p) {
    int b = blockIdx.x;
    if (b < CNT_BLOCKS) {
        int e = b * 256 + threadIdx.x;
        if (e >= EP) return;
        int d = (e < EE) ? load_node(eidx, (long long)EE + e) : (e - EE);
        atomicAdd(&g_deg[d], 1);
    } else {
        int t = (b - CNT_BLOCKS) * 256 + threadIdx.x;
        float wc = *wc_p, wt = *wt_p;
        const int N_BCAT = F_IN * NCAT;
        if (t < N_BCAT) {
            int f = t / NCAT, c = t % NCAT;
            float v;
            if (c < HH) v = gat_W1[f * HH + c];
            else if (c < HH + HID) v = gcn_W1[f * HID + (c - HH)];
            else {
                int j = c - HH - HID;
                int h = j & 3;
                const float* av = (j < 4) ? &att_s1[h * HID] : &att_d1[h * HID];
                const float* wr = &gat_W1[f * HH + h * HID];
                float s = 0.f;
#pragma unroll
                for (int d = 0; d < HID; d++) s += wr[d] * av[d];
                v = s;
            }
            g_Bcat[t] = v;
        } else if (t < N_BCAT + 256) {
            int u = t - N_BCAT, f = u >> 1;
            const float* av = (u & 1) ? att_d2 : att_s2;
            const float* wr = &gat_W2[f * CC];
            float s = 0.f;
#pragma unroll
            for (int c = 0; c < CC; c++) s += wr[c] * av[c];
            g_comb2[f * 2 + (u & 1)] = s;
        } else if (t < N_BCAT + 256 + HH * CC) {
            int u = t - N_BCAT - 256;
            int f = u / CC, c = u % CC;
            float s = 0.f;
#pragma unroll
            for (int j = 0; j < CC; j++) s += gat_W2[f * CC + j] * lin_W[(CC + j) * CC + c];
            g_W2fold[u] = s * wt;
        } else if (t < N_BCAT + 256 + HH * CC + HID * CC) {
            int u = t - N_BCAT - 256 - HH * CC;
            int f = u / CC, c = u % CC;
            float s = 0.f;
#pragma unroll
            for (int j = 0; j < CC; j++) s += gcn_W2[f * CC + j] * lin_W[j * CC + c];
            g_Wgfold[u] = s * wc;
        } else if (t < N_BCAT + 256 + HH * CC + HID * CC + CC) {
            int c = t - N_BCAT - 256 - HH * CC - HID * CC;
            float s = lin_b[c];
#pragma unroll
            for (int j = 0; j < CC; j++) {
                s += wc * gcn_b2[j] * lin_W[j * CC + c];
                s += wt * gat_b2[j] * lin_W[(CC + j) * CC + c];
            }
            g_cvec[c] = s;
        }
    }
}

// ---------------- 3-phase scan ----------------
__global__ void scan_phase1() {
    __shared__ int warp_sums[32];
    int b = blockIdx.x;
    int i = b * SCAN_CHUNK + threadIdx.x;
    int lane = threadIdx.x & 31, wid = threadIdx.x >> 5;
    int v = (i < NN) ? g_deg[i] : 0;
    int x = v;
#pragma unroll
    for (int s = 1; s < 32; s <<= 1) {
        int t = __shfl_up_sync(0xffffffff, x, s);
        if (lane >= s) x += t;
    }
    if (lane == 31) warp_sums[wid] = x;
    __syncthreads();
    if (wid == 0) {
        int ws = warp_sums[lane];
#pragma unroll
        for (int s = 1; s < 32; s <<= 1) {
            int t = __shfl_up_sync(0xffffffff, ws, s);
            if (lane >= s) ws += t;
        }
        warp_sums[lane] = ws;
    }
    __syncthreads();
    int prefix = (wid > 0) ? warp_sums[wid - 1] : 0;
    int excl = prefix + x - v;
    if (i < NN) g_off[i] = excl;
    if (threadIdx.x == SCAN_CHUNK - 1) g_bsum[b] = prefix + x;
}

__global__ void scan_phase2() {
    __shared__ int sh[64];
    int lane = threadIdx.x;
    int v0 = (lane < SCAN_BLOCKS) ? g_bsum[lane] : 0;
    int v1 = (lane + 32 < SCAN_BLOCKS) ? g_bsum[lane + 32] : 0;
    int x = v0;
#pragma unroll
    for (int s = 1; s < 32; s <<= 1) {
        int t = __shfl_up_sync(0xffffffff, x, s);
        if (lane >= s) x += t;
    }
    int tot0 = __shfl_sync(0xffffffff, x, 31);
    int y = v1;
#pragma unroll
    for (int s = 1; s < 32; s <<= 1) {
        int t = __shfl_up_sync(0xffffffff, y, s);
        if (lane >= s) y += t;
    }
    sh[lane] = x - v0;
    sh[lane + 32] = tot0 + y - v1;
    __syncwarp();
    if (lane < SCAN_BLOCKS) g_bsum[lane] = sh[lane];
    if (lane + 32 < SCAN_BLOCKS) g_bsum[lane + 32] = sh[lane + 32];
}

__global__ void scan_phase3() {
    int i = blockIdx.x * blockDim.x + threadIdx.x;
    if (i == 0) g_off[NN] = EP;
    if (i >= NN) return;
    int o = g_off[i] + g_bsum[i / SCAN_CHUNK];
    g_off[i] = o;
    g_cursor[i] = o;
    g_norm[i] = rsqrtf((float)g_deg[i]);
}

// ---------------- merged: fused projection + CSR scatter ----------------
__global__ void __launch_bounds__(256) k_proj_scatter(const float* __restrict__ x,
                                                      const void* __restrict__ eidx) {
    __shared__ float As[BK][BM + 1];
    __shared__ float Bs[BK][BN];
    int b = blockIdx.x;
    if (b >= PROJ_BLOCKS) {
        int e = (b - PROJ_BLOCKS) * 256 + threadIdx.x;
        if (e >= EP) return;
        int s, d;
        if (e < EE) {
            s = load_node(eidx, e);
            d = load_node(eidx, (long long)EE + e);
        } else {
            s = d = e - EE;
        }
        int pos = atomicAdd(&g_cursor[d], 1);
        g_csr_src[pos] = s;
        return;
    }
    int tid = threadIdx.x;
    int tx = tid % 16, ty = tid / 16;
    int row0 = (b / PROJ_COLS) * BM;
    int col0 = (b % PROJ_COLS) * BN;
    float acc[4][4] = {};
    for (int k0 = 0; k0 < F_IN; k0 += BK) {
        {
            int r = tid >> 2;
            int c4 = (tid & 3) * 4;
            int gr = row0 + r;
            float4 v = (gr < NN) ? *(const float4*)&x[gr * F_IN + k0 + c4]
                                 : make_float4(0.f, 0.f, 0.f, 0.f);
            As[c4 + 0][r] = v.x;
            As[c4 + 1][r] = v.y;
            As[c4 + 2][r] = v.z;
            As[c4 + 3][r] = v.w;
        }
        {
            int r = tid >> 4;
            int c4 = (tid & 15) * 4;
            int gc = col0 + c4;
            float4 v = (gc + 3 < NCAT) ? *(const float4*)&g_Bcat[(k0 + r) * NCAT + gc]
                                       : make_float4(0.f, 0.f, 0.f, 0.f);
            *(float4*)&Bs[r][c4] = v;
        }
        __syncthreads();
#pragma unroll
        for (int k = 0; k < BK; k++) {
            float a[4], bb[4];
#pragma unroll
            for (int i = 0; i < 4; i++) a[i] = As[k][ty * 4 + i];
#pragma unroll
            for (int j = 0; j < 4; j++) bb[j] = Bs[k][tx * 4 + j];
#pragma unroll
            for (int i = 0; i < 4; i++)
#pragma unroll
                for (int j = 0; j < 4; j++) acc[i][j] += a[i] * bb[j];
        }
        __syncthreads();
    }
#pragma unroll
    for (int i = 0; i < 4; i++) {
        int gr = row0 + ty * 4 + i;
        if (gr >= NN) continue;
#pragma unroll
        for (int j = 0; j < 4; j++) {
            int gc = col0 + tx * 4 + j;
            if (gc < HH) g_h1[gr * HH + gc] = acc[i][j];
            else if (gc < HH + HID) g_hg1[gr * HID + (gc - HH)] = acc[i][j];
            else if (gc < HH + HID + 4) g_as1[gr * 4 + (gc - HH - HID)] = acc[i][j];
            else if (gc < NCAT) g_ad1[gr * 4 + (gc - HH - HID - 4)] = acc[i][j];
        }
    }
}

// ---------------- merged layer-1: GAT1 (2-warp split) + GCN1 ----------------
__global__ void __launch_bounds__(256) k_layer1(const float* __restrict__ gat_b1,
                                                const float* __restrict__ gcn_b1) {
    __shared__ float s_acc[8][HH];
    __shared__ float s_sum[8][4];
    int b = blockIdx.x;
    int wid = threadIdx.x >> 5;
    int lane = threadIdx.x & 31;
    if (b < GAT1_BLOCKS) {
        int n = b * 4 + (wid >> 1);
        int half = wid & 1;
        int beg = g_off[n], end = g_off[n + 1];
        int mid = beg + ((end - beg) >> 1);
        int lo = half ? mid : beg;
        int hi = half ? end : mid;
        int h = lane >> 3;
        float ad = g_ad1[n * 4 + h];
        float4 acc = {0.f, 0.f, 0.f, 0.f};
        float sumw = 0.f;
        int p = lo;
        for (; p + 3 < hi; p += 4) {
            int s0 = g_csr_src[p];
            int s1 = g_csr_src[p + 1];
            int s2 = g_csr_src[p + 2];
            int s3 = g_csr_src[p + 3];
            float l0 = g_as1[s0 * 4 + h] + ad;
            float l1 = g_as1[s1 * 4 + h] + ad;
            float l2 = g_as1[s2 * 4 + h] + ad;
            float l3 = g_as1[s3 * 4 + h] + ad;
            float4 h0 = *(const float4*)&g_h1[s0 * HH + lane * 4];
            float4 h1 = *(const float4*)&g_h1[s1 * HH + lane * 4];
            float4 h2 = *(const float4*)&g_h1[s2 * HH + lane * 4];
            float4 h3 = *(const float4*)&g_h1[s3 * HH + lane * 4];
            l0 = (l0 > 0.f) ? l0 : NEG_SLOPE * l0;
            l1 = (l1 > 0.f) ? l1 : NEG_SLOPE * l1;
            l2 = (l2 > 0.f) ? l2 : NEG_SLOPE * l2;
            l3 = (l3 > 0.f) ? l3 : NEG_SLOPE * l3;
            float w0 = __expf(l0), w1 = __expf(l1), w2 = __expf(l2), w3 = __expf(l3);
            sumw += (w0 + w1) + (w2 + w3);
            acc.x += w0 * h0.x + w1 * h1.x + w2 * h2.x + w3 * h3.x;
            acc.y += w0 * h0.y + w1 * h1.y + w2 * h2.y + w3 * h3.y;
            acc.z += w0 * h0.z + w1 * h1.z + w2 * h2.z + w3 * h3.z;
            acc.w += w0 * h0.w + w1 * h1.w + w2 * h2.w + w3 * h3.w;
        }
        for (; p < hi; p++) {
            int s0 = g_csr_src[p];
            float l0 = g_as1[s0 * 4 + h] + ad;
            float4 h0 = *(const float4*)&g_h1[s0 * HH + lane * 4];
            l0 = (l0 > 0.f) ? l0 : NEG_SLOPE * l0;
            float w0 = __expf(l0);
            sumw += w0;
            acc.x += w0 * h0.x; acc.y += w0 * h0.y; acc.z += w0 * h0.z; acc.w += w0 * h0.w;
        }
        if (half) {
            *(float4*)&s_acc[wid][lane * 4] = acc;
            if ((lane & 7) == 0) s_sum[wid][h] = sumw;   // per-head partial sums
        }
        __syncthreads();
        if (!half) {
            float4 pa = *(const float4*)&s_acc[wid + 1][lane * 4];
            acc.x += pa.x; acc.y += pa.y; acc.z += pa.z; acc.w += pa.w;
            sumw += s_sum[wid + 1][h];
            float inv = 1.f / sumw;
            float4 bv = *(const float4*)&gat_b1[lane * 4];
            float4 o;
            float vx = acc.x * inv + bv.x; o.x = (vx > 0.f) ? vx : expm1f(vx);
            float vy = acc.y * inv + bv.y; o.y = (vy > 0.f) ? vy : expm1f(vy);
            float vz = acc.z * inv + bv.z; o.z = (vz > 0.f) ? vz : expm1f(vz);
            float vw = acc.w * inv + bv.w; o.w = (vw > 0.f) ? vw : expm1f(vw);
            *(float4*)&g_out1[n * HH + lane * 4] = o;
        }
    } else {
        int n = (b - GAT1_BLOCKS) * 8 + wid;
        if (n >= NN) return;
        int beg = g_off[n], end = g_off[n + 1];
        float nd = g_norm[n];
        float acc = 0.f;
        int p = beg;
        for (; p + 3 < end; p += 4) {
            int s0 = g_csr_src[p];
            int s1 = g_csr_src[p + 1];
            int s2 = g_csr_src[p + 2];
            int s3 = g_csr_src[p + 3];
            float c0 = g_norm[s0], c1 = g_norm[s1], c2 = g_norm[s2], c3 = g_norm[s3];
            float v0 = g_hg1[s0 * HID + lane];
            float v1 = g_hg1[s1 * HID + lane];
            float v2 = g_hg1[s2 * HID + lane];
            float v3 = g_hg1[s3 * HID + lane];
            acc += (c0 * v0 + c1 * v1) + (c2 * v2 + c3 * v3);
        }
        for (; p < end; p++) {
            int s0 = g_csr_src[p];
            acc += g_norm[s0] * g_hg1[s0 * HID + lane];
        }
        float v = acc * nd + gcn_b1[lane];
        g_go1[n * HID + lane] = (v > 0.f) ? v : 0.f;
    }
}

// ---------------- merged layer-2 GEMMs: gemm_l2 + gemm_gcn2 ----------------
__global__ void __launch_bounds__(256) k_gemms2() {
    __shared__ float As[BK][BM + 1];
    __shared__ float Bs[BK][BN];
    int b = blockIdx.x;
    int tid = threadIdx.x;
    int tx = tid % 16, ty = tid / 16;
    float acc[4][4] = {};
    if (b < NB_ROWS) {
        const float* A = g_out1;
        int row0 = b * BM;
        for (int k0 = 0; k0 < HH; k0 += BK) {
            {
                int r = tid >> 2;
                int c4 = (tid & 3) * 4;
                int gr = row0 + r;
                float4 v = (gr < NN) ? *(const float4*)&A[gr * HH + k0 + c4]
                                     : make_float4(0.f, 0.f, 0.f, 0.f);
                As[c4 + 0][r] = v.x;
                As[c4 + 1][r] = v.y;
                As[c4 + 2][r] = v.z;
                As[c4 + 3][r] = v.w;
            }
            for (int i = tid; i < BK * BN; i += 256) {
                int r = i / BN, c = i % BN;
                float v;
                if (c < CC) v = g_W2fold[(k0 + r) * CC + c];
                else if (c < CC + 2) v = g_comb2[(k0 + r) * 2 + (c - CC)];
                else v = 0.f;
                Bs[r][c] = v;
            }
            __syncthreads();
#pragma unroll
            for (int k = 0; k < BK; k++) {
                float a[4], bb[4];
#pragma unroll
                for (int i = 0; i < 4; i++) a[i] = As[k][ty * 4 + i];
#pragma unroll
                for (int j = 0; j < 4; j++) bb[j] = Bs[k][tx * 4 + j];
#pragma unroll
                for (int i = 0; i < 4; i++)
#pragma unroll
                    for (int j = 0; j < 4; j++) acc[i][j] += a[i] * bb[j];
            }
            __syncthreads();
        }
#pragma unroll
        for (int i = 0; i < 4; i++) {
            int gr = row0 + ty * 4 + i;
            if (gr >= NN) continue;
#pragma unroll
            for (int j = 0; j < 4; j++) {
                int gc = tx * 4 + j;
                if (gc < CC) g_h2[gr * CC + gc] = acc[i][j];
                else if (gc == CC) g_as2[gr] = acc[i][j];
                else if (gc == CC + 1) g_ad2[gr] = acc[i][j];
            }
        }
    } else {
        const float* A = g_go1;
        int row0 = (b - NB_ROWS) * BM;
        for (int k0 = 0; k0 < HID; k0 += BK) {
            {
                int r = tid >> 2;
                int c4 = (tid & 3) * 4;
                int gr = row0 + r;
                float4 v = (gr < NN) ? *(const float4*)&A[gr * HID + k0 + c4]
                                     : make_float4(0.f, 0.f, 0.f, 0.f);
                As[c4 + 0][r] = v.x;
                As[c4 + 1][r] = v.y;
                As[c4 + 2][r] = v.z;
                As[c4 + 3][r] = v.w;
            }
            for (int i = tid; i < BK * BN; i += 256) {
                int r = i / BN, c = i % BN;
                Bs[r][c] = (c < CC) ? g_Wgfold[(k0 + r) * CC + c] : 0.f;
            }
            __syncthreads();
#pragma unroll
            for (int k = 0; k < BK; k++) {
                float a[4], bb[4];
#pragma unroll
                for (int i = 0; i < 4; i++) a[i] = As[k][ty * 4 + i];
#pragma unroll
                for (int j = 0; j < 4; j++) bb[j] = Bs[k][tx * 4 + j];
#pragma unroll
                for (int i = 0; i < 4; i++)
#pragma unroll
                    for (int j = 0; j < 4; j++) acc[i][j] += a[i] * bb[j];
            }
            __syncthreads();
        }
#pragma unroll
        for (int i = 0; i < 4; i++) {
            int gr = row0 + ty * 4 + i;
            if (gr >= NN) continue;
#pragma unroll
            for (int j = 0; j < 4; j++) {
                int gc = tx * 4 + j;
                if (gc < CC) g_hg2[gr * CC + gc] = acc[i][j];
            }
        }
    }
}

// ---------------- GCN2 aggregation -> go2 = A_gcn(hg2) + cvec (4x unroll) -----
__global__ void gcn2_agg_csr() {
    int warp = (blockIdx.x * blockDim.x + threadIdx.x) >> 5;
    if (warp >= NN) return;
    int lane = threadIdx.x & 31;
    int n = warp;
    int beg = g_off[n], end = g_off[n + 1];
    float nd = g_norm[n];
    float acc1 = 0.f, acc2 = 0.f;
    int p = beg;
    for (; p + 3 < end; p += 4) {
        int s0 = g_csr_src[p];
        int s1 = g_csr_src[p + 1];
        int s2 = g_csr_src[p + 2];
        int s3 = g_csr_src[p + 3];
        float c0 = g_norm[s0], c1 = g_norm[s1], c2 = g_norm[s2], c3 = g_norm[s3];
        float a0 = g_hg2[s0 * CC + lane];
        float a1 = g_hg2[s1 * CC + lane];
        float a2 = g_hg2[s2 * CC + lane];
        float a3 = g_hg2[s3 * CC + lane];
        acc1 += (c0 * a0 + c1 * a1) + (c2 * a2 + c3 * a3);
        if (lane < CC - 32) {
            float b0 = g_hg2[s0 * CC + 32 + lane];
            float b1 = g_hg2[s1 * CC + 32 + lane];
            float b2 = g_hg2[s2 * CC + 32 + lane];
            float b3 = g_hg2[s3 * CC + 32 + lane];
            acc2 += (c0 * b0 + c1 * b1) + (c2 * b2 + c3 * b3);
        }
    }
    for (; p < end; p++) {
        int s0 = g_csr_src[p];
        float c0 = g_norm[s0];
        acc1 += c0 * g_hg2[s0 * CC + lane];
        if (lane < CC - 32) acc2 += c0 * g_hg2[s0 * CC + 32 + lane];
    }
    g_go2[n * CC + lane] = acc1 * nd + g_cvec[lane];
    if (lane < CC - 32) g_go2[n * CC + 32 + lane] = acc2 * nd + g_cvec[32 + lane];
}

// ---------------- GAT2 aggregation + add go2 -> final out (4x unroll) ---------
__global__ void gat2_agg_out(float* __restrict__ out) {
    int warp = (blockIdx.x * blockDim.x + threadIdx.x) >> 5;
    if (warp >= NN) return;
    int lane = threadIdx.x & 31;
    int n = warp;
    int beg = g_off[n], end = g_off[n + 1];
    float ad = g_ad2[n];
    float acc1 = 0.f, acc2 = 0.f, sumw = 0.f;
    int p = beg;
    for (; p + 3 < end; p += 4) {
        int s0 = g_csr_src[p];
        int s1 = g_csr_src[p + 1];
        int s2 = g_csr_src[p + 2];
        int s3 = g_csr_src[p + 3];
        float l0 = g_as2[s0] + ad;
        float l1 = g_as2[s1] + ad;
        float l2 = g_as2[s2] + ad;
        float l3 = g_as2[s3] + ad;
        float a0 = g_h2[s0 * CC + lane];
        float a1 = g_h2[s1 * CC + lane];
        float a2 = g_h2[s2 * CC + lane];
        float a3 = g_h2[s3 * CC + lane];
        l0 = (l0 > 0.f) ? l0 : NEG_SLOPE * l0;
        l1 = (l1 > 0.f) ? l1 : NEG_SLOPE * l1;
        l2 = (l2 > 0.f) ? l2 : NEG_SLOPE * l2;
        l3 = (l3 > 0.f) ? l3 : NEG_SLOPE * l3;
        float w0 = __expf(l0), w1 = __expf(l1), w2 = __expf(l2), w3 = __expf(l3);
        sumw += (w0 + w1) + (w2 + w3);
        acc1 += (w0 * a0 + w1 * a1) + (w2 * a2 + w3 * a3);
        if (lane < CC - 32) {
            float b0 = g_h2[s0 * CC + 32 + lane];
            float b1 = g_h2[s1 * CC + 32 + lane];
            float b2 = g_h2[s2 * CC + 32 + lane];
            float b3 = g_h2[s3 * CC + 32 + lane];
            acc2 += (w0 * b0 + w1 * b1) + (w2 * b2 + w3 * b3);
        }
    }
    for (; p < end; p++) {
        int s0 = g_csr_src[p];
        float l0 = g_as2[s0] + ad;
        float a0 = g_h2[s0 * CC + lane];
        l0 = (l0 > 0.f) ? l0 : NEG_SLOPE * l0;
        float w0 = __expf(l0);
        sumw += w0;
        acc1 += w0 * a0;
        if (lane < CC - 32) acc2 += w0 * g_h2[s0 * CC + 32 + lane];
    }
    float inv = 1.f / sumw;
    out[n * CC + lane] = acc1 * inv + g_go2[n * CC + lane];
    if (lane < CC - 32) out[n * CC + 32 + lane] = acc2 * inv + g_go2[n * CC + 32 + lane];
}

// ---------------- launch ----------------
extern "C" void kernel_launch(void* const* d_in, const int* in_sizes, int n_in,
                              void* d_out, int out_size) {
    const float* x      = (const float*)d_in[0];
    const void*  eidx   = d_in[1];
    const float* gat_W1 = (const float*)d_in[2];
    const float* att_s1 = (const float*)d_in[3];
    const float* att_d1 = (const float*)d_in[4];
    const float* gat_b1 = (const float*)d_in[5];
    const float* gat_W2 = (const float*)d_in[6];
    const float* att_s2 = (const float*)d_in[7];
    const float* att_d2 = (const float*)d_in[8];
    const float* gat_b2 = (const float*)d_in[9];
    const float* gcn_W1 = (const float*)d_in[10];
    const float* gcn_b1 = (const float*)d_in[11];
    const float* gcn_W2 = (const float*)d_in[12];
    const float* gcn_b2 = (const float*)d_in[13];
    const float* lin_W  = (const float*)d_in[14];
    const float* lin_b  = (const float*)d_in[15];
    const float* wc     = (const float*)d_in[16];
    const float* wt     = (const float*)d_in[17];
    float*       out    = (float*)d_out;

    const int WPB = 8;
    const int AGG_BLK = (NN + WPB - 1) / WPB;

    // 1) zero degrees ∥ dtype detect (flag is set-only, never zeroed)
    k_init_detect<<<ZI_BLOCKS + 256, 256>>>((const unsigned int*)eidx);
    // 2) count degrees ∥ precompute folds
    k_count_pre<<<CNT_BLOCKS + PRE_BLOCKS, 256>>>(eidx, gat_W1, att_s1, att_d1,
                                                  gat_W2, att_s2, att_d2,
                                                  gcn_W1, gcn_W2, gat_b2, gcn_b2,
                                                  lin_W, lin_b, wc, wt);
    // 3-5) scan
    scan_phase1<<<SCAN_BLOCKS, SCAN_CHUNK>>>();
    scan_phase2<<<1, 32>>>();
    scan_phase3<<<(NN + 255) / 256, 256>>>();
    // 6) fused projection ∥ CSR scatter
    k_proj_scatter<<<PROJ_BLOCKS + SCAT_BLOCKS, 256>>>(x, eidx);
    // 7) GAT1 ∥ GCN1
    k_layer1<<<GAT1_BLOCKS + GCN1_BLOCKS, 256>>>(gat_b1, gcn_b1);
    // 8) gemm_l2 ∥ gemm_gcn2
    k_gemms2<<<NB_ROWS * 2, 256>>>();
    // 9) GCN2 aggregation
    gcn2_agg_csr<<<AGG_BLK, WPB * 32>>>();
    // 10) GAT2 aggregation + final output
    gat2_agg_out<<<AGG_BLK, WPB * 32>>>(out);
}

// round 15
// speedup vs baseline: 2.0583x; 1.0012x over previous
#include <cuda_runtime.h>
#include <cuda_bf16.h>
#include <math.h>

// Problem constants (match reference)
#define NN     50000
#define EE     800000
#define EP     850000     // edges + self loops
#define F_IN   128
#define HID    32
#define HEADS  4
#define HH     128        // HEADS*HID
#define CC     40
#define NEG_SLOPE 0.2f

#define SCAN_CHUNK 1024
#define SCAN_BLOCKS ((NN + SCAN_CHUNK - 1) / SCAN_CHUNK)   // 49

#define NCAT (HH + HID + 8)   // 168: [W1 | Wg | comb1]

#define BM 64
#define BN 64
#define BK 16
#define NB_ROWS ((NN + BM - 1) / BM)          // 782
#define PROJ_COLS ((NCAT + BN - 1) / BN)      // 3
#define PROJ_BLOCKS (PROJ_COLS * NB_ROWS)     // 2346
#define SCAT_BLOCKS ((EP + 255) / 256)        // 3321
#define GAT1_BLOCKS (NN / 4)                  // 12500
#define GCN1_BLOCKS ((NN + 7) / 8)            // 6250
#define CNT_BLOCKS ((EP + 255) / 256)         // 3321
#define PRE_TOT (F_IN * NCAT + 256 + HH * CC + HID * CC + CC)
#define PRE_BLOCKS ((PRE_TOT + 255) / 256)    // ~93
#define ZI_BLOCKS ((NN + 255) / 256)          // 196
#define AGG_BLK ((NN + 7) / 8)                // 6250 (8 warps/block)

// ---------------- scratch (device globals; no allocation allowed) ----------------
// g_flag32: NEVER zeroed; set-only (idempotent) => deterministic across replays.
// g_deg: zero at module load; re-zeroed by gat2_agg_out tail blocks each call.
__device__ int   g_flag32;
__device__ int   g_deg[NN];
__device__ int   g_off[NN + 1];
__device__ int   g_cursor[NN];
__device__ int   g_bsum[SCAN_BLOCKS];  // raw per-chunk totals (no global scan pass)
__device__ int   g_csr_src[EP];

__device__ float g_Bcat[F_IN * NCAT];
__device__ float g_comb2[F_IN * 2];
__device__ float g_W2fold[HH * CC];
__device__ float g_Wgfold[HID * CC];
__device__ float g_cvec[CC];

__device__ float g_h1[NN * HH];
__device__ float g_as1[NN * HEADS];
__device__ float g_ad1[NN * HEADS];
__device__ float g_out1[NN * HH];
__device__ float g_h2[NN * CC];
__device__ float g_as2[NN];
__device__ float g_ad2[NN];
__device__ float g_hg1[NN * HID];
__device__ float g_norm[NN];
__device__ float g_go1[NN * HID];
__device__ float g_hg2[NN * CC];
__device__ float g_go2[NN * CC];

__device__ __forceinline__ int load_node(const void* eidx, long long idx) {
    int v = g_flag32 ? ((const int*)eidx)[idx]
                     : (int)((const long long*)eidx)[idx];
    return min(max(v, 0), NN - 1);
}

// ---------------- dtype detect (sampler only; flag is set-only) ----------------
__global__ void k_detect(const unsigned int* __restrict__ raw) {
    int i = blockIdx.x * 256 + threadIdx.x;   // 65536 samples
    unsigned v = raw[2 * i + 1];
    if (v != 0u) g_flag32 = 1;
}

// ---------------- merged: count degrees + precompute folds ----------------
__global__ void k_count_pre(const void* __restrict__ eidx,
                            const float* __restrict__ gat_W1,
                            const float* __restrict__ att_s1,
                            const float* __restrict__ att_d1,
                            const float* __restrict__ gat_W2,
                            const float* __restrict__ att_s2,
                            const float* __restrict__ att_d2,
                            const float* __restrict__ gcn_W1,
                            const float* __restrict__ gcn_W2,
                            const float* __restrict__ gat_b2,
                            const float* __restrict__ gcn_b2,
                            const float* __restrict__ lin_W,
                            const float* __restrict__ lin_b,
                            const float* __restrict__ wc_p,
                            const float* __restrict__ wt_p) {
    int b = blockIdx.x;
    if (b < CNT_BLOCKS) {
        int e = b * 256 + threadIdx.x;
        if (e >= EP) return;
        int d = (e < EE) ? load_node(eidx, (long long)EE + e) : (e - EE);
        atomicAdd(&g_deg[d], 1);
    } else {
        int t = (b - CNT_BLOCKS) * 256 + threadIdx.x;
        float wc = *wc_p, wt = *wt_p;
        const int N_BCAT = F_IN * NCAT;
        if (t < N_BCAT) {
            int f = t / NCAT, c = t % NCAT;
            float v;
            if (c < HH) v = gat_W1[f * HH + c];
            else if (c < HH + HID) v = gcn_W1[f * HID + (c - HH)];
            else {
                int j = c - HH - HID;
                int h = j & 3;
                const float* av = (j < 4) ? &att_s1[h * HID] : &att_d1[h * HID];
                const float* wr = &gat_W1[f * HH + h * HID];
                float s = 0.f;
#pragma unroll
                for (int d = 0; d < HID; d++) s += wr[d] * av[d];
                v = s;
            }
            g_Bcat[t] = v;
        } else if (t < N_BCAT + 256) {
            int u = t - N_BCAT, f = u >> 1;
            const float* av = (u & 1) ? att_d2 : att_s2;
            const float* wr = &gat_W2[f * CC];
            float s = 0.f;
#pragma unroll
            for (int c = 0; c < CC; c++) s += wr[c] * av[c];
            g_comb2[f * 2 + (u & 1)] = s;
        } else if (t < N_BCAT + 256 + HH * CC) {
            int u = t - N_BCAT - 256;
            int f = u / CC, c = u % CC;
            float s = 0.f;
#pragma unroll
            for (int j = 0; j < CC; j++) s += gat_W2[f * CC + j] * lin_W[(CC + j) * CC + c];
            g_W2fold[u] = s * wt;
        } else if (t < N_BCAT + 256 + HH * CC + HID * CC) {
            int u = t - N_BCAT - 256 - HH * CC;
            int f = u / CC, c = u % CC;
            float s = 0.f;
#pragma unroll
            for (int j = 0; j < CC; j++) s += gcn_W2[f * CC + j] * lin_W[j * CC + c];
            g_Wgfold[u] = s * wc;
        } else if (t < N_BCAT + 256 + HH * CC + HID * CC + CC) {
            int c = t - N_BCAT - 256 - HH * CC - HID * CC;
            float s = lin_b[c];
#pragma unroll
            for (int j = 0; j < CC; j++) {
                s += wc * gcn_b2[j] * lin_W[j * CC + c];
                s += wt * gat_b2[j] * lin_W[(CC + j) * CC + c];
            }
            g_cvec[c] = s;
        }
    }
}

// ---------------- scan phase 1: per-chunk exclusive scan + raw chunk totals -----
__global__ void scan_phase1() {
    __shared__ int warp_sums[32];
    int b = blockIdx.x;
    int i = b * SCAN_CHUNK + threadIdx.x;
    int lane = threadIdx.x & 31, wid = threadIdx.x >> 5;
    int v = (i < NN) ? g_deg[i] : 0;
    int x = v;
#pragma unroll
    for (int s = 1; s < 32; s <<= 1) {
        int t = __shfl_up_sync(0xffffffff, x, s);
        if (lane >= s) x += t;
    }
    if (lane == 31) warp_sums[wid] = x;
    __syncthreads();
    if (wid == 0) {
        int ws = warp_sums[lane];
#pragma unroll
        for (int s = 1; s < 32; s <<= 1) {
            int t = __shfl_up_sync(0xffffffff, ws, s);
            if (lane >= s) ws += t;
        }
        warp_sums[lane] = ws;
    }
    __syncthreads();
    int prefix = (wid > 0) ? warp_sums[wid - 1] : 0;
    int excl = prefix + x - v;
    if (i < NN) g_off[i] = excl;
    if (threadIdx.x == SCAN_CHUNK - 1) g_bsum[b] = prefix + x;   // raw total
}

// ---------------- scan phase 3 (with inline chunk-prefix; phase2 deleted) -------
// 256 threads/block => all threads in a block share chunk = blockIdx.x >> 2.
__global__ void scan_phase3() {
    __shared__ int s_prefix;
    int chunk = blockIdx.x >> 2;
    if (threadIdx.x == 0) {
        int s = 0;
        for (int c = 0; c < chunk; c++) s += g_bsum[c];   // <=48 L1-hot loads
        s_prefix = s;
    }
    __syncthreads();
    int i = blockIdx.x * 256 + threadIdx.x;
    if (i == 0) g_off[NN] = EP;
    if (i >= NN) return;
    int o = g_off[i] + s_prefix;
    g_off[i] = o;
    g_cursor[i] = o;
    g_norm[i] = rsqrtf((float)g_deg[i]);
}

// ---------------- merged: fused projection + CSR scatter ----------------
__global__ void __launch_bounds__(256) k_proj_scatter(const float* __restrict__ x,
                                                      const void* __restrict__ eidx) {
    __shared__ float As[BK][BM + 1];
    __shared__ float Bs[BK][BN];
    int b = blockIdx.x;
    if (b >= PROJ_BLOCKS) {
        int e = (b - PROJ_BLOCKS) * 256 + threadIdx.x;
        if (e >= EP) return;
        int s, d;
        if (e < EE) {
            s = load_node(eidx, e);
            d = load_node(eidx, (long long)EE + e);
        } else {
            s = d = e - EE;
        }
        int pos = atomicAdd(&g_cursor[d], 1);
        g_csr_src[pos] = s;
        return;
    }
    int tid = threadIdx.x;
    int tx = tid % 16, ty = tid / 16;
    int row0 = (b / PROJ_COLS) * BM;
    int col0 = (b % PROJ_COLS) * BN;
    float acc[4][4] = {};
    for (int k0 = 0; k0 < F_IN; k0 += BK) {
        {
            int r = tid >> 2;
            int c4 = (tid & 3) * 4;
            int gr = row0 + r;
            float4 v = (gr < NN) ? *(const float4*)&x[gr * F_IN + k0 + c4]
                                 : make_float4(0.f, 0.f, 0.f, 0.f);
            As[c4 + 0][r] = v.x;
            As[c4 + 1][r] = v.y;
            As[c4 + 2][r] = v.z;
            As[c4 + 3][r] = v.w;
        }
        {
            int r = tid >> 4;
            int c4 = (tid & 15) * 4;
            int gc = col0 + c4;
            float4 v = (gc + 3 < NCAT) ? *(const float4*)&g_Bcat[(k0 + r) * NCAT + gc]
                                       : make_float4(0.f, 0.f, 0.f, 0.f);
            *(float4*)&Bs[r][c4] = v;
        }
        __syncthreads();
#pragma unroll
        for (int k = 0; k < BK; k++) {
            float a[4], bb[4];
#pragma unroll
            for (int i = 0; i < 4; i++) a[i] = As[k][ty * 4 + i];
#pragma unroll
            for (int j = 0; j < 4; j++) bb[j] = Bs[k][tx * 4 + j];
#pragma unroll
            for (int i = 0; i < 4; i++)
#pragma unroll
                for (int j = 0; j < 4; j++) acc[i][j] += a[i] * bb[j];
        }
        __syncthreads();
    }
#pragma unroll
    for (int i = 0; i < 4; i++) {
        int gr = row0 + ty * 4 + i;
        if (gr >= NN) continue;
#pragma unroll
        for (int j = 0; j < 4; j++) {
            int gc = col0 + tx * 4 + j;
            if (gc < HH) g_h1[gr * HH + gc] = acc[i][j];
            else if (gc < HH + HID) g_hg1[gr * HID + (gc - HH)] = acc[i][j];
            else if (gc < HH + HID + 4) g_as1[gr * 4 + (gc - HH - HID)] = acc[i][j];
            else if (gc < NCAT) g_ad1[gr * 4 + (gc - HH - HID - 4)] = acc[i][j];
        }
    }
}

// ---------------- merged layer-1: GAT1 (2-warp split) + GCN1 ----------------
__global__ void __launch_bounds__(256) k_layer1(const float* __restrict__ gat_b1,
                                                const float* __restrict__ gcn_b1) {
    __shared__ float s_acc[8][HH];
    __shared__ float s_sum[8][4];
    int b = blockIdx.x;
    int wid = threadIdx.x >> 5;
    int lane = threadIdx.x & 31;
    if (b < GAT1_BLOCKS) {
        int n = b * 4 + (wid >> 1);
        int half = wid & 1;
        int beg = g_off[n], end = g_off[n + 1];
        int mid = beg + ((end - beg) >> 1);
        int lo = half ? mid : beg;
        int hi = half ? end : mid;
        int h = lane >> 3;
        float ad = g_ad1[n * 4 + h];
        float4 acc = {0.f, 0.f, 0.f, 0.f};
        float sumw = 0.f;
        int p = lo;
        for (; p + 3 < hi; p += 4) {
            int s0 = g_csr_src[p];
            int s1 = g_csr_src[p + 1];
            int s2 = g_csr_src[p + 2];
            int s3 = g_csr_src[p + 3];
            float l0 = g_as1[s0 * 4 + h] + ad;
            float l1 = g_as1[s1 * 4 + h] + ad;
            float l2 = g_as1[s2 * 4 + h] + ad;
            float l3 = g_as1[s3 * 4 + h] + ad;
            float4 h0 = *(const float4*)&g_h1[s0 * HH + lane * 4];
            float4 h1 = *(const float4*)&g_h1[s1 * HH + lane * 4];
            float4 h2 = *(const float4*)&g_h1[s2 * HH + lane * 4];
            float4 h3 = *(const float4*)&g_h1[s3 * HH + lane * 4];
            l0 = (l0 > 0.f) ? l0 : NEG_SLOPE * l0;
            l1 = (l1 > 0.f) ? l1 : NEG_SLOPE * l1;
            l2 = (l2 > 0.f) ? l2 : NEG_SLOPE * l2;
            l3 = (l3 > 0.f) ? l3 : NEG_SLOPE * l3;
            float w0 = __expf(l0), w1 = __expf(l1), w2 = __expf(l2), w3 = __expf(l3);
            sumw += (w0 + w1) + (w2 + w3);
            acc.x += w0 * h0.x + w1 * h1.x + w2 * h2.x + w3 * h3.x;
            acc.y += w0 * h0.y + w1 * h1.y + w2 * h2.y + w3 * h3.y;
            acc.z += w0 * h0.z + w1 * h1.z + w2 * h2.z + w3 * h3.z;
            acc.w += w0 * h0.w + w1 * h1.w + w2 * h2.w + w3 * h3.w;
        }
        for (; p < hi; p++) {
            int s0 = g_csr_src[p];
            float l0 = g_as1[s0 * 4 + h] + ad;
            float4 h0 = *(const float4*)&g_h1[s0 * HH + lane * 4];
            l0 = (l0 > 0.f) ? l0 : NEG_SLOPE * l0;
            float w0 = __expf(l0);
            sumw += w0;
            acc.x += w0 * h0.x; acc.y += w0 * h0.y; acc.z += w0 * h0.z; acc.w += w0 * h0.w;
        }
        if (half) {
            *(float4*)&s_acc[wid][lane * 4] = acc;
            if ((lane & 7) == 0) s_sum[wid][h] = sumw;   // per-head partial sums
        }
        __syncthreads();
        if (!half) {
            float4 pa = *(const float4*)&s_acc[wid + 1][lane * 4];
            acc.x += pa.x; acc.y += pa.y; acc.z += pa.z; acc.w += pa.w;
            sumw += s_sum[wid + 1][h];
            float inv = 1.f / sumw;
            float4 bv = *(const float4*)&gat_b1[lane * 4];
            float4 o;
            float vx = acc.x * inv + bv.x; o.x = (vx > 0.f) ? vx : expm1f(vx);
            float vy = acc.y * inv + bv.y; o.y = (vy > 0.f) ? vy : expm1f(vy);
            float vz = acc.z * inv + bv.z; o.z = (vz > 0.f) ? vz : expm1f(vz);
            float vw = acc.w * inv + bv.w; o.w = (vw > 0.f) ? vw : expm1f(vw);
            *(float4*)&g_out1[n * HH + lane * 4] = o;
        }
    } else {
        int n = (b - GAT1_BLOCKS) * 8 + wid;
        if (n >= NN) return;
        int beg = g_off[n], end = g_off[n + 1];
        float nd = g_norm[n];
        float acc = 0.f;
        int p = beg;
        for (; p + 3 < end; p += 4) {
            int s0 = g_csr_src[p];
            int s1 = g_csr_src[p + 1];
            int s2 = g_csr_src[p + 2];
            int s3 = g_csr_src[p + 3];
            float c0 = g_norm[s0], c1 = g_norm[s1], c2 = g_norm[s2], c3 = g_norm[s3];
            float v0 = g_hg1[s0 * HID + lane];
            float v1 = g_hg1[s1 * HID + lane];
            float v2 = g_hg1[s2 * HID + lane];
            float v3 = g_hg1[s3 * HID + lane];
            acc += (c0 * v0 + c1 * v1) + (c2 * v2 + c3 * v3);
        }
        for (; p < end; p++) {
            int s0 = g_csr_src[p];
            acc += g_norm[s0] * g_hg1[s0 * HID + lane];
        }
        float v = acc * nd + gcn_b1[lane];
        g_go1[n * HID + lane] = (v > 0.f) ? v : 0.f;
    }
}

// ---------------- gemm_gcn2 alone: go1 @ Wgfold -> hg2 ----------------
__global__ void __launch_bounds__(256) k_gemm_gcn2() {
    __shared__ float As[BK][BM + 1];
    __shared__ float Bs[BK][BN];
    const float* A = g_go1;
    int tid = threadIdx.x;
    int tx = tid % 16, ty = tid / 16;
    int row0 = blockIdx.x * BM;
    float acc[4][4] = {};
    for (int k0 = 0; k0 < HID; k0 += BK) {
        {
            int r = tid >> 2;
            int c4 = (tid & 3) * 4;
            int gr = row0 + r;
            float4 v = (gr < NN) ? *(const float4*)&A[gr * HID + k0 + c4]
                                 : make_float4(0.f, 0.f, 0.f, 0.f);
            As[c4 + 0][r] = v.x;
            As[c4 + 1][r] = v.y;
            As[c4 + 2][r] = v.z;
            As[c4 + 3][r] = v.w;
        }
        for (int i = tid; i < BK * BN; i += 256) {
            int r = i / BN, c = i % BN;
            Bs[r][c] = (c < CC) ? g_Wgfold[(k0 + r) * CC + c] : 0.f;
        }
        __syncthreads();
#pragma unroll
        for (int k = 0; k < BK; k++) {
            float a[4], bb[4];
#pragma unroll
            for (int i = 0; i < 4; i++) a[i] = As[k][ty * 4 + i];
#pragma unroll
            for (int j = 0; j < 4; j++) bb[j] = Bs[k][tx * 4 + j];
#pragma unroll
            for (int i = 0; i < 4; i++)
#pragma unroll
                for (int j = 0; j < 4; j++) acc[i][j] += a[i] * bb[j];
        }
        __syncthreads();
    }
#pragma unroll
    for (int i = 0; i < 4; i++) {
        int gr = row0 + ty * 4 + i;
        if (gr >= NN) continue;
#pragma unroll
        for (int j = 0; j < 4; j++) {
            int gc = tx * 4 + j;
            if (gc < CC) g_hg2[gr * CC + gc] = acc[i][j];
        }
    }
}

// ---------------- merged: gemm_l2 ∥ gcn2_agg ----------------
__global__ void __launch_bounds__(256) k_l2_mix() {
    __shared__ float As[BK][BM + 1];
    __shared__ float Bs[BK][BN];
    int b = blockIdx.x;
    if (b < NB_ROWS) {
        // gemm_l2: out1 @ [W2fold | comb2]
        const float* A = g_out1;
        int tid = threadIdx.x;
        int tx = tid % 16, ty = tid / 16;
        int row0 = b * BM;
        float acc[4][4] = {};
        for (int k0 = 0; k0 < HH; k0 += BK) {
            {
                int r = tid >> 2;
                int c4 = (tid & 3) * 4;
                int gr = row0 + r;
                float4 v = (gr < NN) ? *(const float4*)&A[gr * HH + k0 + c4]
                                     : make_float4(0.f, 0.f, 0.f, 0.f);
                As[c4 + 0][r] = v.x;
                As[c4 + 1][r] = v.y;
                As[c4 + 2][r] = v.z;
                As[c4 + 3][r] = v.w;
            }
            for (int i = tid; i < BK * BN; i += 256) {
                int r = i / BN, c = i % BN;
                float v;
                if (c < CC) v = g_W2fold[(k0 + r) * CC + c];
                else if (c < CC + 2) v = g_comb2[(k0 + r) * 2 + (c - CC)];
                else v = 0.f;
                Bs[r][c] = v;
            }
            __syncthreads();
#pragma unroll
            for (int k = 0; k < BK; k++) {
                float a[4], bb[4];
#pragma unroll
                for (int i = 0; i < 4; i++) a[i] = As[k][ty * 4 + i];
#pragma unroll
                for (int j = 0; j < 4; j++) bb[j] = Bs[k][tx * 4 + j];
#pragma unroll
                for (int i = 0; i < 4; i++)
#pragma unroll
                    for (int j = 0; j < 4; j++) acc[i][j] += a[i] * bb[j];
            }
            __syncthreads();
        }
#pragma unroll
        for (int i = 0; i < 4; i++) {
            int gr = row0 + ty * 4 + i;
            if (gr >= NN) continue;
#pragma unroll
            for (int j = 0; j < 4; j++) {
                int gc = tx * 4 + j;
                if (gc < CC) g_h2[gr * CC + gc] = acc[i][j];
                else if (gc == CC) g_as2[gr] = acc[i][j];
                else if (gc == CC + 1) g_ad2[gr] = acc[i][j];
            }
        }
    } else {
        // gcn2_agg: warp per node
        int wid = threadIdx.x >> 5;
        int lane = threadIdx.x & 31;
        int n = (b - NB_ROWS) * 8 + wid;
        if (n >= NN) return;
        int beg = g_off[n], end = g_off[n + 1];
        float nd = g_norm[n];
        float acc1 = 0.f, acc2 = 0.f;
        int p = beg;
        for (; p + 3 < end; p += 4) {
            int s0 = g_csr_src[p];
            int s1 = g_csr_src[p + 1];
            int s2 = g_csr_src[p + 2];
            int s3 = g_csr_src[p + 3];
            float c0 = g_norm[s0], c1 = g_norm[s1], c2 = g_norm[s2], c3 = g_norm[s3];
            float a0 = g_hg2[s0 * CC + lane];
            float a1 = g_hg2[s1 * CC + lane];
            float a2 = g_hg2[s2 * CC + lane];
            float a3 = g_hg2[s3 * CC + lane];
            acc1 += (c0 * a0 + c1 * a1) + (c2 * a2 + c3 * a3);
            if (lane < CC - 32) {
                float b0 = g_hg2[s0 * CC + 32 + lane];
                float b1 = g_hg2[s1 * CC + 32 + lane];
                float b2 = g_hg2[s2 * CC + 32 + lane];
                float b3 = g_hg2[s3 * CC + 32 + lane];
                acc2 += (c0 * b0 + c1 * b1) + (c2 * b2 + c3 * b3);
            }
        }
        for (; p < end; p++) {
            int s0 = g_csr_src[p];
            float c0 = g_norm[s0];
            acc1 += c0 * g_hg2[s0 * CC + lane];
            if (lane < CC - 32) acc2 += c0 * g_hg2[s0 * CC + 32 + lane];
        }
        g_go2[n * CC + lane] = acc1 * nd + g_cvec[lane];
        if (lane < CC - 32) g_go2[n * CC + 32 + lane] = acc2 * nd + g_cvec[32 + lane];
    }
}

// ---------------- GAT2 aggregation + final out; tail blocks re-zero g_deg ------
__global__ void gat2_agg_out(float* __restrict__ out) {
    int b = blockIdx.x;
    if (b >= AGG_BLK) {
        int i = (b - AGG_BLK) * 256 + threadIdx.x;
        if (i < NN) g_deg[i] = 0;        // ready for next call (deterministic)
        return;
    }
    int wid = threadIdx.x >> 5;
    int lane = threadIdx.x & 31;
    int n = b * 8 + wid;
    if (n >= NN) return;
    int beg = g_off[n], end = g_off[n + 1];
    float ad = g_ad2[n];
    float acc1 = 0.f, acc2 = 0.f, sumw = 0.f;
    int p = beg;
    for (; p + 3 < end; p += 4) {
        int s0 = g_csr_src[p];
        int s1 = g_csr_src[p + 1];
        int s2 = g_csr_src[p + 2];
        int s3 = g_csr_src[p + 3];
        float l0 = g_as2[s0] + ad;
        float l1 = g_as2[s1] + ad;
        float l2 = g_as2[s2] + ad;
        float l3 = g_as2[s3] + ad;
        float a0 = g_h2[s0 * CC + lane];
        float a1 = g_h2[s1 * CC + lane];
        float a2 = g_h2[s2 * CC + lane];
        float a3 = g_h2[s3 * CC + lane];
        l0 = (l0 > 0.f) ? l0 : NEG_SLOPE * l0;
        l1 = (l1 > 0.f) ? l1 : NEG_SLOPE * l1;
        l2 = (l2 > 0.f) ? l2 : NEG_SLOPE * l2;
        l3 = (l3 > 0.f) ? l3 : NEG_SLOPE * l3;
        float w0 = __expf(l0), w1 = __expf(l1), w2 = __expf(l2), w3 = __expf(l3);
        sumw += (w0 + w1) + (w2 + w3);
        acc1 += (w0 * a0 + w1 * a1) + (w2 * a2 + w3 * a3);
        if (lane < CC - 32) {
            float b0 = g_h2[s0 * CC + 32 + lane];
            float b1 = g_h2[s1 * CC + 32 + lane];
            float b2 = g_h2[s2 * CC + 32 + lane];
            float b3 = g_h2[s3 * CC + 32 + lane];
            acc2 += (w0 * b0 + w1 * b1) + (w2 * b2 + w3 * b3);
        }
    }
    for (; p < end; p++) {
        int s0 = g_csr_src[p];
        float l0 = g_as2[s0] + ad;
        float a0 = g_h2[s0 * CC + lane];
        l0 = (l0 > 0.f) ? l0 : NEG_SLOPE * l0;
        float w0 = __expf(l0);
        sumw += w0;
        acc1 += w0 * a0;
        if (lane < CC - 32) acc2 += w0 * g_h2[s0 * CC + 32 + lane];
    }
    float inv = 1.f / sumw;
    out[n * CC + lane] = acc1 * inv + g_go2[n * CC + lane];
    if (lane < CC - 32) out[n * CC + 32 + lane] = acc2 * inv + g_go2[n * CC + 32 + lane];
}

// ---------------- launch ----------------
extern "C" void kernel_launch(void* const* d_in, const int* in_sizes, int n_in,
                              void* d_out, int out_size) {
    const float* x      = (const float*)d_in[0];
    const void*  eidx   = d_in[1];
    const float* gat_W1 = (const float*)d_in[2];
    const float* att_s1 = (const float*)d_in[3];
    const float* att_d1 = (const float*)d_in[4];
    const float* gat_b1 = (const float*)d_in[5];
    const float* gat_W2 = (const float*)d_in[6];
    const float* att_s2 = (const float*)d_in[7];
    const float* att_d2 = (const float*)d_in[8];
    const float* gat_b2 = (const float*)d_in[9];
    const float* gcn_W1 = (const float*)d_in[10];
    const float* gcn_b1 = (const float*)d_in[11];
    const float* gcn_W2 = (const float*)d_in[12];
    const float* gcn_b2 = (const float*)d_in[13];
    const float* lin_W  = (const float*)d_in[14];
    const float* lin_b  = (const float*)d_in[15];
    const float* wc     = (const float*)d_in[16];
    const float* wt     = (const float*)d_in[17];
    float*       out    = (float*)d_out;

    // 1) dtype detect (g_deg already zero: module load or previous call's tail)
    k_detect<<<256, 256>>>((const unsigned int*)eidx);
    // 2) count degrees ∥ precompute folds
    k_count_pre<<<CNT_BLOCKS + PRE_BLOCKS, 256>>>(eidx, gat_W1, att_s1, att_d1,
                                                  gat_W2, att_s2, att_d2,
                                                  gcn_W1, gcn_W2, gat_b2, gcn_b2,
                                                  lin_W, lin_b, wc, wt);
    // 3-4) scan (phase2 folded into phase3)
    scan_phase1<<<SCAN_BLOCKS, SCAN_CHUNK>>>();
    scan_phase3<<<(NN + 255) / 256, 256>>>();
    // 5) fused projection ∥ CSR scatter
    k_proj_scatter<<<PROJ_BLOCKS + SCAT_BLOCKS, 256>>>(x, eidx);
    // 6) GAT1 ∥ GCN1
    k_layer1<<<GAT1_BLOCKS + GCN1_BLOCKS, 256>>>(gat_b1, gcn_b1);
    // 7) gemm_gcn2
    k_gemm_gcn2<<<NB_ROWS, 256>>>();
    // 8) gemm_l2 ∥ gcn2_agg
    k_l2_mix<<<NB_ROWS + AGG_BLK, 256>>>();
    // 9) GAT2 aggregation + final out; tail re-zeroes g_deg for next call
    gat2_agg_out<<<AGG_BLK + ZI_BLOCKS, 256>>>(out);
}

// round 16
// speedup vs baseline: 2.1627x; 1.0507x over previous
#include <cuda_runtime.h>
#include <cuda_bf16.h>
#include <math.h>

// Problem constants (match reference)
#define NN     50000
#define EE     800000
#define EP     850000     // edges + self loops
#define F_IN   128
#define HID    32
#define HEADS  4
#define HH     128        // HEADS*HID
#define CC     40
#define NEG_SLOPE 0.2f

#define SCAN_CHUNK 1024
#define SCAN_BLOCKS ((NN + SCAN_CHUNK - 1) / SCAN_CHUNK)   // 49

#define NCAT (HH + HID + 8)   // 168: [W1 | Wg | comb1]

#define BM 64
#define BN 64
#define BK 16
#define NB_ROWS ((NN + BM - 1) / BM)          // 782
// Proj uses a 128-row tile with 8x4 register blocking
#define PBM 128
#define PROJ_ROWS ((NN + PBM - 1) / PBM)      // 391
#define PROJ_COLS ((NCAT + BN - 1) / BN)      // 3
#define PROJ_BLOCKS (PROJ_COLS * PROJ_ROWS)   // 1173
#define SCAT_BLOCKS ((EP + 255) / 256)        // 3321
#define GAT1_BLOCKS (NN / 4)                  // 12500
#define GCN1_BLOCKS ((NN + 7) / 8)            // 6250
#define CNT_BLOCKS ((EP + 255) / 256)         // 3321
#define PRE_TOT (F_IN * NCAT + 256 + HH * CC + HID * CC + CC)
#define PRE_BLOCKS ((PRE_TOT + 255) / 256)    // ~93
#define ZI_BLOCKS ((NN + 255) / 256)          // 196
#define AGG_BLK ((NN + 7) / 8)                // 6250 (8 warps/block)

// ---------------- scratch (device globals; no allocation allowed) ----------------
// g_flag32: NEVER zeroed; set-only (idempotent) => deterministic across replays.
// g_deg: zero at module load; re-zeroed by gat2_agg_out tail blocks each call.
__device__ int   g_flag32;
__device__ int   g_deg[NN];
__device__ int   g_off[NN + 1];
__device__ int   g_cursor[NN];
__device__ int   g_bsum[SCAN_BLOCKS];  // raw per-chunk totals
__device__ int   g_csr_src[EP];

__device__ float g_Bcat[F_IN * NCAT];
__device__ float g_comb2[F_IN * 2];
__device__ float g_W2fold[HH * CC];
__device__ float g_Wgfold[HID * CC];
__device__ float g_cvec[CC];

__device__ float g_h1[NN * HH];
__device__ float g_as1[NN * HEADS];
__device__ float g_ad1[NN * HEADS];
__device__ float g_out1[NN * HH];
__device__ float g_h2[NN * CC];
__device__ float g_as2[NN];
__device__ float g_ad2[NN];
__device__ float g_hg1[NN * HID];
__device__ float g_norm[NN];
__device__ float g_go1[NN * HID];
__device__ float g_hg2[NN * CC];
__device__ float g_go2[NN * CC];

__device__ __forceinline__ int load_node(const void* eidx, long long idx) {
    int v = g_flag32 ? ((const int*)eidx)[idx]
                     : (int)((const long long*)eidx)[idx];
    return min(max(v, 0), NN - 1);
}

// ---------------- dtype detect (sampler only; flag is set-only) ----------------
__global__ void k_detect(const unsigned int* __restrict__ raw) {
    int i = blockIdx.x * 256 + threadIdx.x;   // 65536 samples
    unsigned v = raw[2 * i + 1];
    if (v != 0u) g_flag32 = 1;
}

// ---------------- merged: count degrees + precompute folds ----------------
__global__ void k_count_pre(const void* __restrict__ eidx,
                            const float* __restrict__ gat_W1,
                            const float* __restrict__ att_s1,
                            const float* __restrict__ att_d1,
                            const float* __restrict__ gat_W2,
                            const float* __restrict__ att_s2,
                            const float* __restrict__ att_d2,
                            const float* __restrict__ gcn_W1,
                            const float* __restrict__ gcn_W2,
                            const float* __restrict__ gat_b2,
                            const float* __restrict__ gcn_b2,
                            const float* __restrict__ lin_W,
                            const float* __restrict__ lin_b,
                            const float* __restrict__ wc_p,
                            const float* __restrict__ wt_p) {
    int b = blockIdx.x;
    if (b < CNT_BLOCKS) {
        int e = b * 256 + threadIdx.x;
        if (e >= EP) return;
        int d = (e < EE) ? load_node(eidx, (long long)EE + e) : (e - EE);
        atomicAdd(&g_deg[d], 1);
    } else {
        int t = (b - CNT_BLOCKS) * 256 + threadIdx.x;
        float wc = *wc_p, wt = *wt_p;
        const int N_BCAT = F_IN * NCAT;
        if (t < N_BCAT) {
            int f = t / NCAT, c = t % NCAT;
            float v;
            if (c < HH) v = gat_W1[f * HH + c];
            else if (c < HH + HID) v = gcn_W1[f * HID + (c - HH)];
            else {
                int j = c - HH - HID;
                int h = j & 3;
                const float* av = (j < 4) ? &att_s1[h * HID] : &att_d1[h * HID];
                const float* wr = &gat_W1[f * HH + h * HID];
                float s = 0.f;
#pragma unroll
                for (int d = 0; d < HID; d++) s += wr[d] * av[d];
                v = s;
            }
            g_Bcat[t] = v;
        } else if (t < N_BCAT + 256) {
            int u = t - N_BCAT, f = u >> 1;
            const float* av = (u & 1) ? att_d2 : att_s2;
            const float* wr = &gat_W2[f * CC];
            float s = 0.f;
#pragma unroll
            for (int c = 0; c < CC; c++) s += wr[c] * av[c];
            g_comb2[f * 2 + (u & 1)] = s;
        } else if (t < N_BCAT + 256 + HH * CC) {
            int u = t - N_BCAT - 256;
            int f = u / CC, c = u % CC;
            float s = 0.f;
#pragma unroll
            for (int j = 0; j < CC; j++) s += gat_W2[f * CC + j] * lin_W[(CC + j) * CC + c];
            g_W2fold[u] = s * wt;
        } else if (t < N_BCAT + 256 + HH * CC + HID * CC) {
            int u = t - N_BCAT - 256 - HH * CC;
            int f = u / CC, c = u % CC;
            float s = 0.f;
#pragma unroll
            for (int j = 0; j < CC; j++) s += gcn_W2[f * CC + j] * lin_W[j * CC + c];
            g_Wgfold[u] = s * wc;
        } else if (t < N_BCAT + 256 + HH * CC + HID * CC + CC) {
            int c = t - N_BCAT - 256 - HH * CC - HID * CC;
            float s = lin_b[c];
#pragma unroll
            for (int j = 0; j < CC; j++) {
                s += wc * gcn_b2[j] * lin_W[j * CC + c];
                s += wt * gat_b2[j] * lin_W[(CC + j) * CC + c];
            }
            g_cvec[c] = s;
        }
    }
}

// ---------------- scan phase 1: per-chunk exclusive scan + raw chunk totals -----
__global__ void scan_phase1() {
    __shared__ int warp_sums[32];
    int b = blockIdx.x;
    int i = b * SCAN_CHUNK + threadIdx.x;
    int lane = threadIdx.x & 31, wid = threadIdx.x >> 5;
    int v = (i < NN) ? g_deg[i] : 0;
    int x = v;
#pragma unroll
    for (int s = 1; s < 32; s <<= 1) {
        int t = __shfl_up_sync(0xffffffff, x, s);
        if (lane >= s) x += t;
    }
    if (lane == 31) warp_sums[wid] = x;
    __syncthreads();
    if (wid == 0) {
        int ws = warp_sums[lane];
#pragma unroll
        for (int s = 1; s < 32; s <<= 1) {
            int t = __shfl_up_sync(0xffffffff, ws, s);
            if (lane >= s) ws += t;
        }
        warp_sums[lane] = ws;
    }
    __syncthreads();
    int prefix = (wid > 0) ? warp_sums[wid - 1] : 0;
    int excl = prefix + x - v;
    if (i < NN) g_off[i] = excl;
    if (threadIdx.x == SCAN_CHUNK - 1) g_bsum[b] = prefix + x;   // raw total
}

// ---------------- scan phase 3: inline chunk-prefix via parallel reduction ------
// 256 threads/block => chunk = blockIdx.x >> 2 is block-uniform.
__global__ void scan_phase3() {
    __shared__ int sred[64];
    int chunk = blockIdx.x >> 2;     // <= 48
    int t = threadIdx.x;
    if (t < 64) sred[t] = (t < chunk) ? g_bsum[t] : 0;   // parallel loads
    __syncthreads();
    if (t < 32) sred[t] += sred[t + 32];
    __syncwarp();
    if (t < 16) sred[t] += sred[t + 16];
    __syncwarp();
    if (t < 8) sred[t] += sred[t + 8];
    __syncwarp();
    if (t < 4) sred[t] += sred[t + 4];
    __syncwarp();
    if (t < 2) sred[t] += sred[t + 2];
    __syncwarp();
    if (t < 1) sred[t] += sred[t + 1];
    __syncthreads();
    int prefix = sred[0];
    int i = blockIdx.x * 256 + t;
    if (i == 0) g_off[NN] = EP;
    if (i >= NN) return;
    int o = g_off[i] + prefix;
    g_off[i] = o;
    g_cursor[i] = o;
    g_norm[i] = rsqrtf((float)g_deg[i]);
}

// ---------------- merged: fused projection (128x64, 8x4) + CSR scatter ----------
__global__ void __launch_bounds__(256) k_proj_scatter(const float* __restrict__ x,
                                                      const void* __restrict__ eidx) {
    __shared__ float As[BK][PBM + 4];   // +4 keeps 16B alignment, shifts banks
    __shared__ float Bs[BK][BN];
    int b = blockIdx.x;
    if (b >= PROJ_BLOCKS) {
        int e = (b - PROJ_BLOCKS) * 256 + threadIdx.x;
        if (e >= EP) return;
        int s, d;
        if (e < EE) {
            s = load_node(eidx, e);
            d = load_node(eidx, (long long)EE + e);
        } else {
            s = d = e - EE;
        }
        int pos = atomicAdd(&g_cursor[d], 1);
        g_csr_src[pos] = s;
        return;
    }
    int tid = threadIdx.x;
    int tx = tid % 16, ty = tid / 16;     // ty: 0..15 -> 8-row group
    int row0 = (b / PROJ_COLS) * PBM;
    int col0 = (b % PROJ_COLS) * BN;
    float acc[8][4] = {};
    for (int k0 = 0; k0 < F_IN; k0 += BK) {
        // A tile: 128 rows x 16 k. Each thread: one row, 8 consecutive k (2 float4).
        {
            int r = tid >> 1;                 // 0..127
            int kq = (tid & 1) * 8;           // 0 or 8
            int gr = row0 + r;
            float4 v0, v1;
            if (gr < NN) {
                v0 = *(const float4*)&x[gr * F_IN + k0 + kq];
                v1 = *(const float4*)&x[gr * F_IN + k0 + kq + 4];
            } else {
                v0 = make_float4(0.f, 0.f, 0.f, 0.f);
                v1 = v0;
            }
            As[kq + 0][r] = v0.x; As[kq + 1][r] = v0.y;
            As[kq + 2][r] = v0.z; As[kq + 3][r] = v0.w;
            As[kq + 4][r] = v1.x; As[kq + 5][r] = v1.y;
            As[kq + 6][r] = v1.z; As[kq + 7][r] = v1.w;
        }
        // B tile: 16 rows x 64 cols. One float4 per thread.
        {
            int r = tid >> 4;
            int c4 = (tid & 15) * 4;
            int gc = col0 + c4;
            float4 v = (gc + 3 < NCAT) ? *(const float4*)&g_Bcat[(k0 + r) * NCAT + gc]
                                       : make_float4(0.f, 0.f, 0.f, 0.f);
            *(float4*)&Bs[r][c4] = v;
        }
        __syncthreads();
#pragma unroll
        for (int k = 0; k < BK; k++) {
            float a[8], bb[4];
#pragma unroll
            for (int i = 0; i < 8; i++) a[i] = As[k][ty * 8 + i];
#pragma unroll
            for (int j = 0; j < 4; j++) bb[j] = Bs[k][tx * 4 + j];
#pragma unroll
            for (int i = 0; i < 8; i++)
#pragma unroll
                for (int j = 0; j < 4; j++) acc[i][j] += a[i] * bb[j];
        }
        __syncthreads();
    }
#pragma unroll
    for (int i = 0; i < 8; i++) {
        int gr = row0 + ty * 8 + i;
        if (gr >= NN) continue;
#pragma unroll
        for (int j = 0; j < 4; j++) {
            int gc = col0 + tx * 4 + j;
            if (gc < HH) g_h1[gr * HH + gc] = acc[i][j];
            else if (gc < HH + HID) g_hg1[gr * HID + (gc - HH)] = acc[i][j];
            else if (gc < HH + HID + 4) g_as1[gr * 4 + (gc - HH - HID)] = acc[i][j];
            else if (gc < NCAT) g_ad1[gr * 4 + (gc - HH - HID - 4)] = acc[i][j];
        }
    }
}

// ---------------- merged layer-1: GAT1 (2-warp split) + GCN1 ----------------
__global__ void __launch_bounds__(256) k_layer1(const float* __restrict__ gat_b1,
                                                const float* __restrict__ gcn_b1) {
    __shared__ float s_acc[8][HH];
    __shared__ float s_sum[8][4];
    int b = blockIdx.x;
    int wid = threadIdx.x >> 5;
    int lane = threadIdx.x & 31;
    if (b < GAT1_BLOCKS) {
        int n = b * 4 + (wid >> 1);
        int half = wid & 1;
        int beg = g_off[n], end = g_off[n + 1];
        int mid = beg + ((end - beg) >> 1);
        int lo = half ? mid : beg;
        int hi = half ? end : mid;
        int h = lane >> 3;
        float ad = g_ad1[n * 4 + h];
        float4 acc = {0.f, 0.f, 0.f, 0.f};
        float sumw = 0.f;
        int p = lo;
        for (; p + 3 < hi; p += 4) {
            int s0 = g_csr_src[p];
            int s1 = g_csr_src[p + 1];
            int s2 = g_csr_src[p + 2];
            int s3 = g_csr_src[p + 3];
            float l0 = g_as1[s0 * 4 + h] + ad;
            float l1 = g_as1[s1 * 4 + h] + ad;
            float l2 = g_as1[s2 * 4 + h] + ad;
            float l3 = g_as1[s3 * 4 + h] + ad;
            float4 h0 = *(const float4*)&g_h1[s0 * HH + lane * 4];
            float4 h1 = *(const float4*)&g_h1[s1 * HH + lane * 4];
            float4 h2 = *(const float4*)&g_h1[s2 * HH + lane * 4];
            float4 h3 = *(const float4*)&g_h1[s3 * HH + lane * 4];
            l0 = (l0 > 0.f) ? l0 : NEG_SLOPE * l0;
            l1 = (l1 > 0.f) ? l1 : NEG_SLOPE * l1;
            l2 = (l2 > 0.f) ? l2 : NEG_SLOPE * l2;
            l3 = (l3 > 0.f) ? l3 : NEG_SLOPE * l3;
            float w0 = __expf(l0), w1 = __expf(l1), w2 = __expf(l2), w3 = __expf(l3);
            sumw += (w0 + w1) + (w2 + w3);
            acc.x += w0 * h0.x + w1 * h1.x + w2 * h2.x + w3 * h3.x;
            acc.y += w0 * h0.y + w1 * h1.y + w2 * h2.y + w3 * h3.y;
            acc.z += w0 * h0.z + w1 * h1.z + w2 * h2.z + w3 * h3.z;
            acc.w += w0 * h0.w + w1 * h1.w + w2 * h2.w + w3 * h3.w;
        }
        for (; p < hi; p++) {
            int s0 = g_csr_src[p];
            float l0 = g_as1[s0 * 4 + h] + ad;
            float4 h0 = *(const float4*)&g_h1[s0 * HH + lane * 4];
            l0 = (l0 > 0.f) ? l0 : NEG_SLOPE * l0;
            float w0 = __expf(l0);
            sumw += w0;
            acc.x += w0 * h0.x; acc.y += w0 * h0.y; acc.z += w0 * h0.z; acc.w += w0 * h0.w;
        }
        if (half) {
            *(float4*)&s_acc[wid][lane * 4] = acc;
            if ((lane & 7) == 0) s_sum[wid][h] = sumw;   // per-head partial sums
        }
        __syncthreads();
        if (!half) {
            float4 pa = *(const float4*)&s_acc[wid + 1][lane * 4];
            acc.x += pa.x; acc.y += pa.y; acc.z += pa.z; acc.w += pa.w;
            sumw += s_sum[wid + 1][h];
            float inv = 1.f / sumw;
            float4 bv = *(const float4*)&gat_b1[lane * 4];
            float4 o;
            float vx = acc.x * inv + bv.x; o.x = (vx > 0.f) ? vx : expm1f(vx);
            float vy = acc.y * inv + bv.y; o.y = (vy > 0.f) ? vy : expm1f(vy);
            float vz = acc.z * inv + bv.z; o.z = (vz > 0.f) ? vz : expm1f(vz);
            float vw = acc.w * inv + bv.w; o.w = (vw > 0.f) ? vw : expm1f(vw);
            *(float4*)&g_out1[n * HH + lane * 4] = o;
        }
    } else {
        int n = (b - GAT1_BLOCKS) * 8 + wid;
        if (n >= NN) return;
        int beg = g_off[n], end = g_off[n + 1];
        float nd = g_norm[n];
        float acc = 0.f;
        int p = beg;
        for (; p + 3 < end; p += 4) {
            int s0 = g_csr_src[p];
            int s1 = g_csr_src[p + 1];
            int s2 = g_csr_src[p + 2];
            int s3 = g_csr_src[p + 3];
            float c0 = g_norm[s0], c1 = g_norm[s1], c2 = g_norm[s2], c3 = g_norm[s3];
            float v0 = g_hg1[s0 * HID + lane];
            float v1 = g_hg1[s1 * HID + lane];
            float v2 = g_hg1[s2 * HID + lane];
            float v3 = g_hg1[s3 * HID + lane];
            acc += (c0 * v0 + c1 * v1) + (c2 * v2 + c3 * v3);
        }
        for (; p < end; p++) {
            int s0 = g_csr_src[p];
            acc += g_norm[s0] * g_hg1[s0 * HID + lane];
        }
        float v = acc * nd + gcn_b1[lane];
        g_go1[n * HID + lane] = (v > 0.f) ? v : 0.f;
    }
}

// ---------------- gemm_gcn2 alone: go1 @ Wgfold -> hg2 ----------------
__global__ void __launch_bounds__(256) k_gemm_gcn2() {
    __shared__ float As[BK][BM + 1];
    __shared__ float Bs[BK][BN];
    const float* A = g_go1;
    int tid = threadIdx.x;
    int tx = tid % 16, ty = tid / 16;
    int row0 = blockIdx.x * BM;
    float acc[4][4] = {};
    for (int k0 = 0; k0 < HID; k0 += BK) {
        {
            int r = tid >> 2;
            int c4 = (tid & 3) * 4;
            int gr = row0 + r;
            float4 v = (gr < NN) ? *(const float4*)&A[gr * HID + k0 + c4]
                                 : make_float4(0.f, 0.f, 0.f, 0.f);
            As[c4 + 0][r] = v.x;
            As[c4 + 1][r] = v.y;
            As[c4 + 2][r] = v.z;
            As[c4 + 3][r] = v.w;
        }
        for (int i = tid; i < BK * BN; i += 256) {
            int r = i / BN, c = i % BN;
            Bs[r][c] = (c < CC) ? g_Wgfold[(k0 + r) * CC + c] : 0.f;
        }
        __syncthreads();
#pragma unroll
        for (int k = 0; k < BK; k++) {
            float a[4], bb[4];
#pragma unroll
            for (int i = 0; i < 4; i++) a[i] = As[k][ty * 4 + i];
#pragma unroll
            for (int j = 0; j < 4; j++) bb[j] = Bs[k][tx * 4 + j];
#pragma unroll
            for (int i = 0; i < 4; i++)
#pragma unroll
                for (int j = 0; j < 4; j++) acc[i][j] += a[i] * bb[j];
        }
        __syncthreads();
    }
#pragma unroll
    for (int i = 0; i < 4; i++) {
        int gr = row0 + ty * 4 + i;
        if (gr >= NN) continue;
#pragma unroll
        for (int j = 0; j < 4; j++) {
            int gc = tx * 4 + j;
            if (gc < CC) g_hg2[gr * CC + gc] = acc[i][j];
        }
    }
}

// ---------------- merged: gemm_l2 ∥ gcn2_agg ----------------
__global__ void __launch_bounds__(256) k_l2_mix() {
    __shared__ float As[BK][BM + 1];
    __shared__ float Bs[BK][BN];
    int b = blockIdx.x;
    if (b < NB_ROWS) {
        const float* A = g_out1;
        int tid = threadIdx.x;
        int tx = tid % 16, ty = tid / 16;
        int row0 = b * BM;
        float acc[4][4] = {};
        for (int k0 = 0; k0 < HH; k0 += BK) {
            {
                int r = tid >> 2;
                int c4 = (tid & 3) * 4;
                int gr = row0 + r;
                float4 v = (gr < NN) ? *(const float4*)&A[gr * HH + k0 + c4]
                                     : make_float4(0.f, 0.f, 0.f, 0.f);
                As[c4 + 0][r] = v.x;
                As[c4 + 1][r] = v.y;
                As[c4 + 2][r] = v.z;
                As[c4 + 3][r] = v.w;
            }
            for (int i = tid; i < BK * BN; i += 256) {
                int r = i / BN, c = i % BN;
                float v;
                if (c < CC) v = g_W2fold[(k0 + r) * CC + c];
                else if (c < CC + 2) v = g_comb2[(k0 + r) * 2 + (c - CC)];
                else v = 0.f;
                Bs[r][c] = v;
            }
            __syncthreads();
#pragma unroll
            for (int k = 0; k < BK; k++) {
                float a[4], bb[4];
#pragma unroll
                for (int i = 0; i < 4; i++) a[i] = As[k][ty * 4 + i];
#pragma unroll
                for (int j = 0; j < 4; j++) bb[j] = Bs[k][tx * 4 + j];
#pragma unroll
                for (int i = 0; i < 4; i++)
#pragma unroll
                    for (int j = 0; j < 4; j++) acc[i][j] += a[i] * bb[j];
            }
            __syncthreads();
        }
#pragma unroll
        for (int i = 0; i < 4; i++) {
            int gr = row0 + ty * 4 + i;
            if (gr >= NN) continue;
#pragma unroll
            for (int j = 0; j < 4; j++) {
                int gc = tx * 4 + j;
                if (gc < CC) g_h2[gr * CC + gc] = acc[i][j];
                else if (gc == CC) g_as2[gr] = acc[i][j];
                else if (gc == CC + 1) g_ad2[gr] = acc[i][j];
            }
        }
    } else {
        int wid = threadIdx.x >> 5;
        int lane = threadIdx.x & 31;
        int n = (b - NB_ROWS) * 8 + wid;
        if (n >= NN) return;
        int beg = g_off[n], end = g_off[n + 1];
        float nd = g_norm[n];
        float acc1 = 0.f, acc2 = 0.f;
        int p = beg;
        for (; p + 3 < end; p += 4) {
            int s0 = g_csr_src[p];
            int s1 = g_csr_src[p + 1];
            int s2 = g_csr_src[p + 2];
            int s3 = g_csr_src[p + 3];
            float c0 = g_norm[s0], c1 = g_norm[s1], c2 = g_norm[s2], c3 = g_norm[s3];
            float a0 = g_hg2[s0 * CC + lane];
            float a1 = g_hg2[s1 * CC + lane];
            float a2 = g_hg2[s2 * CC + lane];
            float a3 = g_hg2[s3 * CC + lane];
            acc1 += (c0 * a0 + c1 * a1) + (c2 * a2 + c3 * a3);
            if (lane < CC - 32) {
                float b0 = g_hg2[s0 * CC + 32 + lane];
                float b1 = g_hg2[s1 * CC + 32 + lane];
                float b2 = g_hg2[s2 * CC + 32 + lane];
                float b3 = g_hg2[s3 * CC + 32 + lane];
                acc2 += (c0 * b0 + c1 * b1) + (c2 * b2 + c3 * b3);
            }
        }
        for (; p < end; p++) {
            int s0 = g_csr_src[p];
            float c0 = g_norm[s0];
            acc1 += c0 * g_hg2[s0 * CC + lane];
            if (lane < CC - 32) acc2 += c0 * g_hg2[s0 * CC + 32 + lane];
        }
        g_go2[n * CC + lane] = acc1 * nd + g_cvec[lane];
        if (lane < CC - 32) g_go2[n * CC + 32 + lane] = acc2 * nd + g_cvec[32 + lane];
    }
}

// ---------------- GAT2 aggregation + final out; tail blocks re-zero g_deg ------
__global__ void gat2_agg_out(float* __restrict__ out) {
    int b = blockIdx.x;
    if (b >= AGG_BLK) {
        int i = (b - AGG_BLK) * 256 + threadIdx.x;
        if (i < NN) g_deg[i] = 0;        // ready for next call (deterministic)
        return;
    }
    int wid = threadIdx.x >> 5;
    int lane = threadIdx.x & 31;
    int n = b * 8 + wid;
    if (n >= NN) return;
    int beg = g_off[n], end = g_off[n + 1];
    float ad = g_ad2[n];
    float acc1 = 0.f, acc2 = 0.f, sumw = 0.f;
    int p = beg;
    for (; p + 3 < end; p += 4) {
        int s0 = g_csr_src[p];
        int s1 = g_csr_src[p + 1];
        int s2 = g_csr_src[p + 2];
        int s3 = g_csr_src[p + 3];
        float l0 = g_as2[s0] + ad;
        float l1 = g_as2[s1] + ad;
        float l2 = g_as2[s2] + ad;
        float l3 = g_as2[s3] + ad;
        float a0 = g_h2[s0 * CC + lane];
        float a1 = g_h2[s1 * CC + lane];
        float a2 = g_h2[s2 * CC + lane];
        float a3 = g_h2[s3 * CC + lane];
        l0 = (l0 > 0.f) ? l0 : NEG_SLOPE * l0;
        l1 = (l1 > 0.f) ? l1 : NEG_SLOPE * l1;
        l2 = (l2 > 0.f) ? l2 : NEG_SLOPE * l2;
        l3 = (l3 > 0.f) ? l3 : NEG_SLOPE * l3;
        float w0 = __expf(l0), w1 = __expf(l1), w2 = __expf(l2), w3 = __expf(l3);
        sumw += (w0 + w1) + (w2 + w3);
        acc1 += (w0 * a0 + w1 * a1) + (w2 * a2 + w3 * a3);
        if (lane < CC - 32) {
            float b0 = g_h2[s0 * CC + 32 + lane];
            float b1 = g_h2[s1 * CC + 32 + lane];
            float b2 = g_h2[s2 * CC + 32 + lane];
            float b3 = g_h2[s3 * CC + 32 + lane];
            acc2 += (w0 * b0 + w1 * b1) + (w2 * b2 + w3 * b3);
        }
    }
    for (; p < end; p++) {
        int s0 = g_csr_src[p];
        float l0 = g_as2[s0] + ad;
        float a0 = g_h2[s0 * CC + lane];
        l0 = (l0 > 0.f) ? l0 : NEG_SLOPE * l0;
        float w0 = __expf(l0);
        sumw += w0;
        acc1 += w0 * a0;
        if (lane < CC - 32) acc2 += w0 * g_h2[s0 * CC + 32 + lane];
    }
    float inv = 1.f / sumw;
    out[n * CC + lane] = acc1 * inv + g_go2[n * CC + lane];
    if (lane < CC - 32) out[n * CC + 32 + lane] = acc2 * inv + g_go2[n * CC + 32 + lane];
}

// ---------------- launch ----------------
extern "C" void kernel_launch(void* const* d_in, const int* in_sizes, int n_in,
                              void* d_out, int out_size) {
    const float* x      = (const float*)d_in[0];
    const void*  eidx   = d_in[1];
    const float* gat_W1 = (const float*)d_in[2];
    const float* att_s1 = (const float*)d_in[3];
    const float* att_d1 = (const float*)d_in[4];
    const float* gat_b1 = (const float*)d_in[5];
    const float* gat_W2 = (const float*)d_in[6];
    const float* att_s2 = (const float*)d_in[7];
    const float* att_d2 = (const float*)d_in[8];
    const float* gat_b2 = (const float*)d_in[9];
    const float* gcn_W1 = (const float*)d_in[10];
    const float* gcn_b1 = (const float*)d_in[11];
    const float* gcn_W2 = (const float*)d_in[12];
    const float* gcn_b2 = (const float*)d_in[13];
    const float* lin_W  = (const float*)d_in[14];
    const float* lin_b  = (const float*)d_in[15];
    const float* wc     = (const float*)d_in[16];
    const float* wt     = (const float*)d_in[17];
    float*       out    = (float*)d_out;

    // 1) dtype detect (g_deg already zero: module load or previous call's tail)
    k_detect<<<256, 256>>>((const unsigned int*)eidx);
    // 2) count degrees ∥ precompute folds
    k_count_pre<<<CNT_BLOCKS + PRE_BLOCKS, 256>>>(eidx, gat_W1, att_s1, att_d1,
                                                  gat_W2, att_s2, att_d2,
                                                  gcn_W1, gcn_W2, gat_b2, gcn_b2,
                                                  lin_W, lin_b, wc, wt);
    // 3-4) scan (phase2 folded into phase3; parallel chunk-prefix)
    scan_phase1<<<SCAN_BLOCKS, SCAN_CHUNK>>>();
    scan_phase3<<<(NN + 255) / 256, 256>>>();
    // 5) fused projection (128x64, 8x4) ∥ CSR scatter
    k_proj_scatter<<<PROJ_BLOCKS + SCAT_BLOCKS, 256>>>(x, eidx);
    // 6) GAT1 ∥ GCN1
    k_layer1<<<GAT1_BLOCKS + GCN1_BLOCKS, 256>>>(gat_b1, gcn_b1);
    // 7) gemm_gcn2
    k_gemm_gcn2<<<NB_ROWS, 256>>>();
    // 8) gemm_l2 ∥ gcn2_agg
    k_l2_mix<<<NB_ROWS + AGG_BLK, 256>>>();
    // 9) GAT2 aggregation + final out; tail re-zeroes g_deg for next call
    gat2_agg_out<<<AGG_BLK + ZI_BLOCKS, 256>>>(out);
}

// round 17
// speedup vs baseline: 2.1822x; 1.0090x over previous
#include <cuda_runtime.h>
#include <cuda_bf16.h>
#include <cuda_fp16.h>
#include <math.h>

// Problem constants (match reference)
#define NN     50000
#define EE     800000
#define EP     850000     // edges + self loops
#define F_IN   128
#define HID    32
#define HEADS  4
#define HH     128        // HEADS*HID
#define CC     40
#define NEG_SLOPE 0.2f

#define SCAN_CHUNK 1024
#define SCAN_BLOCKS ((NN + SCAN_CHUNK - 1) / SCAN_CHUNK)   // 49

#define NCAT (HH + HID + 8)   // 168: [W1 | Wg | comb1]

#define BM 64
#define BN 64
#define BK 16
#define NB_ROWS ((NN + BM - 1) / BM)          // 782
#define PBM 128
#define PROJ_ROWS ((NN + PBM - 1) / PBM)      // 391
#define PROJ_COLS ((NCAT + BN - 1) / BN)      // 3
#define PROJ_BLOCKS (PROJ_COLS * PROJ_ROWS)   // 1173
#define SCAT_BLOCKS ((EP + 255) / 256)        // 3321
#define GAT1_BLOCKS (NN / 4)                  // 12500
#define GCN1_BLOCKS ((NN + 7) / 8)            // 6250
#define CNT_BLOCKS ((EP + 255) / 256)         // 3321
#define PRE_TOT (F_IN * NCAT + 256 + HH * CC + HID * CC + CC)
#define PRE_BLOCKS ((PRE_TOT + 255) / 256)    // ~93
#define ZI_BLOCKS ((NN + 255) / 256)          // 196
#define AGG_BLK ((NN + 7) / 8)                // 6250 (8 warps/block)

// ---------------- scratch (device globals; no allocation allowed) ----------------
// g_flag32: NEVER zeroed; set-only (idempotent) => deterministic across replays.
// g_deg: zero at module load; re-zeroed by gat2_agg_out tail blocks each call.
__device__ int   g_flag32;
__device__ int   g_deg[NN];
__device__ int   g_off[NN + 1];
__device__ int   g_cursor[NN];
__device__ int   g_bsum[SCAN_BLOCKS];
__device__ int   g_csr_src[EP];

__device__ float g_Bcat[F_IN * NCAT];
__device__ float g_comb2[F_IN * 2];
__device__ float g_W2fold[HH * CC];
__device__ float g_Wgfold[HID * CC];
__device__ float g_cvec[CC];

// Layer-1 gather operands in fp16 (single consumer each; softmax weights stay fp32)
__device__ __half g_h1h[NN * HH];
__device__ __half g_hg1h[NN * HID];

__device__ float g_as1[NN * HEADS];
__device__ float g_ad1[NN * HEADS];
__device__ float g_out1[NN * HH];
__device__ float g_h2[NN * CC];
__device__ float g_as2[NN];
__device__ float g_ad2[NN];
__device__ float g_norm[NN];
__device__ float g_go1[NN * HID];
__device__ float g_hg2[NN * CC];
__device__ float g_go2[NN * CC];

__device__ __forceinline__ int load_node(const void* eidx, long long idx) {
    int v = g_flag32 ? ((const int*)eidx)[idx]
                     : (int)((const long long*)eidx)[idx];
    return min(max(v, 0), NN - 1);
}

// ---------------- dtype detect (sampler only; flag is set-only) ----------------
__global__ void k_detect(const unsigned int* __restrict__ raw) {
    int i = blockIdx.x * 256 + threadIdx.x;   // 65536 samples
    unsigned v = raw[2 * i + 1];
    if (v != 0u) g_flag32 = 1;
}

// ---------------- merged: count degrees + precompute folds ----------------
__global__ void k_count_pre(const void* __restrict__ eidx,
                            const float* __restrict__ gat_W1,
                            const float* __restrict__ att_s1,
                            const float* __restrict__ att_d1,
                            const float* __restrict__ gat_W2,
                            const float* __restrict__ att_s2,
                            const float* __restrict__ att_d2,
                            const float* __restrict__ gcn_W1,
                            const float* __restrict__ gcn_W2,
                            const float* __restrict__ gat_b2,
                            const float* __restrict__ gcn_b2,
                            const float* __restrict__ lin_W,
                            const float* __restrict__ lin_b,
                            const float* __restrict__ wc_p,
                            const float* __restrict__ wt_p) {
    int b = blockIdx.x;
    if (b < CNT_BLOCKS) {
        int e = b * 256 + threadIdx.x;
        if (e >= EP) return;
        int d = (e < EE) ? load_node(eidx, (long long)EE + e) : (e - EE);
        atomicAdd(&g_deg[d], 1);
    } else {
        int t = (b - CNT_BLOCKS) * 256 + threadIdx.x;
        float wc = *wc_p, wt = *wt_p;
        const int N_BCAT = F_IN * NCAT;
        if (t < N_BCAT) {
            int f = t / NCAT, c = t % NCAT;
            float v;
            if (c < HH) v = gat_W1[f * HH + c];
            else if (c < HH + HID) v = gcn_W1[f * HID + (c - HH)];
            else {
                int j = c - HH - HID;
                int h = j & 3;
                const float* av = (j < 4) ? &att_s1[h * HID] : &att_d1[h * HID];
                const float* wr = &gat_W1[f * HH + h * HID];
                float s = 0.f;
#pragma unroll
                for (int d = 0; d < HID; d++) s += wr[d] * av[d];
                v = s;
            }
            g_Bcat[t] = v;
        } else if (t < N_BCAT + 256) {
            int u = t - N_BCAT, f = u >> 1;
            const float* av = (u & 1) ? att_d2 : att_s2;
            const float* wr = &gat_W2[f * CC];
            float s = 0.f;
#pragma unroll
            for (int c = 0; c < CC; c++) s += wr[c] * av[c];
            g_comb2[f * 2 + (u & 1)] = s;
        } else if (t < N_BCAT + 256 + HH * CC) {
            int u = t - N_BCAT - 256;
            int f = u / CC, c = u % CC;
            float s = 0.f;
#pragma unroll
            for (int j = 0; j < CC; j++) s += gat_W2[f * CC + j] * lin_W[(CC + j) * CC + c];
            g_W2fold[u] = s * wt;
        } else if (t < N_BCAT + 256 + HH * CC + HID * CC) {
            int u = t - N_BCAT - 256 - HH * CC;
            int f = u / CC, c = u % CC;
            float s = 0.f;
#pragma unroll
            for (int j = 0; j < CC; j++) s += gcn_W2[f * CC + j] * lin_W[j * CC + c];
            g_Wgfold[u] = s * wc;
        } else if (t < N_BCAT + 256 + HH * CC + HID * CC + CC) {
            int c = t - N_BCAT - 256 - HH * CC - HID * CC;
            float s = lin_b[c];
#pragma unroll
            for (int j = 0; j < CC; j++) {
                s += wc * gcn_b2[j] * lin_W[j * CC + c];
                s += wt * gat_b2[j] * lin_W[(CC + j) * CC + c];
            }
            g_cvec[c] = s;
        }
    }
}

// ---------------- scan phase 1 ----------------
__global__ void scan_phase1() {
    __shared__ int warp_sums[32];
    int b = blockIdx.x;
    int i = b * SCAN_CHUNK + threadIdx.x;
    int lane = threadIdx.x & 31, wid = threadIdx.x >> 5;
    int v = (i < NN) ? g_deg[i] : 0;
    int x = v;
#pragma unroll
    for (int s = 1; s < 32; s <<= 1) {
        int t = __shfl_up_sync(0xffffffff, x, s);
        if (lane >= s) x += t;
    }
    if (lane == 31) warp_sums[wid] = x;
    __syncthreads();
    if (wid == 0) {
        int ws = warp_sums[lane];
#pragma unroll
        for (int s = 1; s < 32; s <<= 1) {
            int t = __shfl_up_sync(0xffffffff, ws, s);
            if (lane >= s) ws += t;
        }
        warp_sums[lane] = ws;
    }
    __syncthreads();
    int prefix = (wid > 0) ? warp_sums[wid - 1] : 0;
    int excl = prefix + x - v;
    if (i < NN) g_off[i] = excl;
    if (threadIdx.x == SCAN_CHUNK - 1) g_bsum[b] = prefix + x;
}

// ---------------- scan phase 3: inline chunk-prefix ----------------
__global__ void scan_phase3() {
    __shared__ int sred[64];
    int chunk = blockIdx.x >> 2;
    int t = threadIdx.x;
    if (t < 64) sred[t] = (t < chunk) ? g_bsum[t] : 0;
    __syncthreads();
    if (t < 32) sred[t] += sred[t + 32];
    __syncwarp();
    if (t < 16) sred[t] += sred[t + 16];
    __syncwarp();
    if (t < 8) sred[t] += sred[t + 8];
    __syncwarp();
    if (t < 4) sred[t] += sred[t + 4];
    __syncwarp();
    if (t < 2) sred[t] += sred[t + 2];
    __syncwarp();
    if (t < 1) sred[t] += sred[t + 1];
    __syncthreads();
    int prefix = sred[0];
    int i = blockIdx.x * 256 + t;
    if (i == 0) g_off[NN] = EP;
    if (i >= NN) return;
    int o = g_off[i] + prefix;
    g_off[i] = o;
    g_cursor[i] = o;
    g_norm[i] = rsqrtf((float)g_deg[i]);
}

// ---------------- merged: fused projection (128x64, 8x4) + CSR scatter ----------
__global__ void __launch_bounds__(256) k_proj_scatter(const float* __restrict__ x,
                                                      const void* __restrict__ eidx) {
    __shared__ float As[BK][PBM + 4];
    __shared__ float Bs[BK][BN];
    int b = blockIdx.x;
    if (b >= PROJ_BLOCKS) {
        int e = (b - PROJ_BLOCKS) * 256 + threadIdx.x;
        if (e >= EP) return;
        int s, d;
        if (e < EE) {
            s = load_node(eidx, e);
            d = load_node(eidx, (long long)EE + e);
        } else {
            s = d = e - EE;
        }
        int pos = atomicAdd(&g_cursor[d], 1);
        g_csr_src[pos] = s;
        return;
    }
    int tid = threadIdx.x;
    int tx = tid % 16, ty = tid / 16;
    int row0 = (b / PROJ_COLS) * PBM;
    int col0 = (b % PROJ_COLS) * BN;
    float acc[8][4] = {};
    for (int k0 = 0; k0 < F_IN; k0 += BK) {
        {
            int r = tid >> 1;
            int kq = (tid & 1) * 8;
            int gr = row0 + r;
            float4 v0, v1;
            if (gr < NN) {
                v0 = *(const float4*)&x[gr * F_IN + k0 + kq];
                v1 = *(const float4*)&x[gr * F_IN + k0 + kq + 4];
            } else {
                v0 = make_float4(0.f, 0.f, 0.f, 0.f);
                v1 = v0;
            }
            As[kq + 0][r] = v0.x; As[kq + 1][r] = v0.y;
            As[kq + 2][r] = v0.z; As[kq + 3][r] = v0.w;
            As[kq + 4][r] = v1.x; As[kq + 5][r] = v1.y;
            As[kq + 6][r] = v1.z; As[kq + 7][r] = v1.w;
        }
        {
            int r = tid >> 4;
            int c4 = (tid & 15) * 4;
            int gc = col0 + c4;
            float4 v = (gc + 3 < NCAT) ? *(const float4*)&g_Bcat[(k0 + r) * NCAT + gc]
                                       : make_float4(0.f, 0.f, 0.f, 0.f);
            *(float4*)&Bs[r][c4] = v;
        }
        __syncthreads();
#pragma unroll
        for (int k = 0; k < BK; k++) {
            float a[8], bb[4];
#pragma unroll
            for (int i = 0; i < 8; i++) a[i] = As[k][ty * 8 + i];
#pragma unroll
            for (int j = 0; j < 4; j++) bb[j] = Bs[k][tx * 4 + j];
#pragma unroll
            for (int i = 0; i < 8; i++)
#pragma unroll
                for (int j = 0; j < 4; j++) acc[i][j] += a[i] * bb[j];
        }
        __syncthreads();
    }
#pragma unroll
    for (int i = 0; i < 8; i++) {
        int gr = row0 + ty * 8 + i;
        if (gr >= NN) continue;
#pragma unroll
        for (int j = 0; j < 4; j++) {
            int gc = col0 + tx * 4 + j;
            if (gc < HH) g_h1h[gr * HH + gc] = __float2half(acc[i][j]);
            else if (gc < HH + HID) g_hg1h[gr * HID + (gc - HH)] = __float2half(acc[i][j]);
            else if (gc < HH + HID + 4) g_as1[gr * 4 + (gc - HH - HID)] = acc[i][j];
            else if (gc < NCAT) g_ad1[gr * 4 + (gc - HH - HID - 4)] = acc[i][j];
        }
    }
}

// ---------------- merged layer-1: GAT1 (2-warp split, fp16 gathers) + GCN1 ------
__global__ void __launch_bounds__(256) k_layer1(const float* __restrict__ gat_b1,
                                                const float* __restrict__ gcn_b1) {
    __shared__ float s_acc[8][HH];
    __shared__ float s_sum[8][4];
    int b = blockIdx.x;
    int wid = threadIdx.x >> 5;
    int lane = threadIdx.x & 31;
    if (b < GAT1_BLOCKS) {
        int n = b * 4 + (wid >> 1);
        int half = wid & 1;
        int beg = g_off[n], end = g_off[n + 1];
        int mid = beg + ((end - beg) >> 1);
        int lo = half ? mid : beg;
        int hi = half ? end : mid;
        int h = lane >> 3;
        float ad = g_ad1[n * 4 + h];
        float4 acc = {0.f, 0.f, 0.f, 0.f};
        float sumw = 0.f;
        int p = lo;
        for (; p + 3 < hi; p += 4) {
            int s0 = g_csr_src[p];
            int s1 = g_csr_src[p + 1];
            int s2 = g_csr_src[p + 2];
            int s3 = g_csr_src[p + 3];
            float l0 = g_as1[s0 * 4 + h] + ad;
            float l1 = g_as1[s1 * 4 + h] + ad;
            float l2 = g_as1[s2 * 4 + h] + ad;
            float l3 = g_as1[s3 * 4 + h] + ad;
            // 4 fp16 features per lane = one 8-byte load
            float2 r0 = *(const float2*)&g_h1h[s0 * HH + lane * 4];
            float2 r1 = *(const float2*)&g_h1h[s1 * HH + lane * 4];
            float2 r2 = *(const float2*)&g_h1h[s2 * HH + lane * 4];
            float2 r3 = *(const float2*)&g_h1h[s3 * HH + lane * 4];
            float2 a0 = __half22float2(((const __half2*)&r0)[0]);
            float2 b0 = __half22float2(((const __half2*)&r0)[1]);
            float2 a1 = __half22float2(((const __half2*)&r1)[0]);
            float2 b1 = __half22float2(((const __half2*)&r1)[1]);
            float2 a2 = __half22float2(((const __half2*)&r2)[0]);
            float2 b2 = __half22float2(((const __half2*)&r2)[1]);
            float2 a3 = __half22float2(((const __half2*)&r3)[0]);
            float2 b3 = __half22float2(((const __half2*)&r3)[1]);
            l0 = (l0 > 0.f) ? l0 : NEG_SLOPE * l0;
            l1 = (l1 > 0.f) ? l1 : NEG_SLOPE * l1;
            l2 = (l2 > 0.f) ? l2 : NEG_SLOPE * l2;
            l3 = (l3 > 0.f) ? l3 : NEG_SLOPE * l3;
            float w0 = __expf(l0), w1 = __expf(l1), w2 = __expf(l2), w3 = __expf(l3);
            sumw += (w0 + w1) + (w2 + w3);
            acc.x += w0 * a0.x + w1 * a1.x + w2 * a2.x + w3 * a3.x;
            acc.y += w0 * a0.y + w1 * a1.y + w2 * a2.y + w3 * a3.y;
            acc.z += w0 * b0.x + w1 * b1.x + w2 * b2.x + w3 * b3.x;
            acc.w += w0 * b0.y + w1 * b1.y + w2 * b2.y + w3 * b3.y;
        }
        for (; p < hi; p++) {
            int s0 = g_csr_src[p];
            float l0 = g_as1[s0 * 4 + h] + ad;
            float2 r0 = *(const float2*)&g_h1h[s0 * HH + lane * 4];
            float2 a0 = __half22float2(((const __half2*)&r0)[0]);
            float2 b0 = __half22float2(((const __half2*)&r0)[1]);
            l0 = (l0 > 0.f) ? l0 : NEG_SLOPE * l0;
            float w0 = __expf(l0);
            sumw += w0;
            acc.x += w0 * a0.x; acc.y += w0 * a0.y; acc.z += w0 * b0.x; acc.w += w0 * b0.y;
        }
        if (half) {
            *(float4*)&s_acc[wid][lane * 4] = acc;
            if ((lane & 7) == 0) s_sum[wid][h] = sumw;   // per-head partial sums
        }
        __syncthreads();
        if (!half) {
            float4 pa = *(const float4*)&s_acc[wid + 1][lane * 4];
            acc.x += pa.x; acc.y += pa.y; acc.z += pa.z; acc.w += pa.w;
            sumw += s_sum[wid + 1][h];
            float inv = 1.f / sumw;
            float4 bv = *(const float4*)&gat_b1[lane * 4];
            float4 o;
            float vx = acc.x * inv + bv.x; o.x = (vx > 0.f) ? vx : expm1f(vx);
            float vy = acc.y * inv + bv.y; o.y = (vy > 0.f) ? vy : expm1f(vy);
            float vz = acc.z * inv + bv.z; o.z = (vz > 0.f) ? vz : expm1f(vz);
            float vw = acc.w * inv + bv.w; o.w = (vw > 0.f) ? vw : expm1f(vw);
            *(float4*)&g_out1[n * HH + lane * 4] = o;
        }
    } else {
        int n = (b - GAT1_BLOCKS) * 8 + wid;
        if (n >= NN) return;
        int beg = g_off[n], end = g_off[n + 1];
        float nd = g_norm[n];
        float acc = 0.f;
        int p = beg;
        for (; p + 3 < end; p += 4) {
            int s0 = g_csr_src[p];
            int s1 = g_csr_src[p + 1];
            int s2 = g_csr_src[p + 2];
            int s3 = g_csr_src[p + 3];
            float c0 = g_norm[s0], c1 = g_norm[s1], c2 = g_norm[s2], c3 = g_norm[s3];
            float v0 = __half2float(g_hg1h[s0 * HID + lane]);
            float v1 = __half2float(g_hg1h[s1 * HID + lane]);
            float v2 = __half2float(g_hg1h[s2 * HID + lane]);
            float v3 = __half2float(g_hg1h[s3 * HID + lane]);
            acc += (c0 * v0 + c1 * v1) + (c2 * v2 + c3 * v3);
        }
        for (; p < end; p++) {
            int s0 = g_csr_src[p];
            acc += g_norm[s0] * __half2float(g_hg1h[s0 * HID + lane]);
        }
        float v = acc * nd + gcn_b1[lane];
        g_go1[n * HID + lane] = (v > 0.f) ? v : 0.f;
    }
}

// ---------------- gemm_gcn2 alone: go1 @ Wgfold -> hg2 ----------------
__global__ void __launch_bounds__(256) k_gemm_gcn2() {
    __shared__ float As[BK][BM + 1];
    __shared__ float Bs[BK][BN];
    const float* A = g_go1;
    int tid = threadIdx.x;
    int tx = tid % 16, ty = tid / 16;
    int row0 = blockIdx.x * BM;
    float acc[4][4] = {};
    for (int k0 = 0; k0 < HID; k0 += BK) {
        {
            int r = tid >> 2;
            int c4 = (tid & 3) * 4;
            int gr = row0 + r;
            float4 v = (gr < NN) ? *(const float4*)&A[gr * HID + k0 + c4]
                                 : make_float4(0.f, 0.f, 0.f, 0.f);
            As[c4 + 0][r] = v.x;
            As[c4 + 1][r] = v.y;
            As[c4 + 2][r] = v.z;
            As[c4 + 3][r] = v.w;
        }
        for (int i = tid; i < BK * BN; i += 256) {
            int r = i / BN, c = i % BN;
            Bs[r][c] = (c < CC) ? g_Wgfold[(k0 + r) * CC + c] : 0.f;
        }
        __syncthreads();
#pragma unroll
        for (int k = 0; k < BK; k++) {
            float a[4], bb[4];
#pragma unroll
            for (int i = 0; i < 4; i++) a[i] = As[k][ty * 4 + i];
#pragma unroll
            for (int j = 0; j < 4; j++) bb[j] = Bs[k][tx * 4 + j];
#pragma unroll
            for (int i = 0; i < 4; i++)
#pragma unroll
                for (int j = 0; j < 4; j++) acc[i][j] += a[i] * bb[j];
        }
        __syncthreads();
    }
#pragma unroll
    for (int i = 0; i < 4; i++) {
        int gr = row0 + ty * 4 + i;
        if (gr >= NN) continue;
#pragma unroll
        for (int j = 0; j < 4; j++) {
            int gc = tx * 4 + j;
            if (gc < CC) g_hg2[gr * CC + gc] = acc[i][j];
        }
    }
}

// ---------------- merged: gemm_l2 ∥ gcn2_agg ----------------
__global__ void __launch_bounds__(256) k_l2_mix() {
    __shared__ float As[BK][BM + 1];
    __shared__ float Bs[BK][BN];
    int b = blockIdx.x;
    if (b < NB_ROWS) {
        const float* A = g_out1;
        int tid = threadIdx.x;
        int tx = tid % 16, ty = tid / 16;
        int row0 = b * BM;
        float acc[4][4] = {};
        for (int k0 = 0; k0 < HH; k0 += BK) {
            {
                int r = tid >> 2;
                int c4 = (tid & 3) * 4;
                int gr = row0 + r;
                float4 v = (gr < NN) ? *(const float4*)&A[gr * HH + k0 + c4]
                                     : make_float4(0.f, 0.f, 0.f, 0.f);
                As[c4 + 0][r] = v.x;
                As[c4 + 1][r] = v.y;
                As[c4 + 2][r] = v.z;
                As[c4 + 3][r] = v.w;
            }
            for (int i = tid; i < BK * BN; i += 256) {
                int r = i / BN, c = i % BN;
                float v;
                if (c < CC) v = g_W2fold[(k0 + r) * CC + c];
                else if (c < CC + 2) v = g_comb2[(k0 + r) * 2 + (c - CC)];
                else v = 0.f;
                Bs[r][c] = v;
            }
            __syncthreads();
#pragma unroll
            for (int k = 0; k < BK; k++) {
                float a[4], bb[4];
#pragma unroll
                for (int i = 0; i < 4; i++) a[i] = As[k][ty * 4 + i];
#pragma unroll
                for (int j = 0; j < 4; j++) bb[j] = Bs[k][tx * 4 + j];
#pragma unroll
                for (int i = 0; i < 4; i++)
#pragma unroll
                    for (int j = 0; j < 4; j++) acc[i][j] += a[i] * bb[j];
            }
            __syncthreads();
        }
#pragma unroll
        for (int i = 0; i < 4; i++) {
            int gr = row0 + ty * 4 + i;
            if (gr >= NN) continue;
#pragma unroll
            for (int j = 0; j < 4; j++) {
                int gc = tx * 4 + j;
                if (gc < CC) g_h2[gr * CC + gc] = acc[i][j];
                else if (gc == CC) g_as2[gr] = acc[i][j];
                else if (gc == CC + 1) g_ad2[gr] = acc[i][j];
            }
        }
    } else {
        int wid = threadIdx.x >> 5;
        int lane = threadIdx.x & 31;
        int n = (b - NB_ROWS) * 8 + wid;
        if (n >= NN) return;
        int beg = g_off[n], end = g_off[n + 1];
        float nd = g_norm[n];
        float acc1 = 0.f, acc2 = 0.f;
        int p = beg;
        for (; p + 3 < end; p += 4) {
            int s0 = g_csr_src[p];
            int s1 = g_csr_src[p + 1];
            int s2 = g_csr_src[p + 2];
            int s3 = g_csr_src[p + 3];
            float c0 = g_norm[s0], c1 = g_norm[s1], c2 = g_norm[s2], c3 = g_norm[s3];
            float a0 = g_hg2[s0 * CC + lane];
            float a1 = g_hg2[s1 * CC + lane];
            float a2 = g_hg2[s2 * CC + lane];
            float a3 = g_hg2[s3 * CC + lane];
            acc1 += (c0 * a0 + c1 * a1) + (c2 * a2 + c3 * a3);
            if (lane < CC - 32) {
                float b0 = g_hg2[s0 * CC + 32 + lane];
                float b1 = g_hg2[s1 * CC + 32 + lane];
                float b2 = g_hg2[s2 * CC + 32 + lane];
                float b3 = g_hg2[s3 * CC + 32 + lane];
                acc2 += (c0 * b0 + c1 * b1) + (c2 * b2 + c3 * b3);
            }
        }
        for (; p < end; p++) {
            int s0 = g_csr_src[p];
            float c0 = g_norm[s0];
            acc1 += c0 * g_hg2[s0 * CC + lane];
            if (lane < CC - 32) acc2 += c0 * g_hg2[s0 * CC + 32 + lane];
        }
        g_go2[n * CC + lane] = acc1 * nd + g_cvec[lane];
        if (lane < CC - 32) g_go2[n * CC + 32 + lane] = acc2 * nd + g_cvec[32 + lane];
    }
}

// ---------------- GAT2 aggregation + final out; tail blocks re-zero g_deg ------
__global__ void gat2_agg_out(float* __restrict__ out) {
    int b = blockIdx.x;
    if (b >= AGG_BLK) {
        int i = (b - AGG_BLK) * 256 + threadIdx.x;
        if (i < NN) g_deg[i] = 0;        // ready for next call (deterministic)
        return;
    }
    int wid = threadIdx.x >> 5;
    int lane = threadIdx.x & 31;
    int n = b * 8 + wid;
    if (n >= NN) return;
    int beg = g_off[n], end = g_off[n + 1];
    float ad = g_ad2[n];
    float acc1 = 0.f, acc2 = 0.f, sumw = 0.f;
    int p = beg;
    for (; p + 3 < end; p += 4) {
        int s0 = g_csr_src[p];
        int s1 = g_csr_src[p + 1];
        int s2 = g_csr_src[p + 2];
        int s3 = g_csr_src[p + 3];
        float l0 = g_as2[s0] + ad;
        float l1 = g_as2[s1] + ad;
        float l2 = g_as2[s2] + ad;
        float l3 = g_as2[s3] + ad;
        float a0 = g_h2[s0 * CC + lane];
        float a1 = g_h2[s1 * CC + lane];
        float a2 = g_h2[s2 * CC + lane];
        float a3 = g_h2[s3 * CC + lane];
        l0 = (l0 > 0.f) ? l0 : NEG_SLOPE * l0;
        l1 = (l1 > 0.f) ? l1 : NEG_SLOPE * l1;
        l2 = (l2 > 0.f) ? l2 : NEG_SLOPE * l2;
        l3 = (l3 > 0.f) ? l3 : NEG_SLOPE * l3;
        float w0 = __expf(l0), w1 = __expf(l1), w2 = __expf(l2), w3 = __expf(l3);
        sumw += (w0 + w1) + (w2 + w3);
        acc1 += (w0 * a0 + w1 * a1) + (w2 * a2 + w3 * a3);
        if (lane < CC - 32) {
            float b0 = g_h2[s0 * CC + 32 + lane];
            float b1 = g_h2[s1 * CC + 32 + lane];
            float b2 = g_h2[s2 * CC + 32 + lane];
            float b3 = g_h2[s3 * CC + 32 + lane];
            acc2 += (w0 * b0 + w1 * b1) + (w2 * b2 + w3 * b3);
        }
    }
    for (; p < end; p++) {
        int s0 = g_csr_src[p];
        float l0 = g_as2[s0] + ad;
        float a0 = g_h2[s0 * CC + lane];
        l0 = (l0 > 0.f) ? l0 : NEG_SLOPE * l0;
        float w0 = __expf(l0);
        sumw += w0;
        acc1 += w0 * a0;
        if (lane < CC - 32) acc2 += w0 * g_h2[s0 * CC + 32 + lane];
    }
    float inv = 1.f / sumw;
    out[n * CC + lane] = acc1 * inv + g_go2[n * CC + lane];
    if (lane < CC - 32) out[n * CC + 32 + lane] = acc2 * inv + g_go2[n * CC + 32 + lane];
}

// ---------------- launch ----------------
extern "C" void kernel_launch(void* const* d_in, const int* in_sizes, int n_in,
                              void* d_out, int out_size) {
    const float* x      = (const float*)d_in[0];
    const void*  eidx   = d_in[1];
    const float* gat_W1 = (const float*)d_in[2];
    const float* att_s1 = (const float*)d_in[3];
    const float* att_d1 = (const float*)d_in[4];
    const float* gat_b1 = (const float*)d_in[5];
    const float* gat_W2 = (const float*)d_in[6];
    const float* att_s2 = (const float*)d_in[7];
    const float* att_d2 = (const float*)d_in[8];
    const float* gat_b2 = (const float*)d_in[9];
    const float* gcn_W1 = (const float*)d_in[10];
    const float* gcn_b1 = (const float*)d_in[11];
    const float* gcn_W2 = (const float*)d_in[12];
    const float* gcn_b2 = (const float*)d_in[13];
    const float* lin_W  = (const float*)d_in[14];
    const float* lin_b  = (const float*)d_in[15];
    const float* wc     = (const float*)d_in[16];
    const float* wt     = (const float*)d_in[17];
    float*       out    = (float*)d_out;

    // 1) dtype detect (g_deg already zero: module load or previous call's tail)
    k_detect<<<256, 256>>>((const unsigned int*)eidx);
    // 2) count degrees ∥ precompute folds
    k_count_pre<<<CNT_BLOCKS + PRE_BLOCKS, 256>>>(eidx, gat_W1, att_s1, att_d1,
                                                  gat_W2, att_s2, att_d2,
                                                  gcn_W1, gcn_W2, gat_b2, gcn_b2,
                                                  lin_W, lin_b, wc, wt);
    // 3-4) scan
    scan_phase1<<<SCAN_BLOCKS, SCAN_CHUNK>>>();
    scan_phase3<<<(NN + 255) / 256, 256>>>();
    // 5) fused projection (fp16 h1/hg1 outputs) ∥ CSR scatter
    k_proj_scatter<<<PROJ_BLOCKS + SCAT_BLOCKS, 256>>>(x, eidx);
    // 6) GAT1 ∥ GCN1 (fp16 gathers, fp32 accumulation)
    k_layer1<<<GAT1_BLOCKS + GCN1_BLOCKS, 256>>>(gat_b1, gcn_b1);
    // 7) gemm_gcn2
    k_gemm_gcn2<<<NB_ROWS, 256>>>();
    // 8) gemm_l2 ∥ gcn2_agg
    k_l2_mix<<<NB_ROWS + AGG_BLK, 256>>>();
    // 9) GAT2 aggregation + final out; tail re-zeroes g_deg for next call
    gat2_agg_out<<<AGG_BLK + ZI_BLOCKS, 256>>>(out);
}